// round 12
// baseline (speedup 1.0000x reference)
#include <cuda_runtime.h>
#include <math.h>

#define BB 16
#define LL 1023
#define SS 1024
#define DD 128
#define DVAL 64
#define NDEMO 16
#define HH 8
#define DH 16
#define NLAY 2
#define DFF 512
#define MLPH 256

#define AS_ELEMS (64 * 36)
#define BS_ELEMS (32 * 136)
#define STAGE_ELEMS (AS_ELEMS + BS_ELEMS)
#define GEMM_SMEM_BYTES (3 * STAGE_ELEMS * 4)

// embed smem: 2 x (As + Bs)
#define EMBED_SMEM_BYTES (2 * STAGE_ELEMS * 4)

// fused FFN smem layout (unsigned units)
#define FFN_AX_OFF 0
#define FFN_AX_STRIDE 132
#define FFN_HS_OFF (64 * FFN_AX_STRIDE)                 // 8448
#define FFN_HS_STRIDE 516
#define FFN_BST_OFF (FFN_HS_OFF + 64 * FFN_HS_STRIDE)   // 41472
#define FFN_SMEM_BYTES ((FFN_BST_OFF + 3 * BS_ELEMS) * 4)  // 218112

// ---------------- device scratch (no allocs allowed) ----------------
__device__ float g_x[BB * SS * DD];
__device__ float g_q[BB * SS * DD];
__device__ float g_k[BB * SS * DD];
__device__ float g_v[BB * SS * DD];
__device__ float g_o[BB * SS * DD];

__device__ __forceinline__ unsigned f2tf(float x) {
    unsigned r;
    asm("cvt.rna.tf32.f32 %0, %1;" : "=r"(r) : "f"(x));
    return r;
}

__device__ __forceinline__ float ex2f(float x) {
    float r;
    asm("ex2.approx.ftz.f32 %0, %1;" : "=f"(r) : "f"(x));
    return r;
}

__device__ __forceinline__ void mma_tf32(float* c, unsigned a0, unsigned a1,
                                         unsigned a2, unsigned a3,
                                         unsigned b0, unsigned b1) {
    asm("mma.sync.aligned.m16n8k8.row.col.f32.tf32.tf32.f32 "
        "{%0,%1,%2,%3},{%4,%5,%6,%7},{%8,%9},{%0,%1,%2,%3};"
        : "+f"(c[0]), "+f"(c[1]), "+f"(c[2]), "+f"(c[3])
        : "r"(a0), "r"(a1), "r"(a2), "r"(a3), "r"(b0), "r"(b1));
}

__device__ __forceinline__ unsigned smem_u32(const void* p) {
    return (unsigned)__cvta_generic_to_shared(p);
}

__device__ __forceinline__ void cp_async16(unsigned s, const void* g) {
    asm volatile("cp.async.ca.shared.global [%0], [%1], 16;" :: "r"(s), "l"(g));
}
#define CP_COMMIT() asm volatile("cp.async.commit_group;" ::: "memory")
#define CP_WAIT2() asm volatile("cp.async.wait_group 2;" ::: "memory")
#define CP_WAIT1() asm volatile("cp.async.wait_group 1;" ::: "memory")
#define CP_WAIT0() asm volatile("cp.async.wait_group 0;" ::: "memory")

// ---------------- GEMM tile: 64 rows x 128 cols, 256 threads ----------------
__device__ __forceinline__ void compute_chunk(float (*acc)[4],
                                              const unsigned (*As)[36],
                                              const unsigned (*Bs)[136],
                                              int mq, int nh, int g, int tg) {
    int mr = mq * 16;
    #pragma unroll
    for (int ks = 0; ks < 4; ks++) {
        unsigned a0 = As[mr + g][ks * 8 + tg];
        unsigned a1 = As[mr + g + 8][ks * 8 + tg];
        unsigned a2 = As[mr + g][ks * 8 + tg + 4];
        unsigned a3 = As[mr + g + 8][ks * 8 + tg + 4];
        #pragma unroll
        for (int nt = 0; nt < 8; nt++) {
            unsigned b0 = Bs[ks * 8 + tg][nh * 64 + nt * 8 + g];
            unsigned b1 = Bs[ks * 8 + tg + 4][nh * 64 + nt * 8 + g];
            mma_tf32(acc[nt], a0, a1, a2, a3, b0, b1);
        }
    }
}

// variant: A resident in smem with arbitrary row stride + column offset
__device__ __forceinline__ void compute_chunk_resA(float (*acc)[4],
        const unsigned* Ax, int astride, int aoff,
        const unsigned (*Bs)[136], int mq, int nh, int g, int tg) {
    int mr = mq * 16;
    #pragma unroll
    for (int ks = 0; ks < 4; ks++) {
        const unsigned* r0 = Ax + (mr + g) * astride + aoff + ks * 8;
        const unsigned* r1 = Ax + (mr + g + 8) * astride + aoff + ks * 8;
        unsigned a0 = r0[tg], a1 = r1[tg], a2 = r0[tg + 4], a3 = r1[tg + 4];
        #pragma unroll
        for (int nt = 0; nt < 8; nt++) {
            unsigned b0 = Bs[ks * 8 + tg][nh * 64 + nt * 8 + g];
            unsigned b1 = Bs[ks * 8 + tg + 4][nh * 64 + nt * 8 + g];
            mma_tf32(acc[nt], a0, a1, a2, a3, b0, b1);
        }
    }
}

// cp.async triple-buffered (depth-2) GEMM mainloop over nK k-chunks of 32.
__device__ __forceinline__ void gemm_mainloop_cp(
    float (*acc)[4], unsigned* smemu,
    const float* Ag, int lda, const float* Wg, int ldw, int nK,
    int t, int mq, int nh, int g, int tg) {
    int ra = t >> 2, c0 = (t & 3) * 8;
    int rb = t >> 3, f0 = t & 7;

    auto stage = [&](int kc) {
        unsigned* base = smemu + (kc % 3) * STAGE_ELEMS;
        unsigned (*As)[36] = (unsigned(*)[36])base;
        unsigned (*Bs)[136] = (unsigned(*)[136])(base + AS_ELEMS);
        const float* ap = Ag + (size_t)ra * lda + kc * 32 + c0;
        cp_async16(smem_u32(&As[ra][c0]), ap);
        cp_async16(smem_u32(&As[ra][c0 + 4]), ap + 4);
        const float* bp = Wg + (size_t)(kc * 32 + rb) * ldw;
        #pragma unroll
        for (int j = 0; j < 4; j++) {
            int c = (f0 + j * 8) * 4;
            cp_async16(smem_u32(&Bs[rb][c]), bp + c);
        }
        CP_COMMIT();
    };

    stage(0);
    if (nK > 1) stage(1);
    for (int kc = 0; kc < nK; kc++) {
        if (kc + 2 < nK) {
            stage(kc + 2);
            CP_WAIT2();
        } else if (kc + 1 < nK) {
            CP_WAIT1();
        } else {
            CP_WAIT0();
        }
        __syncthreads();
        unsigned* base = smemu + (kc % 3) * STAGE_ELEMS;
        compute_chunk(acc, (const unsigned(*)[36])base,
                      (const unsigned(*)[136])(base + AS_ELEMS), mq, nh, g, tg);
        __syncthreads();
    }
}

// ---------------- demo token row ----------------
__global__ __launch_bounds__(128) void demo_kernel(
    const float* __restrict__ demo,
    const float* __restrict__ W_demo, const float* __restrict__ b_demo) {
    int b = blockIdx.x, d = threadIdx.x;
    float acc = b_demo[d];
    #pragma unroll
    for (int k = 0; k < NDEMO; k++) acc += demo[b * NDEMO + k] * W_demo[k * DD + d];
    g_x[(size_t)b * SS * DD + d] = acc;
}

// ---------------- embedding (value tokens) via mma: grid (16 tiles, BB) ----------------
__global__ __launch_bounds__(256) void embed_mma_kernel(
    const float* __restrict__ times, const float* __restrict__ values,
    const float* __restrict__ timescales,
    const float* __restrict__ W_val, const float* __restrict__ b_val,
    const int* __restrict__ length) {
    int tile = blockIdx.x, b = blockIdx.y;
    int row0 = tile * 64;                 // token index t base
    if (row0 >= length[b]) return;        // s = t+1 > length for whole tile

    extern __shared__ unsigned smemu[];
    int t = threadIdx.x, w = t >> 5, lane = t & 31;
    int g = lane >> 2, tg = lane & 3, mq = w >> 1, nh = w & 1;

    int ra = t >> 2, c0a = (t & 3) * 8;
    int rb = t >> 3, f0 = t & 7;

    auto stage = [&](int kc, int buf) {
        unsigned* base = smemu + buf * STAGE_ELEMS;
        unsigned (*As)[36] = (unsigned(*)[36])base;
        unsigned (*Bs)[136] = (unsigned(*)[136])(base + AS_ELEMS);
        int tt = row0 + ra;
        int te = (tt > LL - 1) ? (LL - 1) : tt;
        const float* ap = values + ((size_t)b * LL + te) * DVAL + kc * 32 + c0a;
        cp_async16(smem_u32(&As[ra][c0a]), ap);
        cp_async16(smem_u32(&As[ra][c0a + 4]), ap + 4);
        const float* bp = W_val + (size_t)(kc * 32 + rb) * DD;
        #pragma unroll
        for (int j = 0; j < 4; j++) {
            int c = (f0 + j * 8) * 4;
            cp_async16(smem_u32(&Bs[rb][c]), bp + c);
        }
        CP_COMMIT();
    };

    float acc[8][4];
    #pragma unroll
    for (int i = 0; i < 8; i++) acc[i][0] = acc[i][1] = acc[i][2] = acc[i][3] = 0.f;

    stage(0, 0);
    stage(1, 1);
    #pragma unroll
    for (int kc = 0; kc < 2; kc++) {
        if (kc == 0) CP_WAIT1(); else CP_WAIT0();
        __syncthreads();
        unsigned* base = smemu + kc * STAGE_ELEMS;
        compute_chunk(acc, (const unsigned(*)[36])base,
                      (const unsigned(*)[136])(base + AS_ELEMS), mq, nh, g, tg);
        __syncthreads();
    }

    // epilogue: bias + positional encoding, write x rows s = t+1
    int t0 = row0 + mq * 16 + g, t1 = t0 + 8;
    float tm0 = (t0 <= LL - 1) ? times[b * LL + t0] : 0.f;
    float tm1 = (t1 <= LL - 1) ? times[b * LL + t1] : 0.f;
    #pragma unroll
    for (int nt = 0; nt < 8; nt++) {
        int col = nh * 64 + nt * 8 + 2 * tg;
        float2 bi = *(const float2*)&b_val[col];
        float ts0 = timescales[col & 63], ts1 = timescales[(col + 1) & 63];
        float a0 = __fdividef(tm0, ts0), a1 = __fdividef(tm0, ts1);
        float b0 = __fdividef(tm1, ts0), b1 = __fdividef(tm1, ts1);
        float pe00 = (col < 64) ? __sinf(a0) : __cosf(a0);
        float pe01 = (col + 1 < 64) ? __sinf(a1) : __cosf(a1);
        float pe10 = (col < 64) ? __sinf(b0) : __cosf(b0);
        float pe11 = (col + 1 < 64) ? __sinf(b1) : __cosf(b1);
        if (t0 <= LL - 1) {
            float2 lo = {acc[nt][0] + bi.x + pe00, acc[nt][1] + bi.y + pe01};
            *(float2*)&g_x[((size_t)b * SS + t0 + 1) * DD + col] = lo;
        }
        if (t1 <= LL - 1) {
            float2 hi = {acc[nt][2] + bi.x + pe10, acc[nt][3] + bi.y + pe11};
            *(float2*)&g_x[((size_t)b * SS + t1 + 1) * DD + col] = hi;
        }
    }
}

// ---------------- QKV: grid (tiles, 3) ----------------
__global__ __launch_bounds__(256) void qkv_mma_kernel(
    const int* __restrict__ length,
    const float* __restrict__ Wq, const float* __restrict__ bq,
    const float* __restrict__ Wk, const float* __restrict__ bk,
    const float* __restrict__ Wv, const float* __restrict__ bv) {
    int row0 = blockIdx.x * 64;
    int b = row0 >> 10;
    int valid_len = length[b] + 1;
    if ((row0 & (SS - 1)) >= valid_len) return;
    int wi = blockIdx.y;
    const float* W = (wi == 0) ? Wq : (wi == 1) ? Wk : Wv;
    const float* bias = (wi == 0) ? bq : (wi == 1) ? bk : bv;
    float* out = (wi == 0) ? g_q : (wi == 1) ? g_k : g_v;

    extern __shared__ unsigned smemu[];
    int t = threadIdx.x, w = t >> 5, lane = t & 31;
    int g = lane >> 2, tg = lane & 3, mq = w >> 1, nh = w & 1;

    float acc[8][4];
    #pragma unroll
    for (int i = 0; i < 8; i++) acc[i][0] = acc[i][1] = acc[i][2] = acc[i][3] = 0.f;

    gemm_mainloop_cp(acc, smemu, g_x + (size_t)row0 * DD, DD, W, DD, 4,
                     t, mq, nh, g, tg);

    int r0 = row0 + mq * 16 + g, r1 = r0 + 8;
    #pragma unroll
    for (int nt = 0; nt < 8; nt++) {
        int col = nh * 64 + nt * 8 + 2 * tg;
        float2 bi = *(const float2*)&bias[col];
        float2 lo = {acc[nt][0] + bi.x, acc[nt][1] + bi.y};
        float2 hi = {acc[nt][2] + bi.x, acc[nt][3] + bi.y};
        *(float2*)&out[(size_t)r0 * DD + col] = lo;
        *(float2*)&out[(size_t)r1 * DD + col] = hi;
    }
}

// ---------------- flash attention: no-max softmax, cp.async double-buffered ----------------
__global__ __launch_bounds__(128) void attn_mma_kernel(const int* __restrict__ length) {
    const int qt = blockIdx.x, h = blockIdx.y, b = blockIdx.z;
    int valid_len = length[b] + 1;
    int q0 = qt * 64;
    if (q0 >= valid_len) return;

    __shared__ unsigned Ks[2][64][20];
    __shared__ unsigned Vs[2][64][24];
    __shared__ unsigned Ps[64][68];

    int t = threadIdx.x;
    int w = t >> 5, lane = t & 31;
    int g = lane >> 2, tg = lane & 3;
    int qrow_base = b * SS + q0 + w * 16;

    int key_st = t >> 1, d8 = (t & 1) << 3;
    auto stage = [&](int c, int buf) {
        size_t src = (size_t)(b * SS + c * 64 + key_st) * DD + h * DH + d8;
        const float* kp = g_k + src;
        cp_async16(smem_u32(&Ks[buf][key_st][d8]), kp);
        cp_async16(smem_u32(&Ks[buf][key_st][d8 + 4]), kp + 4);
        const float* vp = g_v + src;
        cp_async16(smem_u32(&Vs[buf][key_st][d8]), vp);
        cp_async16(smem_u32(&Vs[buf][key_st][d8 + 4]), vp + 4);
        CP_COMMIT();
    };

    const float qscale = 0.25f * 1.44269504f;
    unsigned qa[2][4];
    #pragma unroll
    for (int ks = 0; ks < 2; ks++) {
        int r_lo = (qrow_base + g) * DD + h * DH + ks * 8 + tg;
        int r_hi = (qrow_base + g + 8) * DD + h * DH + ks * 8 + tg;
        qa[ks][0] = f2tf(g_q[r_lo] * qscale);
        qa[ks][1] = f2tf(g_q[r_hi] * qscale);
        qa[ks][2] = f2tf(g_q[r_lo + 4] * qscale);
        qa[ks][3] = f2tf(g_q[r_hi + 4] * qscale);
    }

    float l0 = 0.f, l1 = 0.f;
    float oc[2][4];
    #pragma unroll
    for (int i = 0; i < 2; i++)
        #pragma unroll
        for (int j = 0; j < 4; j++) oc[i][j] = 0.f;

    int nch = (valid_len + 63) >> 6;

    stage(0, 0);

    for (int c = 0; c < nch; c++) {
        int bi = c & 1;
        if (c + 1 < nch) {
            stage(c + 1, bi ^ 1);
            CP_WAIT1();
        } else {
            CP_WAIT0();
        }
        __syncthreads();

        float sc[8][4];
        #pragma unroll
        for (int nt = 0; nt < 8; nt++) {
            sc[nt][0] = sc[nt][1] = sc[nt][2] = sc[nt][3] = 0.f;
            #pragma unroll
            for (int ks = 0; ks < 2; ks++) {
                unsigned b0 = Ks[bi][nt * 8 + g][ks * 8 + tg];
                unsigned b1 = Ks[bi][nt * 8 + g][ks * 8 + tg + 4];
                mma_tf32(sc[nt], qa[ks][0], qa[ks][1], qa[ks][2], qa[ks][3], b0, b1);
            }
        }

        int limit = valid_len - c * 64;
        #pragma unroll
        for (int nt = 0; nt < 8; nt++) {
            int col0 = nt * 8 + 2 * tg;
            int col1 = col0 + 1;
            float p0 = ex2f((col0 < limit) ? sc[nt][0] : -1e30f);
            float p1 = ex2f((col1 < limit) ? sc[nt][1] : -1e30f);
            float p2 = ex2f((col0 < limit) ? sc[nt][2] : -1e30f);
            float p3 = ex2f((col1 < limit) ? sc[nt][3] : -1e30f);
            l0 += p0 + p1;
            l1 += p2 + p3;
            int colw = nt * 8 + 2 * tg;
            uint2 lo = {__float_as_uint(p0), __float_as_uint(p1)};
            uint2 hi = {__float_as_uint(p2), __float_as_uint(p3)};
            *(uint2*)&Ps[w * 16 + g][colw] = lo;
            *(uint2*)&Ps[w * 16 + g + 8][colw] = hi;
        }
        __syncwarp();

        #pragma unroll
        for (int j = 0; j < 8; j++) {
            unsigned pa0 = Ps[w * 16 + g][j * 8 + tg];
            unsigned pa1 = Ps[w * 16 + g + 8][j * 8 + tg];
            unsigned pa2 = Ps[w * 16 + g][j * 8 + tg + 4];
            unsigned pa3 = Ps[w * 16 + g + 8][j * 8 + tg + 4];
            #pragma unroll
            for (int mt = 0; mt < 2; mt++) {
                unsigned vb0 = Vs[bi][j * 8 + tg][mt * 8 + g];
                unsigned vb1 = Vs[bi][j * 8 + tg + 4][mt * 8 + g];
                mma_tf32(oc[mt], pa0, pa1, pa2, pa3, vb0, vb1);
            }
        }
        __syncthreads();
    }

    l0 += __shfl_xor_sync(0xffffffff, l0, 1);
    l0 += __shfl_xor_sync(0xffffffff, l0, 2);
    l1 += __shfl_xor_sync(0xffffffff, l1, 1);
    l1 += __shfl_xor_sync(0xffffffff, l1, 2);

    float inv0 = 1.f / l0, inv1 = 1.f / l1;
    #pragma unroll
    for (int mt = 0; mt < 2; mt++) {
        int col = h * DH + mt * 8 + 2 * tg;
        float2 lo = {oc[mt][0] * inv0, oc[mt][1] * inv0};
        float2 hi = {oc[mt][2] * inv1, oc[mt][3] * inv1};
        *(float2*)&g_o[(qrow_base + g) * DD + col] = lo;
        *(float2*)&g_o[(qrow_base + g + 8) * DD + col] = hi;
    }
}

// ---------------- O-proj + residual + LN1 ----------------
__global__ __launch_bounds__(256) void oproj_ln_mma_kernel(
    const int* __restrict__ length,
    const float* __restrict__ Wo, const float* __restrict__ bo,
    const float* __restrict__ g1, const float* __restrict__ be1) {
    int row0 = blockIdx.x * 64;
    int b = row0 >> 10;
    int valid_len = length[b] + 1;
    if ((row0 & (SS - 1)) >= valid_len) return;

    extern __shared__ unsigned smemu[];
    __shared__ float redS[2][64];
    __shared__ float redQ[2][64];
    int t = threadIdx.x, w = t >> 5, lane = t & 31;
    int g = lane >> 2, tg = lane & 3, mq = w >> 1, nh = w & 1;

    float acc[8][4];
    #pragma unroll
    for (int i = 0; i < 8; i++) acc[i][0] = acc[i][1] = acc[i][2] = acc[i][3] = 0.f;

    gemm_mainloop_cp(acc, smemu, g_o + (size_t)row0 * DD, DD, Wo, DD, 4,
                     t, mq, nh, g, tg);

    int r0 = row0 + mq * 16 + g, r1 = r0 + 8;
    float rs0 = 0.f, rq0 = 0.f, rs1 = 0.f, rq1 = 0.f;
    #pragma unroll
    for (int nt = 0; nt < 8; nt++) {
        int col = nh * 64 + nt * 8 + 2 * tg;
        float2 bi = *(const float2*)&bo[col];
        float2 e0 = *(const float2*)&g_x[(size_t)r0 * DD + col];
        float2 e1 = *(const float2*)&g_x[(size_t)r1 * DD + col];
        acc[nt][0] += bi.x + e0.x;
        acc[nt][1] += bi.y + e0.y;
        acc[nt][2] += bi.x + e1.x;
        acc[nt][3] += bi.y + e1.y;
        rs0 += acc[nt][0] + acc[nt][1];
        rq0 += acc[nt][0] * acc[nt][0] + acc[nt][1] * acc[nt][1];
        rs1 += acc[nt][2] + acc[nt][3];
        rq1 += acc[nt][2] * acc[nt][2] + acc[nt][3] * acc[nt][3];
    }
    rs0 += __shfl_xor_sync(0xffffffff, rs0, 1);
    rs0 += __shfl_xor_sync(0xffffffff, rs0, 2);
    rq0 += __shfl_xor_sync(0xffffffff, rq0, 1);
    rq0 += __shfl_xor_sync(0xffffffff, rq0, 2);
    rs1 += __shfl_xor_sync(0xffffffff, rs1, 1);
    rs1 += __shfl_xor_sync(0xffffffff, rs1, 2);
    rq1 += __shfl_xor_sync(0xffffffff, rq1, 1);
    rq1 += __shfl_xor_sync(0xffffffff, rq1, 2);
    if (tg == 0) {
        redS[nh][mq * 16 + g] = rs0;
        redS[nh][mq * 16 + g + 8] = rs1;
        redQ[nh][mq * 16 + g] = rq0;
        redQ[nh][mq * 16 + g + 8] = rq1;
    }
    __syncthreads();
    float mu0 = (redS[0][mq * 16 + g] + redS[1][mq * 16 + g]) * (1.f / DD);
    float mu1 = (redS[0][mq * 16 + g + 8] + redS[1][mq * 16 + g + 8]) * (1.f / DD);
    float v0 = fmaxf((redQ[0][mq * 16 + g] + redQ[1][mq * 16 + g]) * (1.f / DD) - mu0 * mu0, 0.f);
    float v1 = fmaxf((redQ[0][mq * 16 + g + 8] + redQ[1][mq * 16 + g + 8]) * (1.f / DD) - mu1 * mu1, 0.f);
    float rst0 = rsqrtf(v0 + 1e-3f), rst1 = rsqrtf(v1 + 1e-3f);
    #pragma unroll
    for (int nt = 0; nt < 8; nt++) {
        int col = nh * 64 + nt * 8 + 2 * tg;
        float2 gm = *(const float2*)&g1[col];
        float2 bt = *(const float2*)&be1[col];
        float2 lo = {(acc[nt][0] - mu0) * rst0 * gm.x + bt.x,
                     (acc[nt][1] - mu0) * rst0 * gm.y + bt.y};
        float2 hi = {(acc[nt][2] - mu1) * rst1 * gm.x + bt.x,
                     (acc[nt][3] - mu1) * rst1 * gm.y + bt.y};
        *(float2*)&g_x[(size_t)r0 * DD + col] = lo;
        *(float2*)&g_x[(size_t)r1 * DD + col] = hi;
    }
}

// ---------------- Fused FFN: x@W1+b1, relu, @W2+b2, residual, LN2 ----------------
__global__ __launch_bounds__(256) void ffn_fused_kernel(
    const int* __restrict__ length,
    const float* __restrict__ W1, const float* __restrict__ b1,
    const float* __restrict__ W2, const float* __restrict__ b2,
    const float* __restrict__ g2, const float* __restrict__ be2) {
    int row0 = blockIdx.x * 64;
    int b = row0 >> 10;
    int valid_len = length[b] + 1;
    if ((row0 & (SS - 1)) >= valid_len) return;

    extern __shared__ unsigned smemu[];
    unsigned* Ax = smemu + FFN_AX_OFF;
    unsigned* Hs = smemu + FFN_HS_OFF;
    unsigned* Bst = smemu + FFN_BST_OFF;
    __shared__ float redS[2][64];
    __shared__ float redQ[2][64];

    int t = threadIdx.x, w = t >> 5, lane = t & 31;
    int g = lane >> 2, tg = lane & 3, mq = w >> 1, nh = w & 1;
    int rb = t >> 3, f0 = t & 7;

    // stage x tile (64x128) resident, stride 132
    {
        int r = t >> 2, cseg = (t & 3) * 32;
        const float* xp = g_x + (size_t)(row0 + r) * DD + cseg;
        #pragma unroll
        for (int j = 0; j < 8; j++)
            cp_async16(smem_u32(&Ax[r * FFN_AX_STRIDE + cseg + j * 4]), xp + j * 4);
        CP_COMMIT();
    }

    auto stageB = [&](int i, const float* Wg, int ldw, int krow0, int coloff) {
        unsigned (*Bs)[136] = (unsigned(*)[136])(Bst + (i % 3) * BS_ELEMS);
        const float* bp = Wg + (size_t)(krow0 + rb) * ldw + coloff;
        #pragma unroll
        for (int j = 0; j < 4; j++) {
            int c = (f0 + j * 8) * 4;
            cp_async16(smem_u32(&Bs[rb][c]), bp + c);
        }
        CP_COMMIT();
    };

    float acc[8][4];
    #pragma unroll
    for (int i = 0; i < 8; i++) acc[i][0] = acc[i][1] = acc[i][2] = acc[i][3] = 0.f;

    // ---- phase 1: hidden = relu(x @ W1 + b1), 16 (cg,kc) chunks ----
    stageB(0, W1, DFF, 0, 0);
    stageB(1, W1, DFF, 32, 0);
    for (int i = 0; i < 16; i++) {
        int cg = i >> 2, kc = i & 3;
        if (i + 2 < 16) {
            int i2 = i + 2;
            stageB(i2, W1, DFF, (i2 & 3) * 32, (i2 >> 2) * 128);
            CP_WAIT2();
        } else if (i + 1 < 16) {
            CP_WAIT1();
        } else {
            CP_WAIT0();
        }
        __syncthreads();
        compute_chunk_resA(acc, Ax, FFN_AX_STRIDE, kc * 32,
                           (const unsigned(*)[136])(Bst + (i % 3) * BS_ELEMS),
                           mq, nh, g, tg);
        __syncthreads();
        if (kc == 3) {
            int hr0 = mq * 16 + g, hr1 = hr0 + 8;
            #pragma unroll
            for (int nt = 0; nt < 8; nt++) {
                int col = cg * 128 + nh * 64 + nt * 8 + 2 * tg;
                float2 bi = *(const float2*)&b1[col];
                uint2 lo = {__float_as_uint(fmaxf(acc[nt][0] + bi.x, 0.f)),
                            __float_as_uint(fmaxf(acc[nt][1] + bi.y, 0.f))};
                uint2 hi = {__float_as_uint(fmaxf(acc[nt][2] + bi.x, 0.f)),
                            __float_as_uint(fmaxf(acc[nt][3] + bi.y, 0.f))};
                *(uint2*)&Hs[hr0 * FFN_HS_STRIDE + col] = lo;
                *(uint2*)&Hs[hr1 * FFN_HS_STRIDE + col] = hi;
                acc[nt][0] = acc[nt][1] = acc[nt][2] = acc[nt][3] = 0.f;
            }
        }
    }
    __syncthreads();

    // ---- phase 2: out = hidden @ W2, 16 k-chunks ----
    stageB(0, W2, DD, 0, 0);
    stageB(1, W2, DD, 32, 0);
    for (int kc = 0; kc < 16; kc++) {
        if (kc + 2 < 16) {
            stageB(kc + 2, W2, DD, (kc + 2) * 32, 0);
            CP_WAIT2();
        } else if (kc + 1 < 16) {
            CP_WAIT1();
        } else {
            CP_WAIT0();
        }
        __syncthreads();
        compute_chunk_resA(acc, Hs, FFN_HS_STRIDE, kc * 32,
                           (const unsigned(*)[136])(Bst + (kc % 3) * BS_ELEMS),
                           mq, nh, g, tg);
        __syncthreads();
    }

    // ---- epilogue: bias + residual + LN ----
    int r0 = row0 + mq * 16 + g, r1 = r0 + 8;
    float rs0 = 0.f, rq0 = 0.f, rs1 = 0.f, rq1 = 0.f;
    #pragma unroll
    for (int nt = 0; nt < 8; nt++) {
        int col = nh * 64 + nt * 8 + 2 * tg;
        float2 bi = *(const float2*)&b2[col];
        int hr0 = mq * 16 + g, hr1 = hr0 + 8;
        float e00 = __uint_as_float(Ax[hr0 * FFN_AX_STRIDE + col]);
        float e01 = __uint_as_float(Ax[hr0 * FFN_AX_STRIDE + col + 1]);
        float e10 = __uint_as_float(Ax[hr1 * FFN_AX_STRIDE + col]);
        float e11 = __uint_as_float(Ax[hr1 * FFN_AX_STRIDE + col + 1]);
        acc[nt][0] += bi.x + e00;
        acc[nt][1] += bi.y + e01;
        acc[nt][2] += bi.x + e10;
        acc[nt][3] += bi.y + e11;
        rs0 += acc[nt][0] + acc[nt][1];
        rq0 += acc[nt][0] * acc[nt][0] + acc[nt][1] * acc[nt][1];
        rs1 += acc[nt][2] + acc[nt][3];
        rq1 += acc[nt][2] * acc[nt][2] + acc[nt][3] * acc[nt][3];
    }
    rs0 += __shfl_xor_sync(0xffffffff, rs0, 1);
    rs0 += __shfl_xor_sync(0xffffffff, rs0, 2);
    rq0 += __shfl_xor_sync(0xffffffff, rq0, 1);
    rq0 += __shfl_xor_sync(0xffffffff, rq0, 2);
    rs1 += __shfl_xor_sync(0xffffffff, rs1, 1);
    rs1 += __shfl_xor_sync(0xffffffff, rs1, 2);
    rq1 += __shfl_xor_sync(0xffffffff, rq1, 1);
    rq1 += __shfl_xor_sync(0xffffffff, rq1, 2);
    if (tg == 0) {
        redS[nh][mq * 16 + g] = rs0;
        redS[nh][mq * 16 + g + 8] = rs1;
        redQ[nh][mq * 16 + g] = rq0;
        redQ[nh][mq * 16 + g + 8] = rq1;
    }
    __syncthreads();
    float mu0 = (redS[0][mq * 16 + g] + redS[1][mq * 16 + g]) * (1.f / DD);
    float mu1 = (redS[0][mq * 16 + g + 8] + redS[1][mq * 16 + g + 8]) * (1.f / DD);
    float v0 = fmaxf((redQ[0][mq * 16 + g] + redQ[1][mq * 16 + g]) * (1.f / DD) - mu0 * mu0, 0.f);
    float v1 = fmaxf((redQ[0][mq * 16 + g + 8] + redQ[1][mq * 16 + g + 8]) * (1.f / DD) - mu1 * mu1, 0.f);
    float rst0 = rsqrtf(v0 + 1e-3f), rst1 = rsqrtf(v1 + 1e-3f);
    #pragma unroll
    for (int nt = 0; nt < 8; nt++) {
        int col = nh * 64 + nt * 8 + 2 * tg;
        float2 gm = *(const float2*)&g2[col];
        float2 bt = *(const float2*)&be2[col];
        float2 lo = {(acc[nt][0] - mu0) * rst0 * gm.x + bt.x,
                     (acc[nt][1] - mu0) * rst0 * gm.y + bt.y};
        float2 hi = {(acc[nt][2] - mu1) * rst1 * gm.x + bt.x,
                     (acc[nt][3] - mu1) * rst1 * gm.y + bt.y};
        *(float2*)&g_x[(size_t)r0 * DD + col] = lo;
        *(float2*)&g_x[(size_t)r1 * DD + col] = hi;
    }
}

// ---------------- masked mean-pool + MLP head + sigmoid ----------------
__global__ __launch_bounds__(256) void head_kernel(
    const int* __restrict__ length,
    const float* __restrict__ Wm1, const float* __restrict__ bm1,
    const float* __restrict__ Wm2, const float* __restrict__ bm2,
    float* __restrict__ out) {
    int b = blockIdx.x;
    int t = threadIdx.x;
    __shared__ float part[2][DD];
    __shared__ float agg[DD];
    __shared__ float hh[MLPH];
    __shared__ float red[8];
    int cnt = length[b] + 1;
    int d = t & 127, grp = t >> 7;
    float s0 = 0.f, s1 = 0.f, s2 = 0.f, s3 = 0.f;
    int ss = grp;
    for (; ss + 6 < cnt; ss += 8) {
        s0 += g_x[(b * SS + ss) * DD + d];
        s1 += g_x[(b * SS + ss + 2) * DD + d];
        s2 += g_x[(b * SS + ss + 4) * DD + d];
        s3 += g_x[(b * SS + ss + 6) * DD + d];
    }
    for (; ss < cnt; ss += 2) s0 += g_x[(b * SS + ss) * DD + d];
    part[grp][d] = s0 + s1 + s2 + s3;
    __syncthreads();
    if (t < DD) agg[t] = (part[0][t] + part[1][t]) / (float)cnt;
    __syncthreads();
    {
        float acc = bm1[t];
        #pragma unroll 8
        for (int k = 0; k < DD; k++) acc += agg[k] * Wm1[k * MLPH + t];
        hh[t] = fmaxf(acc, 0.f);
    }
    __syncthreads();
    float v = hh[t] * Wm2[t];
    #pragma unroll
    for (int o = 16; o > 0; o >>= 1) v += __shfl_xor_sync(0xffffffff, v, o);
    if ((t & 31) == 0) red[t >> 5] = v;
    __syncthreads();
    if (t == 0) {
        float s = 0.f;
        #pragma unroll
        for (int i = 0; i < 8; i++) s += red[i];
        s += bm2[0];
        out[b] = 1.f / (1.f + __expf(-s));
    }
}

// ---------------- launch ----------------
extern "C" void kernel_launch(void* const* d_in, const int* in_sizes, int n_in,
                              void* d_out, int out_size) {
    (void)in_sizes; (void)n_in; (void)out_size;
    const float* demo       = (const float*)d_in[0];
    const float* times      = (const float*)d_in[1];
    const float* values     = (const float*)d_in[2];
    const int*   length     = (const int*)d_in[3];
    const float* timescales = (const float*)d_in[4];
    const float* W_demo = (const float*)d_in[5];
    const float* b_demo = (const float*)d_in[6];
    const float* W_val  = (const float*)d_in[7];
    const float* b_val  = (const float*)d_in[8];
    const float* Wq = (const float*)d_in[9];
    const float* bq = (const float*)d_in[10];
    const float* Wk = (const float*)d_in[11];
    const float* bk = (const float*)d_in[12];
    const float* Wv = (const float*)d_in[13];
    const float* bv = (const float*)d_in[14];
    const float* Wo = (const float*)d_in[15];
    const float* bo = (const float*)d_in[16];
    const float* ln1g = (const float*)d_in[17];
    const float* ln1b = (const float*)d_in[18];
    const float* W1 = (const float*)d_in[19];
    const float* b1 = (const float*)d_in[20];
    const float* W2 = (const float*)d_in[21];
    const float* b2 = (const float*)d_in[22];
    const float* ln2g = (const float*)d_in[23];
    const float* ln2b = (const float*)d_in[24];
    const float* Wm1 = (const float*)d_in[25];
    const float* bm1 = (const float*)d_in[26];
    const float* Wm2 = (const float*)d_in[27];
    const float* bm2 = (const float*)d_in[28];
    float* out = (float*)d_out;

    cudaFuncSetAttribute(embed_mma_kernel, cudaFuncAttributeMaxDynamicSharedMemorySize, EMBED_SMEM_BYTES);
    cudaFuncSetAttribute(qkv_mma_kernel, cudaFuncAttributeMaxDynamicSharedMemorySize, GEMM_SMEM_BYTES);
    cudaFuncSetAttribute(oproj_ln_mma_kernel, cudaFuncAttributeMaxDynamicSharedMemorySize, GEMM_SMEM_BYTES);
    cudaFuncSetAttribute(ffn_fused_kernel, cudaFuncAttributeMaxDynamicSharedMemorySize, FFN_SMEM_BYTES);

    demo_kernel<<<BB, 128>>>(demo, W_demo, b_demo);
    dim3 ge(16, BB);
    embed_mma_kernel<<<ge, 256, EMBED_SMEM_BYTES>>>(times, values, timescales, W_val, b_val, length);

    int ntiles = BB * SS / 64;
    for (int l = 0; l < NLAY; l++) {
        dim3 gq(ntiles, 3);
        qkv_mma_kernel<<<gq, 256, GEMM_SMEM_BYTES>>>(length,
            Wq + l * DD * DD, bq + l * DD,
            Wk + l * DD * DD, bk + l * DD,
            Wv + l * DD * DD, bv + l * DD);
        dim3 ag(SS / 64, HH, BB);
        attn_mma_kernel<<<ag, 128>>>(length);
        oproj_ln_mma_kernel<<<ntiles, 256, GEMM_SMEM_BYTES>>>(length,
            Wo + l * DD * DD, bo + l * DD, ln1g + l * DD, ln1b + l * DD);
        ffn_fused_kernel<<<ntiles, 256, FFN_SMEM_BYTES>>>(length,
            W1 + l * DD * DFF, b1 + l * DFF,
            W2 + l * DFF * DD, b2 + l * DD, ln2g + l * DD, ln2b + l * DD);
    }

    head_kernel<<<BB, 256>>>(length, Wm1, bm1, Wm2, bm2, out);
}

// round 13
// speedup vs baseline: 1.0453x; 1.0453x over previous
#include <cuda_runtime.h>
#include <math.h>

#define BB 16
#define LL 1023
#define SS 1024
#define DD 128
#define DVAL 64
#define NDEMO 16
#define HH 8
#define DH 16
#define NLAY 2
#define DFF 512
#define MLPH 256

#define AS_ELEMS (64 * 36)
#define BS_ELEMS (32 * 136)
#define STAGE_ELEMS (AS_ELEMS + BS_ELEMS)
#define GEMM_SMEM_BYTES (3 * STAGE_ELEMS * 4)

// attention smem layout (unsigned units)
#define ATTN_KS_OFF 0
#define ATTN_VS_OFF (2 * 64 * 20)                  // 2560
#define ATTN_PS_OFF (ATTN_VS_OFF + 2 * 64 * 24)    // 5632
#define ATTN_SMEM_BYTES ((ATTN_PS_OFF + 128 * 68) * 4)  // 57344

// ---------------- device scratch (no allocs allowed) ----------------
__device__ float g_x[BB * SS * DD];
__device__ float g_q[BB * SS * DD];
__device__ float g_k[BB * SS * DD];
__device__ float g_v[BB * SS * DD];
__device__ float g_o[BB * SS * DD];
__device__ float g_h[BB * SS * DFF];

__device__ __forceinline__ unsigned f2tf(float x) {
    unsigned r;
    asm("cvt.rna.tf32.f32 %0, %1;" : "=r"(r) : "f"(x));
    return r;
}

__device__ __forceinline__ float ex2f(float x) {
    float r;
    asm("ex2.approx.ftz.f32 %0, %1;" : "=f"(r) : "f"(x));
    return r;
}

__device__ __forceinline__ void mma_tf32(float* c, unsigned a0, unsigned a1,
                                         unsigned a2, unsigned a3,
                                         unsigned b0, unsigned b1) {
    asm("mma.sync.aligned.m16n8k8.row.col.f32.tf32.tf32.f32 "
        "{%0,%1,%2,%3},{%4,%5,%6,%7},{%8,%9},{%0,%1,%2,%3};"
        : "+f"(c[0]), "+f"(c[1]), "+f"(c[2]), "+f"(c[3])
        : "r"(a0), "r"(a1), "r"(a2), "r"(a3), "r"(b0), "r"(b1));
}

__device__ __forceinline__ unsigned smem_u32(const void* p) {
    return (unsigned)__cvta_generic_to_shared(p);
}

__device__ __forceinline__ void cp_async16(unsigned s, const void* g) {
    asm volatile("cp.async.ca.shared.global [%0], [%1], 16;" :: "r"(s), "l"(g));
}
#define CP_COMMIT() asm volatile("cp.async.commit_group;" ::: "memory")
#define CP_WAIT2() asm volatile("cp.async.wait_group 2;" ::: "memory")
#define CP_WAIT1() asm volatile("cp.async.wait_group 1;" ::: "memory")
#define CP_WAIT0() asm volatile("cp.async.wait_group 0;" ::: "memory")

// ---------------- GEMM tile: 64 rows x 128 cols, 256 threads ----------------
__device__ __forceinline__ void compute_chunk(float (*acc)[4],
                                              const unsigned (*As)[36],
                                              const unsigned (*Bs)[136],
                                              int mq, int nh, int g, int tg) {
    int mr = mq * 16;
    #pragma unroll
    for (int ks = 0; ks < 4; ks++) {
        unsigned a0 = As[mr + g][ks * 8 + tg];
        unsigned a1 = As[mr + g + 8][ks * 8 + tg];
        unsigned a2 = As[mr + g][ks * 8 + tg + 4];
        unsigned a3 = As[mr + g + 8][ks * 8 + tg + 4];
        #pragma unroll
        for (int nt = 0; nt < 8; nt++) {
            unsigned b0 = Bs[ks * 8 + tg][nh * 64 + nt * 8 + g];
            unsigned b1 = Bs[ks * 8 + tg + 4][nh * 64 + nt * 8 + g];
            mma_tf32(acc[nt], a0, a1, a2, a3, b0, b1);
        }
    }
}

// cp.async triple-buffered (depth-2) GEMM mainloop over nK k-chunks of 32.
__device__ __forceinline__ void gemm_mainloop_cp(
    float (*acc)[4], unsigned* smemu,
    const float* Ag, int lda, const float* Wg, int ldw, int nK,
    int t, int mq, int nh, int g, int tg) {
    int ra = t >> 2, c0 = (t & 3) * 8;
    int rb = t >> 3, f0 = t & 7;

    auto stage = [&](int kc) {
        unsigned* base = smemu + (kc % 3) * STAGE_ELEMS;
        unsigned (*As)[36] = (unsigned(*)[36])base;
        unsigned (*Bs)[136] = (unsigned(*)[136])(base + AS_ELEMS);
        const float* ap = Ag + (size_t)ra * lda + kc * 32 + c0;
        cp_async16(smem_u32(&As[ra][c0]), ap);
        cp_async16(smem_u32(&As[ra][c0 + 4]), ap + 4);
        const float* bp = Wg + (size_t)(kc * 32 + rb) * ldw;
        #pragma unroll
        for (int j = 0; j < 4; j++) {
            int c = (f0 + j * 8) * 4;
            cp_async16(smem_u32(&Bs[rb][c]), bp + c);
        }
        CP_COMMIT();
    };

    stage(0);
    if (nK > 1) stage(1);
    for (int kc = 0; kc < nK; kc++) {
        if (kc + 2 < nK) {
            stage(kc + 2);
            CP_WAIT2();
        } else if (kc + 1 < nK) {
            CP_WAIT1();
        } else {
            CP_WAIT0();
        }
        __syncthreads();
        unsigned* base = smemu + (kc % 3) * STAGE_ELEMS;
        compute_chunk(acc, (const unsigned(*)[36])base,
                      (const unsigned(*)[136])(base + AS_ELEMS), mq, nh, g, tg);
        __syncthreads();
    }
}

// ---------------- embedding ----------------
__global__ __launch_bounds__(256) void embed_kernel(
    const float* __restrict__ demo, const float* __restrict__ times,
    const float* __restrict__ values, const float* __restrict__ timescales,
    const float* __restrict__ W_demo, const float* __restrict__ b_demo,
    const float* __restrict__ W_val, const float* __restrict__ b_val,
    const int* __restrict__ length) {
    int idx = blockIdx.x * blockDim.x + threadIdx.x;
    if (idx >= BB * SS * DD) return;
    int d = idx % DD;
    int s = (idx / DD) % SS;
    int b = idx / (DD * SS);
    if (s > length[b]) return;
    float out;
    if (s == 0) {
        float acc = b_demo[d];
        #pragma unroll
        for (int k = 0; k < NDEMO; k++) acc += demo[b * NDEMO + k] * W_demo[k * DD + d];
        out = acc;
    } else {
        int t = s - 1;
        float acc = b_val[d];
        const float4* vrow = (const float4*)(values + (b * LL + t) * DVAL);
        #pragma unroll
        for (int k4 = 0; k4 < DVAL / 4; k4++) {
            float4 vv = vrow[k4];
            acc += vv.x * W_val[(k4 * 4 + 0) * DD + d];
            acc += vv.y * W_val[(k4 * 4 + 1) * DD + d];
            acc += vv.z * W_val[(k4 * 4 + 2) * DD + d];
            acc += vv.w * W_val[(k4 * 4 + 3) * DD + d];
        }
        float tm = times[b * LL + t];
        float st = tm / timescales[d & 63];
        out = acc + ((d < 64) ? __sinf(st) : __cosf(st));
    }
    g_x[idx] = out;
}

// ---------------- QKV: grid (tiles, 3) ----------------
__global__ __launch_bounds__(256) void qkv_mma_kernel(
    const int* __restrict__ length,
    const float* __restrict__ Wq, const float* __restrict__ bq,
    const float* __restrict__ Wk, const float* __restrict__ bk,
    const float* __restrict__ Wv, const float* __restrict__ bv) {
    int row0 = blockIdx.x * 64;
    int b = row0 >> 10;
    int valid_len = length[b] + 1;
    if ((row0 & (SS - 1)) >= valid_len) return;
    int wi = blockIdx.y;
    const float* W = (wi == 0) ? Wq : (wi == 1) ? Wk : Wv;
    const float* bias = (wi == 0) ? bq : (wi == 1) ? bk : bv;
    float* out = (wi == 0) ? g_q : (wi == 1) ? g_k : g_v;

    extern __shared__ unsigned smemu[];
    int t = threadIdx.x, w = t >> 5, lane = t & 31;
    int g = lane >> 2, tg = lane & 3, mq = w >> 1, nh = w & 1;

    float acc[8][4];
    #pragma unroll
    for (int i = 0; i < 8; i++) acc[i][0] = acc[i][1] = acc[i][2] = acc[i][3] = 0.f;

    gemm_mainloop_cp(acc, smemu, g_x + (size_t)row0 * DD, DD, W, DD, 4,
                     t, mq, nh, g, tg);

    int r0 = row0 + mq * 16 + g, r1 = r0 + 8;
    #pragma unroll
    for (int nt = 0; nt < 8; nt++) {
        int col = nh * 64 + nt * 8 + 2 * tg;
        float2 bi = *(const float2*)&bias[col];
        float2 lo = {acc[nt][0] + bi.x, acc[nt][1] + bi.y};
        float2 hi = {acc[nt][2] + bi.x, acc[nt][3] + bi.y};
        *(float2*)&out[(size_t)r0 * DD + col] = lo;
        *(float2*)&out[(size_t)r1 * DD + col] = hi;
    }
}

// ---------------- flash attention: 128 queries/block, warp = m32 ----------------
__global__ __launch_bounds__(128) void attn_mma_kernel(const int* __restrict__ length) {
    const int qt = blockIdx.x, h = blockIdx.y, b = blockIdx.z;
    int valid_len = length[b] + 1;
    int q0 = qt * 128;
    if (q0 >= valid_len) return;

    extern __shared__ unsigned smemu[];
    unsigned (*Ks)[64][20] = (unsigned(*)[64][20])(smemu + ATTN_KS_OFF);
    unsigned (*Vs)[64][24] = (unsigned(*)[64][24])(smemu + ATTN_VS_OFF);
    unsigned (*Ps)[68] = (unsigned(*)[68])(smemu + ATTN_PS_OFF);

    int t = threadIdx.x;
    int w = t >> 5, lane = t & 31;
    int g = lane >> 2, tg = lane & 3;
    int qrow_base = b * SS + q0 + w * 32;   // warp covers 32 queries (2 m16 tiles)

    int key_st = t >> 1, d8 = (t & 1) << 3;
    auto stage = [&](int c, int buf) {
        size_t src = (size_t)(b * SS + c * 64 + key_st) * DD + h * DH + d8;
        const float* kp = g_k + src;
        cp_async16(smem_u32(&Ks[buf][key_st][d8]), kp);
        cp_async16(smem_u32(&Ks[buf][key_st][d8 + 4]), kp + 4);
        const float* vp = g_v + src;
        cp_async16(smem_u32(&Vs[buf][key_st][d8]), vp);
        cp_async16(smem_u32(&Vs[buf][key_st][d8 + 4]), vp + 4);
        CP_COMMIT();
    };

    const float qscale = 0.25f * 1.44269504f;
    unsigned qa[2][2][4];  // [mt][ks]
    #pragma unroll
    for (int mt = 0; mt < 2; mt++)
        #pragma unroll
        for (int ks = 0; ks < 2; ks++) {
            int r_lo = (qrow_base + mt * 16 + g) * DD + h * DH + ks * 8 + tg;
            int r_hi = r_lo + 8 * DD;
            qa[mt][ks][0] = f2tf(g_q[r_lo] * qscale);
            qa[mt][ks][1] = f2tf(g_q[r_hi] * qscale);
            qa[mt][ks][2] = f2tf(g_q[r_lo + 4] * qscale);
            qa[mt][ks][3] = f2tf(g_q[r_hi + 4] * qscale);
        }

    float l[2][2] = {{0.f, 0.f}, {0.f, 0.f}};   // [mt][rowhalf]
    float oc[2][2][4];                          // [mt][dtile]
    #pragma unroll
    for (int mt = 0; mt < 2; mt++)
        #pragma unroll
        for (int dt = 0; dt < 2; dt++)
            oc[mt][dt][0] = oc[mt][dt][1] = oc[mt][dt][2] = oc[mt][dt][3] = 0.f;

    int nch = (valid_len + 63) >> 6;
    stage(0, 0);

    for (int c = 0; c < nch; c++) {
        int bi = c & 1;
        if (c + 1 < nch) {
            stage(c + 1, bi ^ 1);
            CP_WAIT1();
        } else {
            CP_WAIT0();
        }
        __syncthreads();

        int limit = valid_len - c * 64;
        // S = Q K^T per nt; K fragments loaded once, reused for both m16 tiles
        #pragma unroll
        for (int nt = 0; nt < 8; nt++) {
            unsigned kb0[2], kb1[2];
            #pragma unroll
            for (int ks = 0; ks < 2; ks++) {
                kb0[ks] = Ks[bi][nt * 8 + g][ks * 8 + tg];
                kb1[ks] = Ks[bi][nt * 8 + g][ks * 8 + tg + 4];
            }
            int col0 = nt * 8 + 2 * tg, col1 = col0 + 1;
            bool m0 = col0 < limit, m1 = col1 < limit;
            #pragma unroll
            for (int mt = 0; mt < 2; mt++) {
                float sc[4] = {0.f, 0.f, 0.f, 0.f};
                #pragma unroll
                for (int ks = 0; ks < 2; ks++)
                    mma_tf32(sc, qa[mt][ks][0], qa[mt][ks][1], qa[mt][ks][2],
                             qa[mt][ks][3], kb0[ks], kb1[ks]);
                float p0 = ex2f(m0 ? sc[0] : -1e30f);
                float p1 = ex2f(m1 ? sc[1] : -1e30f);
                float p2 = ex2f(m0 ? sc[2] : -1e30f);
                float p3 = ex2f(m1 ? sc[3] : -1e30f);
                l[mt][0] += p0 + p1;
                l[mt][1] += p2 + p3;
                int prow = w * 32 + mt * 16 + g;
                uint2 lo = {__float_as_uint(p0), __float_as_uint(p1)};
                uint2 hi = {__float_as_uint(p2), __float_as_uint(p3)};
                *(uint2*)&Ps[prow][col0] = lo;
                *(uint2*)&Ps[prow + 8][col0] = hi;
            }
        }
        __syncwarp();

        // O += P V; V fragments loaded once per (j, dtile), reused for both mt
        #pragma unroll
        for (int j = 0; j < 8; j++) {
            unsigned vb0[2], vb1[2];
            #pragma unroll
            for (int dt = 0; dt < 2; dt++) {
                vb0[dt] = Vs[bi][j * 8 + tg][dt * 8 + g];
                vb1[dt] = Vs[bi][j * 8 + tg + 4][dt * 8 + g];
            }
            #pragma unroll
            for (int mt = 0; mt < 2; mt++) {
                int prow = w * 32 + mt * 16 + g;
                unsigned pa0 = Ps[prow][j * 8 + tg];
                unsigned pa1 = Ps[prow + 8][j * 8 + tg];
                unsigned pa2 = Ps[prow][j * 8 + tg + 4];
                unsigned pa3 = Ps[prow + 8][j * 8 + tg + 4];
                #pragma unroll
                for (int dt = 0; dt < 2; dt++)
                    mma_tf32(oc[mt][dt], pa0, pa1, pa2, pa3, vb0[dt], vb1[dt]);
            }
        }
        __syncthreads();
    }

    #pragma unroll
    for (int mt = 0; mt < 2; mt++) {
        l[mt][0] += __shfl_xor_sync(0xffffffff, l[mt][0], 1);
        l[mt][0] += __shfl_xor_sync(0xffffffff, l[mt][0], 2);
        l[mt][1] += __shfl_xor_sync(0xffffffff, l[mt][1], 1);
        l[mt][1] += __shfl_xor_sync(0xffffffff, l[mt][1], 2);
        float inv0 = 1.f / l[mt][0], inv1 = 1.f / l[mt][1];
        #pragma unroll
        for (int dt = 0; dt < 2; dt++) {
            int col = h * DH + dt * 8 + 2 * tg;
            int r = qrow_base + mt * 16 + g;
            float2 lo = {oc[mt][dt][0] * inv0, oc[mt][dt][1] * inv0};
            float2 hi = {oc[mt][dt][2] * inv1, oc[mt][dt][3] * inv1};
            *(float2*)&g_o[(size_t)r * DD + col] = lo;
            *(float2*)&g_o[(size_t)(r + 8) * DD + col] = hi;
        }
    }
}

// ---------------- O-proj + residual + LN1 ----------------
__global__ __launch_bounds__(256) void oproj_ln_mma_kernel(
    const int* __restrict__ length,
    const float* __restrict__ Wo, const float* __restrict__ bo,
    const float* __restrict__ g1, const float* __restrict__ be1) {
    int row0 = blockIdx.x * 64;
    int b = row0 >> 10;
    int valid_len = length[b] + 1;
    if ((row0 & (SS - 1)) >= valid_len) return;

    extern __shared__ unsigned smemu[];
    __shared__ float redS[2][64];
    __shared__ float redQ[2][64];
    int t = threadIdx.x, w = t >> 5, lane = t & 31;
    int g = lane >> 2, tg = lane & 3, mq = w >> 1, nh = w & 1;

    float acc[8][4];
    #pragma unroll
    for (int i = 0; i < 8; i++) acc[i][0] = acc[i][1] = acc[i][2] = acc[i][3] = 0.f;

    gemm_mainloop_cp(acc, smemu, g_o + (size_t)row0 * DD, DD, Wo, DD, 4,
                     t, mq, nh, g, tg);

    int r0 = row0 + mq * 16 + g, r1 = r0 + 8;
    float rs0 = 0.f, rq0 = 0.f, rs1 = 0.f, rq1 = 0.f;
    #pragma unroll
    for (int nt = 0; nt < 8; nt++) {
        int col = nh * 64 + nt * 8 + 2 * tg;
        float2 bi = *(const float2*)&bo[col];
        float2 e0 = *(const float2*)&g_x[(size_t)r0 * DD + col];
        float2 e1 = *(const float2*)&g_x[(size_t)r1 * DD + col];
        acc[nt][0] += bi.x + e0.x;
        acc[nt][1] += bi.y + e0.y;
        acc[nt][2] += bi.x + e1.x;
        acc[nt][3] += bi.y + e1.y;
        rs0 += acc[nt][0] + acc[nt][1];
        rq0 += acc[nt][0] * acc[nt][0] + acc[nt][1] * acc[nt][1];
        rs1 += acc[nt][2] + acc[nt][3];
        rq1 += acc[nt][2] * acc[nt][2] + acc[nt][3] * acc[nt][3];
    }
    rs0 += __shfl_xor_sync(0xffffffff, rs0, 1);
    rs0 += __shfl_xor_sync(0xffffffff, rs0, 2);
    rq0 += __shfl_xor_sync(0xffffffff, rq0, 1);
    rq0 += __shfl_xor_sync(0xffffffff, rq0, 2);
    rs1 += __shfl_xor_sync(0xffffffff, rs1, 1);
    rs1 += __shfl_xor_sync(0xffffffff, rs1, 2);
    rq1 += __shfl_xor_sync(0xffffffff, rq1, 1);
    rq1 += __shfl_xor_sync(0xffffffff, rq1, 2);
    if (tg == 0) {
        redS[nh][mq * 16 + g] = rs0;
        redS[nh][mq * 16 + g + 8] = rs1;
        redQ[nh][mq * 16 + g] = rq0;
        redQ[nh][mq * 16 + g + 8] = rq1;
    }
    __syncthreads();
    float mu0 = (redS[0][mq * 16 + g] + redS[1][mq * 16 + g]) * (1.f / DD);
    float mu1 = (redS[0][mq * 16 + g + 8] + redS[1][mq * 16 + g + 8]) * (1.f / DD);
    float v0 = fmaxf((redQ[0][mq * 16 + g] + redQ[1][mq * 16 + g]) * (1.f / DD) - mu0 * mu0, 0.f);
    float v1 = fmaxf((redQ[0][mq * 16 + g + 8] + redQ[1][mq * 16 + g + 8]) * (1.f / DD) - mu1 * mu1, 0.f);
    float rst0 = rsqrtf(v0 + 1e-3f), rst1 = rsqrtf(v1 + 1e-3f);
    #pragma unroll
    for (int nt = 0; nt < 8; nt++) {
        int col = nh * 64 + nt * 8 + 2 * tg;
        float2 gm = *(const float2*)&g1[col];
        float2 bt = *(const float2*)&be1[col];
        float2 lo = {(acc[nt][0] - mu0) * rst0 * gm.x + bt.x,
                     (acc[nt][1] - mu0) * rst0 * gm.y + bt.y};
        float2 hi = {(acc[nt][2] - mu1) * rst1 * gm.x + bt.x,
                     (acc[nt][3] - mu1) * rst1 * gm.y + bt.y};
        *(float2*)&g_x[(size_t)r0 * DD + col] = lo;
        *(float2*)&g_x[(size_t)r1 * DD + col] = hi;
    }
}

// ---------------- FFN1: grid (tiles, 4) ----------------
__global__ __launch_bounds__(256) void ffn1_mma_kernel(
    const int* __restrict__ length,
    const float* __restrict__ W1, const float* __restrict__ b1) {
    int row0 = blockIdx.x * 64;
    int b = row0 >> 10;
    int valid_len = length[b] + 1;
    if ((row0 & (SS - 1)) >= valid_len) return;
    int ncol0 = blockIdx.y * 128;

    extern __shared__ unsigned smemu[];
    int t = threadIdx.x, w = t >> 5, lane = t & 31;
    int g = lane >> 2, tg = lane & 3, mq = w >> 1, nh = w & 1;

    float acc[8][4];
    #pragma unroll
    for (int i = 0; i < 8; i++) acc[i][0] = acc[i][1] = acc[i][2] = acc[i][3] = 0.f;

    gemm_mainloop_cp(acc, smemu, g_x + (size_t)row0 * DD, DD, W1 + ncol0, DFF, 4,
                     t, mq, nh, g, tg);

    int r0 = row0 + mq * 16 + g, r1 = r0 + 8;
    #pragma unroll
    for (int nt = 0; nt < 8; nt++) {
        int col = ncol0 + nh * 64 + nt * 8 + 2 * tg;
        float2 bi = *(const float2*)&b1[col];
        float2 lo = {fmaxf(acc[nt][0] + bi.x, 0.f), fmaxf(acc[nt][1] + bi.y, 0.f)};
        float2 hi = {fmaxf(acc[nt][2] + bi.x, 0.f), fmaxf(acc[nt][3] + bi.y, 0.f)};
        *(float2*)&g_h[(size_t)r0 * DFF + col] = lo;
        *(float2*)&g_h[(size_t)r1 * DFF + col] = hi;
    }
}

// ---------------- FFN2 + residual + LN2 ----------------
__global__ __launch_bounds__(256) void ffn2_ln_mma_kernel(
    const int* __restrict__ length,
    const float* __restrict__ W2, const float* __restrict__ b2,
    const float* __restrict__ g2, const float* __restrict__ be2) {
    int row0 = blockIdx.x * 64;
    int b = row0 >> 10;
    int valid_len = length[b] + 1;
    if ((row0 & (SS - 1)) >= valid_len) return;

    extern __shared__ unsigned smemu[];
    __shared__ float redS[2][64];
    __shared__ float redQ[2][64];
    int t = threadIdx.x, w = t >> 5, lane = t & 31;
    int g = lane >> 2, tg = lane & 3, mq = w >> 1, nh = w & 1;

    float acc[8][4];
    #pragma unroll
    for (int i = 0; i < 8; i++) acc[i][0] = acc[i][1] = acc[i][2] = acc[i][3] = 0.f;

    gemm_mainloop_cp(acc, smemu, g_h + (size_t)row0 * DFF, DFF, W2, DD, DFF / 32,
                     t, mq, nh, g, tg);

    int r0 = row0 + mq * 16 + g, r1 = r0 + 8;
    float rs0 = 0.f, rq0 = 0.f, rs1 = 0.f, rq1 = 0.f;
    #pragma unroll
    for (int nt = 0; nt < 8; nt++) {
        int col = nh * 64 + nt * 8 + 2 * tg;
        float2 bi = *(const float2*)&b2[col];
        float2 e0 = *(const float2*)&g_x[(size_t)r0 * DD + col];
        float2 e1 = *(const float2*)&g_x[(size_t)r1 * DD + col];
        acc[nt][0] += bi.x + e0.x;
        acc[nt][1] += bi.y + e0.y;
        acc[nt][2] += bi.x + e1.x;
        acc[nt][3] += bi.y + e1.y;
        rs0 += acc[nt][0] + acc[nt][1];
        rq0 += acc[nt][0] * acc[nt][0] + acc[nt][1] * acc[nt][1];
        rs1 += acc[nt][2] + acc[nt][3];
        rq1 += acc[nt][2] * acc[nt][2] + acc[nt][3] * acc[nt][3];
    }
    rs0 += __shfl_xor_sync(0xffffffff, rs0, 1);
    rs0 += __shfl_xor_sync(0xffffffff, rs0, 2);
    rq0 += __shfl_xor_sync(0xffffffff, rq0, 1);
    rq0 += __shfl_xor_sync(0xffffffff, rq0, 2);
    rs1 += __shfl_xor_sync(0xffffffff, rs1, 1);
    rs1 += __shfl_xor_sync(0xffffffff, rs1, 2);
    rq1 += __shfl_xor_sync(0xffffffff, rq1, 1);
    rq1 += __shfl_xor_sync(0xffffffff, rq1, 2);
    if (tg == 0) {
        redS[nh][mq * 16 + g] = rs0;
        redS[nh][mq * 16 + g + 8] = rs1;
        redQ[nh][mq * 16 + g] = rq0;
        redQ[nh][mq * 16 + g + 8] = rq1;
    }
    __syncthreads();
    float mu0 = (redS[0][mq * 16 + g] + redS[1][mq * 16 + g]) * (1.f / DD);
    float mu1 = (redS[0][mq * 16 + g + 8] + redS[1][mq * 16 + g + 8]) * (1.f / DD);
    float v0 = fmaxf((redQ[0][mq * 16 + g] + redQ[1][mq * 16 + g]) * (1.f / DD) - mu0 * mu0, 0.f);
    float v1 = fmaxf((redQ[0][mq * 16 + g + 8] + redQ[1][mq * 16 + g + 8]) * (1.f / DD) - mu1 * mu1, 0.f);
    float rst0 = rsqrtf(v0 + 1e-3f), rst1 = rsqrtf(v1 + 1e-3f);
    #pragma unroll
    for (int nt = 0; nt < 8; nt++) {
        int col = nh * 64 + nt * 8 + 2 * tg;
        float2 gm = *(const float2*)&g2[col];
        float2 bt = *(const float2*)&be2[col];
        float2 lo = {(acc[nt][0] - mu0) * rst0 * gm.x + bt.x,
                     (acc[nt][1] - mu0) * rst0 * gm.y + bt.y};
        float2 hi = {(acc[nt][2] - mu1) * rst1 * gm.x + bt.x,
                     (acc[nt][3] - mu1) * rst1 * gm.y + bt.y};
        *(float2*)&g_x[(size_t)r0 * DD + col] = lo;
        *(float2*)&g_x[(size_t)r1 * DD + col] = hi;
    }
}

// ---------------- masked mean-pool + MLP head + sigmoid ----------------
__global__ __launch_bounds__(256) void head_kernel(
    const int* __restrict__ length,
    const float* __restrict__ Wm1, const float* __restrict__ bm1,
    const float* __restrict__ Wm2, const float* __restrict__ bm2,
    float* __restrict__ out) {
    int b = blockIdx.x;
    int t = threadIdx.x;
    __shared__ float part[2][DD];
    __shared__ float agg[DD];
    __shared__ float hh[MLPH];
    __shared__ float red[8];
    int cnt = length[b] + 1;
    int d = t & 127, grp = t >> 7;
    float s0 = 0.f, s1 = 0.f, s2 = 0.f, s3 = 0.f;
    int ss = grp;
    for (; ss + 6 < cnt; ss += 8) {
        s0 += g_x[(b * SS + ss) * DD + d];
        s1 += g_x[(b * SS + ss + 2) * DD + d];
        s2 += g_x[(b * SS + ss + 4) * DD + d];
        s3 += g_x[(b * SS + ss + 6) * DD + d];
    }
    for (; ss < cnt; ss += 2) s0 += g_x[(b * SS + ss) * DD + d];
    part[grp][d] = s0 + s1 + s2 + s3;
    __syncthreads();
    if (t < DD) agg[t] = (part[0][t] + part[1][t]) / (float)cnt;
    __syncthreads();
    {
        float acc = bm1[t];
        #pragma unroll 8
        for (int k = 0; k < DD; k++) acc += agg[k] * Wm1[k * MLPH + t];
        hh[t] = fmaxf(acc, 0.f);
    }
    __syncthreads();
    float v = hh[t] * Wm2[t];
    #pragma unroll
    for (int o = 16; o > 0; o >>= 1) v += __shfl_xor_sync(0xffffffff, v, o);
    if ((t & 31) == 0) red[t >> 5] = v;
    __syncthreads();
    if (t == 0) {
        float s = 0.f;
        #pragma unroll
        for (int i = 0; i < 8; i++) s += red[i];
        s += bm2[0];
        out[b] = 1.f / (1.f + __expf(-s));
    }
}

// ---------------- launch ----------------
extern "C" void kernel_launch(void* const* d_in, const int* in_sizes, int n_in,
                              void* d_out, int out_size) {
    (void)in_sizes; (void)n_in; (void)out_size;
    const float* demo       = (const float*)d_in[0];
    const float* times      = (const float*)d_in[1];
    const float* values     = (const float*)d_in[2];
    const int*   length     = (const int*)d_in[3];
    const float* timescales = (const float*)d_in[4];
    const float* W_demo = (const float*)d_in[5];
    const float* b_demo = (const float*)d_in[6];
    const float* W_val  = (const float*)d_in[7];
    const float* b_val  = (const float*)d_in[8];
    const float* Wq = (const float*)d_in[9];
    const float* bq = (const float*)d_in[10];
    const float* Wk = (const float*)d_in[11];
    const float* bk = (const float*)d_in[12];
    const float* Wv = (const float*)d_in[13];
    const float* bv = (const float*)d_in[14];
    const float* Wo = (const float*)d_in[15];
    const float* bo = (const float*)d_in[16];
    const float* ln1g = (const float*)d_in[17];
    const float* ln1b = (const float*)d_in[18];
    const float* W1 = (const float*)d_in[19];
    const float* b1 = (const float*)d_in[20];
    const float* W2 = (const float*)d_in[21];
    const float* b2 = (const float*)d_in[22];
    const float* ln2g = (const float*)d_in[23];
    const float* ln2b = (const float*)d_in[24];
    const float* Wm1 = (const float*)d_in[25];
    const float* bm1 = (const float*)d_in[26];
    const float* Wm2 = (const float*)d_in[27];
    const float* bm2 = (const float*)d_in[28];
    float* out = (float*)d_out;

    cudaFuncSetAttribute(qkv_mma_kernel, cudaFuncAttributeMaxDynamicSharedMemorySize, GEMM_SMEM_BYTES);
    cudaFuncSetAttribute(oproj_ln_mma_kernel, cudaFuncAttributeMaxDynamicSharedMemorySize, GEMM_SMEM_BYTES);
    cudaFuncSetAttribute(ffn1_mma_kernel, cudaFuncAttributeMaxDynamicSharedMemorySize, GEMM_SMEM_BYTES);
    cudaFuncSetAttribute(ffn2_ln_mma_kernel, cudaFuncAttributeMaxDynamicSharedMemorySize, GEMM_SMEM_BYTES);
    cudaFuncSetAttribute(attn_mma_kernel, cudaFuncAttributeMaxDynamicSharedMemorySize, ATTN_SMEM_BYTES);

    embed_kernel<<<(BB * SS * DD + 255) / 256, 256>>>(
        demo, times, values, timescales, W_demo, b_demo, W_val, b_val, length);

    int ntiles = BB * SS / 64;
    for (int l = 0; l < NLAY; l++) {
        dim3 gq(ntiles, 3);
        qkv_mma_kernel<<<gq, 256, GEMM_SMEM_BYTES>>>(length,
            Wq + l * DD * DD, bq + l * DD,
            Wk + l * DD * DD, bk + l * DD,
            Wv + l * DD * DD, bv + l * DD);
        dim3 ag(SS / 128, HH, BB);
        attn_mma_kernel<<<ag, 128, ATTN_SMEM_BYTES>>>(length);
        oproj_ln_mma_kernel<<<ntiles, 256, GEMM_SMEM_BYTES>>>(length,
            Wo + l * DD * DD, bo + l * DD, ln1g + l * DD, ln1b + l * DD);
        dim3 gf(ntiles, 4);
        ffn1_mma_kernel<<<gf, 256, GEMM_SMEM_BYTES>>>(length, W1 + l * DD * DFF, b1 + l * DFF);
        ffn2_ln_mma_kernel<<<ntiles, 256, GEMM_SMEM_BYTES>>>(length,
            W2 + l * DFF * DD, b2 + l * DD, ln2g + l * DD, ln2b + l * DD);
    }

    head_kernel<<<BB, 256>>>(length, Wm1, bm1, Wm2, bm2, out);
}

// round 14
// speedup vs baseline: 1.1547x; 1.1046x over previous
#include <cuda_runtime.h>
#include <math.h>

#define BB 16
#define LL 1023
#define SS 1024
#define DD 128
#define DVAL 64
#define NDEMO 16
#define HH 8
#define DH 16
#define NLAY 2
#define DFF 512
#define MLPH 256

#define AS_ELEMS (64 * 36)
#define BS_ELEMS (32 * 136)
#define STAGE_ELEMS (AS_ELEMS + BS_ELEMS)
#define GEMM_SMEM_BYTES (3 * STAGE_ELEMS * 4)
#define EMBED_SMEM_BYTES (2 * STAGE_ELEMS * 4)

// attention smem layout (unsigned units)
#define ATTN_KS_OFF 0
#define ATTN_VS_OFF (2 * 64 * 20)
#define ATTN_PS_OFF (ATTN_VS_OFF + 2 * 64 * 24)
#define ATTN_SMEM_BYTES ((ATTN_PS_OFF + 128 * 68) * 4)  // 57344

// ---------------- device scratch (no allocs allowed) ----------------
__device__ float g_x[BB * SS * DD];
__device__ float g_q[BB * SS * DD];   // head-major: [b][h][s][DH]
__device__ float g_k[BB * SS * DD];   // head-major
__device__ float g_v[BB * SS * DD];   // head-major
__device__ float g_o[BB * SS * DD];   // token-major
__device__ float g_h[BB * SS * DFF];

__device__ __forceinline__ unsigned f2tf(float x) {
    unsigned r;
    asm("cvt.rna.tf32.f32 %0, %1;" : "=r"(r) : "f"(x));
    return r;
}

__device__ __forceinline__ float ex2f(float x) {
    float r;
    asm("ex2.approx.ftz.f32 %0, %1;" : "=f"(r) : "f"(x));
    return r;
}

__device__ __forceinline__ void mma_tf32(float* c, unsigned a0, unsigned a1,
                                         unsigned a2, unsigned a3,
                                         unsigned b0, unsigned b1) {
    asm("mma.sync.aligned.m16n8k8.row.col.f32.tf32.tf32.f32 "
        "{%0,%1,%2,%3},{%4,%5,%6,%7},{%8,%9},{%0,%1,%2,%3};"
        : "+f"(c[0]), "+f"(c[1]), "+f"(c[2]), "+f"(c[3])
        : "r"(a0), "r"(a1), "r"(a2), "r"(a3), "r"(b0), "r"(b1));
}

__device__ __forceinline__ unsigned smem_u32(const void* p) {
    return (unsigned)__cvta_generic_to_shared(p);
}

__device__ __forceinline__ void cp_async16(unsigned s, const void* g) {
    asm volatile("cp.async.ca.shared.global [%0], [%1], 16;" :: "r"(s), "l"(g));
}
#define CP_COMMIT() asm volatile("cp.async.commit_group;" ::: "memory")
#define CP_WAIT2() asm volatile("cp.async.wait_group 2;" ::: "memory")
#define CP_WAIT1() asm volatile("cp.async.wait_group 1;" ::: "memory")
#define CP_WAIT0() asm volatile("cp.async.wait_group 0;" ::: "memory")

// ---------------- GEMM tile: 64 rows x 128 cols, 256 threads ----------------
__device__ __forceinline__ void compute_chunk(float (*acc)[4],
                                              const unsigned (*As)[36],
                                              const unsigned (*Bs)[136],
                                              int mq, int nh, int g, int tg) {
    int mr = mq * 16;
    #pragma unroll
    for (int ks = 0; ks < 4; ks++) {
        unsigned a0 = As[mr + g][ks * 8 + tg];
        unsigned a1 = As[mr + g + 8][ks * 8 + tg];
        unsigned a2 = As[mr + g][ks * 8 + tg + 4];
        unsigned a3 = As[mr + g + 8][ks * 8 + tg + 4];
        #pragma unroll
        for (int nt = 0; nt < 8; nt++) {
            unsigned b0 = Bs[ks * 8 + tg][nh * 64 + nt * 8 + g];
            unsigned b1 = Bs[ks * 8 + tg + 4][nh * 64 + nt * 8 + g];
            mma_tf32(acc[nt], a0, a1, a2, a3, b0, b1);
        }
    }
}

// cp.async triple-buffered (depth-2) GEMM mainloop over nK k-chunks of 32.
__device__ __forceinline__ void gemm_mainloop_cp(
    float (*acc)[4], unsigned* smemu,
    const float* Ag, int lda, const float* Wg, int ldw, int nK,
    int t, int mq, int nh, int g, int tg) {
    int ra = t >> 2, c0 = (t & 3) * 8;
    int rb = t >> 3, f0 = t & 7;

    auto stage = [&](int kc) {
        unsigned* base = smemu + (kc % 3) * STAGE_ELEMS;
        unsigned (*As)[36] = (unsigned(*)[36])base;
        unsigned (*Bs)[136] = (unsigned(*)[136])(base + AS_ELEMS);
        const float* ap = Ag + (size_t)ra * lda + kc * 32 + c0;
        cp_async16(smem_u32(&As[ra][c0]), ap);
        cp_async16(smem_u32(&As[ra][c0 + 4]), ap + 4);
        const float* bp = Wg + (size_t)(kc * 32 + rb) * ldw;
        #pragma unroll
        for (int j = 0; j < 4; j++) {
            int c = (f0 + j * 8) * 4;
            cp_async16(smem_u32(&Bs[rb][c]), bp + c);
        }
        CP_COMMIT();
    };

    stage(0);
    if (nK > 1) stage(1);
    for (int kc = 0; kc < nK; kc++) {
        if (kc + 2 < nK) {
            stage(kc + 2);
            CP_WAIT2();
        } else if (kc + 1 < nK) {
            CP_WAIT1();
        } else {
            CP_WAIT0();
        }
        __syncthreads();
        unsigned* base = smemu + (kc % 3) * STAGE_ELEMS;
        compute_chunk(acc, (const unsigned(*)[36])base,
                      (const unsigned(*)[136])(base + AS_ELEMS), mq, nh, g, tg);
        __syncthreads();
    }
}

// ---------------- demo token row ----------------
__global__ __launch_bounds__(128) void demo_kernel(
    const float* __restrict__ demo,
    const float* __restrict__ W_demo, const float* __restrict__ b_demo) {
    int b = blockIdx.x, d = threadIdx.x;
    float acc = b_demo[d];
    #pragma unroll
    for (int k = 0; k < NDEMO; k++) acc += demo[b * NDEMO + k] * W_demo[k * DD + d];
    g_x[(size_t)b * SS * DD + d] = acc;
}

// ---------------- embedding (value tokens) via mma: grid (16 tiles, BB) ----------------
__global__ __launch_bounds__(256) void embed_mma_kernel(
    const float* __restrict__ times, const float* __restrict__ values,
    const float* __restrict__ timescales,
    const float* __restrict__ W_val, const float* __restrict__ b_val,
    const int* __restrict__ length) {
    int tile = blockIdx.x, b = blockIdx.y;
    int row0 = tile * 64;
    if (row0 >= length[b]) return;

    extern __shared__ unsigned smemu[];
    int t = threadIdx.x, w = t >> 5, lane = t & 31;
    int g = lane >> 2, tg = lane & 3, mq = w >> 1, nh = w & 1;

    int ra = t >> 2, c0a = (t & 3) * 8;
    int rb = t >> 3, f0 = t & 7;

    auto stage = [&](int kc, int buf) {
        unsigned* base = smemu + buf * STAGE_ELEMS;
        unsigned (*As)[36] = (unsigned(*)[36])base;
        unsigned (*Bs)[136] = (unsigned(*)[136])(base + AS_ELEMS);
        int tt = row0 + ra;
        int te = (tt > LL - 1) ? (LL - 1) : tt;
        const float* ap = values + ((size_t)b * LL + te) * DVAL + kc * 32 + c0a;
        cp_async16(smem_u32(&As[ra][c0a]), ap);
        cp_async16(smem_u32(&As[ra][c0a + 4]), ap + 4);
        const float* bp = W_val + (size_t)(kc * 32 + rb) * DD;
        #pragma unroll
        for (int j = 0; j < 4; j++) {
            int c = (f0 + j * 8) * 4;
            cp_async16(smem_u32(&Bs[rb][c]), bp + c);
        }
        CP_COMMIT();
    };

    float acc[8][4];
    #pragma unroll
    for (int i = 0; i < 8; i++) acc[i][0] = acc[i][1] = acc[i][2] = acc[i][3] = 0.f;

    stage(0, 0);
    stage(1, 1);
    #pragma unroll
    for (int kc = 0; kc < 2; kc++) {
        if (kc == 0) CP_WAIT1(); else CP_WAIT0();
        __syncthreads();
        unsigned* base = smemu + kc * STAGE_ELEMS;
        compute_chunk(acc, (const unsigned(*)[36])base,
                      (const unsigned(*)[136])(base + AS_ELEMS), mq, nh, g, tg);
        __syncthreads();
    }

    int t0 = row0 + mq * 16 + g, t1 = t0 + 8;
    float tm0 = (t0 <= LL - 1) ? times[b * LL + t0] : 0.f;
    float tm1 = (t1 <= LL - 1) ? times[b * LL + t1] : 0.f;
    #pragma unroll
    for (int nt = 0; nt < 8; nt++) {
        int col = nh * 64 + nt * 8 + 2 * tg;
        float2 bi = *(const float2*)&b_val[col];
        float ts0 = timescales[col & 63], ts1 = timescales[(col + 1) & 63];
        float a0 = __fdividef(tm0, ts0), a1 = __fdividef(tm0, ts1);
        float b0 = __fdividef(tm1, ts0), b1 = __fdividef(tm1, ts1);
        float pe00 = (col < 64) ? __sinf(a0) : __cosf(a0);
        float pe01 = (col + 1 < 64) ? __sinf(a1) : __cosf(a1);
        float pe10 = (col < 64) ? __sinf(b0) : __cosf(b0);
        float pe11 = (col + 1 < 64) ? __sinf(b1) : __cosf(b1);
        if (t0 <= LL - 1) {
            float2 lo = {acc[nt][0] + bi.x + pe00, acc[nt][1] + bi.y + pe01};
            *(float2*)&g_x[((size_t)b * SS + t0 + 1) * DD + col] = lo;
        }
        if (t1 <= LL - 1) {
            float2 hi = {acc[nt][2] + bi.x + pe10, acc[nt][3] + bi.y + pe11};
            *(float2*)&g_x[((size_t)b * SS + t1 + 1) * DD + col] = hi;
        }
    }
}

// ---------------- QKV: grid (tiles, 3); outputs head-major [b][h][s][16] ----------------
__global__ __launch_bounds__(256) void qkv_mma_kernel(
    const int* __restrict__ length,
    const float* __restrict__ Wq, const float* __restrict__ bq,
    const float* __restrict__ Wk, const float* __restrict__ bk,
    const float* __restrict__ Wv, const float* __restrict__ bv) {
    int row0 = blockIdx.x * 64;
    int b = row0 >> 10;
    int valid_len = length[b] + 1;
    int s0base = row0 & (SS - 1);
    if (s0base >= valid_len) return;
    int wi = blockIdx.y;
    const float* W = (wi == 0) ? Wq : (wi == 1) ? Wk : Wv;
    const float* bias = (wi == 0) ? bq : (wi == 1) ? bk : bv;
    float* out = (wi == 0) ? g_q : (wi == 1) ? g_k : g_v;

    extern __shared__ unsigned smemu[];
    int t = threadIdx.x, w = t >> 5, lane = t & 31;
    int g = lane >> 2, tg = lane & 3, mq = w >> 1, nh = w & 1;

    float acc[8][4];
    #pragma unroll
    for (int i = 0; i < 8; i++) acc[i][0] = acc[i][1] = acc[i][2] = acc[i][3] = 0.f;

    gemm_mainloop_cp(acc, smemu, g_x + (size_t)row0 * DD, DD, W, DD, 4,
                     t, mq, nh, g, tg);

    int s0 = s0base + mq * 16 + g, s1 = s0 + 8;
    #pragma unroll
    for (int nt = 0; nt < 8; nt++) {
        int col = nh * 64 + nt * 8 + 2 * tg;
        int hcol = col >> 4, d = col & 15;
        float2 bi = *(const float2*)&bias[col];
        float2 lo = {acc[nt][0] + bi.x, acc[nt][1] + bi.y};
        float2 hi = {acc[nt][2] + bi.x, acc[nt][3] + bi.y};
        size_t base = ((size_t)b * HH + hcol) * SS;
        *(float2*)&out[(base + s0) * DH + d] = lo;
        *(float2*)&out[(base + s1) * DH + d] = hi;
    }
}

// ---------------- flash attention: 128 q/block, warp = m32, head-major K/V ----------------
__global__ __launch_bounds__(128) void attn_mma_kernel(const int* __restrict__ length) {
    const int qt = blockIdx.x, h = blockIdx.y, b = blockIdx.z;
    int valid_len = length[b] + 1;
    int q0 = qt * 128;
    if (q0 >= valid_len) return;

    extern __shared__ unsigned smemu[];
    unsigned (*Ks)[64][20] = (unsigned(*)[64][20])(smemu + ATTN_KS_OFF);
    unsigned (*Vs)[64][24] = (unsigned(*)[64][24])(smemu + ATTN_VS_OFF);
    unsigned (*Ps)[68] = (unsigned(*)[68])(smemu + ATTN_PS_OFF);

    int t = threadIdx.x;
    int w = t >> 5, lane = t & 31;
    int g = lane >> 2, tg = lane & 3;
    size_t hb = ((size_t)b * HH + h) * SS;   // head-major row base
    int orow_base = b * SS + q0 + w * 32;    // token-major output base

    int key_st = t >> 1, d8 = (t & 1) << 3;
    auto stage = [&](int c, int buf) {
        size_t src = (hb + c * 64 + key_st) * DH + d8;
        const float* kp = g_k + src;
        cp_async16(smem_u32(&Ks[buf][key_st][d8]), kp);
        cp_async16(smem_u32(&Ks[buf][key_st][d8 + 4]), kp + 4);
        const float* vp = g_v + src;
        cp_async16(smem_u32(&Vs[buf][key_st][d8]), vp);
        cp_async16(smem_u32(&Vs[buf][key_st][d8 + 4]), vp + 4);
        CP_COMMIT();
    };

    const float qscale = 0.25f * 1.44269504f;
    unsigned qa[2][2][4];
    #pragma unroll
    for (int mt = 0; mt < 2; mt++)
        #pragma unroll
        for (int ks = 0; ks < 2; ks++) {
            size_t a_lo = (hb + q0 + w * 32 + mt * 16 + g) * DH + ks * 8 + tg;
            size_t a_hi = a_lo + 8 * DH;
            qa[mt][ks][0] = f2tf(g_q[a_lo] * qscale);
            qa[mt][ks][1] = f2tf(g_q[a_hi] * qscale);
            qa[mt][ks][2] = f2tf(g_q[a_lo + 4] * qscale);
            qa[mt][ks][3] = f2tf(g_q[a_hi + 4] * qscale);
        }

    float l[2][2] = {{0.f, 0.f}, {0.f, 0.f}};
    float oc[2][2][4];
    #pragma unroll
    for (int mt = 0; mt < 2; mt++)
        #pragma unroll
        for (int dt = 0; dt < 2; dt++)
            oc[mt][dt][0] = oc[mt][dt][1] = oc[mt][dt][2] = oc[mt][dt][3] = 0.f;

    int nch = (valid_len + 63) >> 6;
    stage(0, 0);

    for (int c = 0; c < nch; c++) {
        int bi = c & 1;
        if (c + 1 < nch) {
            stage(c + 1, bi ^ 1);
            CP_WAIT1();
        } else {
            CP_WAIT0();
        }
        __syncthreads();

        int limit = valid_len - c * 64;
        #pragma unroll
        for (int nt = 0; nt < 8; nt++) {
            unsigned kb0[2], kb1[2];
            #pragma unroll
            for (int ks = 0; ks < 2; ks++) {
                kb0[ks] = Ks[bi][nt * 8 + g][ks * 8 + tg];
                kb1[ks] = Ks[bi][nt * 8 + g][ks * 8 + tg + 4];
            }
            int col0 = nt * 8 + 2 * tg, col1 = col0 + 1;
            bool m0 = col0 < limit, m1 = col1 < limit;
            #pragma unroll
            for (int mt = 0; mt < 2; mt++) {
                float sc[4] = {0.f, 0.f, 0.f, 0.f};
                #pragma unroll
                for (int ks = 0; ks < 2; ks++)
                    mma_tf32(sc, qa[mt][ks][0], qa[mt][ks][1], qa[mt][ks][2],
                             qa[mt][ks][3], kb0[ks], kb1[ks]);
                float p0 = ex2f(m0 ? sc[0] : -1e30f);
                float p1 = ex2f(m1 ? sc[1] : -1e30f);
                float p2 = ex2f(m0 ? sc[2] : -1e30f);
                float p3 = ex2f(m1 ? sc[3] : -1e30f);
                l[mt][0] += p0 + p1;
                l[mt][1] += p2 + p3;
                int prow = w * 32 + mt * 16 + g;
                uint2 lo = {__float_as_uint(p0), __float_as_uint(p1)};
                uint2 hi = {__float_as_uint(p2), __float_as_uint(p3)};
                *(uint2*)&Ps[prow][col0] = lo;
                *(uint2*)&Ps[prow + 8][col0] = hi;
            }
        }
        __syncwarp();

        #pragma unroll
        for (int j = 0; j < 8; j++) {
            unsigned vb0[2], vb1[2];
            #pragma unroll
            for (int dt = 0; dt < 2; dt++) {
                vb0[dt] = Vs[bi][j * 8 + tg][dt * 8 + g];
                vb1[dt] = Vs[bi][j * 8 + tg + 4][dt * 8 + g];
            }
            #pragma unroll
            for (int mt = 0; mt < 2; mt++) {
                int prow = w * 32 + mt * 16 + g;
                unsigned pa0 = Ps[prow][j * 8 + tg];
                unsigned pa1 = Ps[prow + 8][j * 8 + tg];
                unsigned pa2 = Ps[prow][j * 8 + tg + 4];
                unsigned pa3 = Ps[prow + 8][j * 8 + tg + 4];
                #pragma unroll
                for (int dt = 0; dt < 2; dt++)
                    mma_tf32(oc[mt][dt], pa0, pa1, pa2, pa3, vb0[dt], vb1[dt]);
            }
        }
        __syncthreads();
    }

    #pragma unroll
    for (int mt = 0; mt < 2; mt++) {
        l[mt][0] += __shfl_xor_sync(0xffffffff, l[mt][0], 1);
        l[mt][0] += __shfl_xor_sync(0xffffffff, l[mt][0], 2);
        l[mt][1] += __shfl_xor_sync(0xffffffff, l[mt][1], 1);
        l[mt][1] += __shfl_xor_sync(0xffffffff, l[mt][1], 2);
        float inv0 = 1.f / l[mt][0], inv1 = 1.f / l[mt][1];
        #pragma unroll
        for (int dt = 0; dt < 2; dt++) {
            int col = h * DH + dt * 8 + 2 * tg;
            int r = orow_base + mt * 16 + g;
            float2 lo = {oc[mt][dt][0] * inv0, oc[mt][dt][1] * inv0};
            float2 hi = {oc[mt][dt][2] * inv1, oc[mt][dt][3] * inv1};
            *(float2*)&g_o[(size_t)r * DD + col] = lo;
            *(float2*)&g_o[(size_t)(r + 8) * DD + col] = hi;
        }
    }
}

// ---------------- O-proj + residual + LN1 ----------------
__global__ __launch_bounds__(256) void oproj_ln_mma_kernel(
    const int* __restrict__ length,
    const float* __restrict__ Wo, const float* __restrict__ bo,
    const float* __restrict__ g1, const float* __restrict__ be1) {
    int row0 = blockIdx.x * 64;
    int b = row0 >> 10;
    int valid_len = length[b] + 1;
    if ((row0 & (SS - 1)) >= valid_len) return;

    extern __shared__ unsigned smemu[];
    __shared__ float redS[2][64];
    __shared__ float redQ[2][64];
    int t = threadIdx.x, w = t >> 5, lane = t & 31;
    int g = lane >> 2, tg = lane & 3, mq = w >> 1, nh = w & 1;

    float acc[8][4];
    #pragma unroll
    for (int i = 0; i < 8; i++) acc[i][0] = acc[i][1] = acc[i][2] = acc[i][3] = 0.f;

    gemm_mainloop_cp(acc, smemu, g_o + (size_t)row0 * DD, DD, Wo, DD, 4,
                     t, mq, nh, g, tg);

    int r0 = row0 + mq * 16 + g, r1 = r0 + 8;
    float rs0 = 0.f, rq0 = 0.f, rs1 = 0.f, rq1 = 0.f;
    #pragma unroll
    for (int nt = 0; nt < 8; nt++) {
        int col = nh * 64 + nt * 8 + 2 * tg;
        float2 bi = *(const float2*)&bo[col];
        float2 e0 = *(const float2*)&g_x[(size_t)r0 * DD + col];
        float2 e1 = *(const float2*)&g_x[(size_t)r1 * DD + col];
        acc[nt][0] += bi.x + e0.x;
        acc[nt][1] += bi.y + e0.y;
        acc[nt][2] += bi.x + e1.x;
        acc[nt][3] += bi.y + e1.y;
        rs0 += acc[nt][0] + acc[nt][1];
        rq0 += acc[nt][0] * acc[nt][0] + acc[nt][1] * acc[nt][1];
        rs1 += acc[nt][2] + acc[nt][3];
        rq1 += acc[nt][2] * acc[nt][2] + acc[nt][3] * acc[nt][3];
    }
    rs0 += __shfl_xor_sync(0xffffffff, rs0, 1);
    rs0 += __shfl_xor_sync(0xffffffff, rs0, 2);
    rq0 += __shfl_xor_sync(0xffffffff, rq0, 1);
    rq0 += __shfl_xor_sync(0xffffffff, rq0, 2);
    rs1 += __shfl_xor_sync(0xffffffff, rs1, 1);
    rs1 += __shfl_xor_sync(0xffffffff, rs1, 2);
    rq1 += __shfl_xor_sync(0xffffffff, rq1, 1);
    rq1 += __shfl_xor_sync(0xffffffff, rq1, 2);
    if (tg == 0) {
        redS[nh][mq * 16 + g] = rs0;
        redS[nh][mq * 16 + g + 8] = rs1;
        redQ[nh][mq * 16 + g] = rq0;
        redQ[nh][mq * 16 + g + 8] = rq1;
    }
    __syncthreads();
    float mu0 = (redS[0][mq * 16 + g] + redS[1][mq * 16 + g]) * (1.f / DD);
    float mu1 = (redS[0][mq * 16 + g + 8] + redS[1][mq * 16 + g + 8]) * (1.f / DD);
    float v0 = fmaxf((redQ[0][mq * 16 + g] + redQ[1][mq * 16 + g]) * (1.f / DD) - mu0 * mu0, 0.f);
    float v1 = fmaxf((redQ[0][mq * 16 + g + 8] + redQ[1][mq * 16 + g + 8]) * (1.f / DD) - mu1 * mu1, 0.f);
    float rst0 = rsqrtf(v0 + 1e-3f), rst1 = rsqrtf(v1 + 1e-3f);
    #pragma unroll
    for (int nt = 0; nt < 8; nt++) {
        int col = nh * 64 + nt * 8 + 2 * tg;
        float2 gm = *(const float2*)&g1[col];
        float2 bt = *(const float2*)&be1[col];
        float2 lo = {(acc[nt][0] - mu0) * rst0 * gm.x + bt.x,
                     (acc[nt][1] - mu0) * rst0 * gm.y + bt.y};
        float2 hi = {(acc[nt][2] - mu1) * rst1 * gm.x + bt.x,
                     (acc[nt][3] - mu1) * rst1 * gm.y + bt.y};
        *(float2*)&g_x[(size_t)r0 * DD + col] = lo;
        *(float2*)&g_x[(size_t)r1 * DD + col] = hi;
    }
}

// ---------------- FFN1: grid (tiles, 4) ----------------
__global__ __launch_bounds__(256) void ffn1_mma_kernel(
    const int* __restrict__ length,
    const float* __restrict__ W1, const float* __restrict__ b1) {
    int row0 = blockIdx.x * 64;
    int b = row0 >> 10;
    int valid_len = length[b] + 1;
    if ((row0 & (SS - 1)) >= valid_len) return;
    int ncol0 = blockIdx.y * 128;

    extern __shared__ unsigned smemu[];
    int t = threadIdx.x, w = t >> 5, lane = t & 31;
    int g = lane >> 2, tg = lane & 3, mq = w >> 1, nh = w & 1;

    float acc[8][4];
    #pragma unroll
    for (int i = 0; i < 8; i++) acc[i][0] = acc[i][1] = acc[i][2] = acc[i][3] = 0.f;

    gemm_mainloop_cp(acc, smemu, g_x + (size_t)row0 * DD, DD, W1 + ncol0, DFF, 4,
                     t, mq, nh, g, tg);

    int r0 = row0 + mq * 16 + g, r1 = r0 + 8;
    #pragma unroll
    for (int nt = 0; nt < 8; nt++) {
        int col = ncol0 + nh * 64 + nt * 8 + 2 * tg;
        float2 bi = *(const float2*)&b1[col];
        float2 lo = {fmaxf(acc[nt][0] + bi.x, 0.f), fmaxf(acc[nt][1] + bi.y, 0.f)};
        float2 hi = {fmaxf(acc[nt][2] + bi.x, 0.f), fmaxf(acc[nt][3] + bi.y, 0.f)};
        *(float2*)&g_h[(size_t)r0 * DFF + col] = lo;
        *(float2*)&g_h[(size_t)r1 * DFF + col] = hi;
    }
}

// ---------------- FFN2 + residual + LN2 ----------------
__global__ __launch_bounds__(256) void ffn2_ln_mma_kernel(
    const int* __restrict__ length,
    const float* __restrict__ W2, const float* __restrict__ b2,
    const float* __restrict__ g2, const float* __restrict__ be2) {
    int row0 = blockIdx.x * 64;
    int b = row0 >> 10;
    int valid_len = length[b] + 1;
    if ((row0 & (SS - 1)) >= valid_len) return;

    extern __shared__ unsigned smemu[];
    __shared__ float redS[2][64];
    __shared__ float redQ[2][64];
    int t = threadIdx.x, w = t >> 5, lane = t & 31;
    int g = lane >> 2, tg = lane & 3, mq = w >> 1, nh = w & 1;

    float acc[8][4];
    #pragma unroll
    for (int i = 0; i < 8; i++) acc[i][0] = acc[i][1] = acc[i][2] = acc[i][3] = 0.f;

    gemm_mainloop_cp(acc, smemu, g_h + (size_t)row0 * DFF, DFF, W2, DD, DFF / 32,
                     t, mq, nh, g, tg);

    int r0 = row0 + mq * 16 + g, r1 = r0 + 8;
    float rs0 = 0.f, rq0 = 0.f, rs1 = 0.f, rq1 = 0.f;
    #pragma unroll
    for (int nt = 0; nt < 8; nt++) {
        int col = nh * 64 + nt * 8 + 2 * tg;
        float2 bi = *(const float2*)&b2[col];
        float2 e0 = *(const float2*)&g_x[(size_t)r0 * DD + col];
        float2 e1 = *(const float2*)&g_x[(size_t)r1 * DD + col];
        acc[nt][0] += bi.x + e0.x;
        acc[nt][1] += bi.y + e0.y;
        acc[nt][2] += bi.x + e1.x;
        acc[nt][3] += bi.y + e1.y;
        rs0 += acc[nt][0] + acc[nt][1];
        rq0 += acc[nt][0] * acc[nt][0] + acc[nt][1] * acc[nt][1];
        rs1 += acc[nt][2] + acc[nt][3];
        rq1 += acc[nt][2] * acc[nt][2] + acc[nt][3] * acc[nt][3];
    }
    rs0 += __shfl_xor_sync(0xffffffff, rs0, 1);
    rs0 += __shfl_xor_sync(0xffffffff, rs0, 2);
    rq0 += __shfl_xor_sync(0xffffffff, rq0, 1);
    rq0 += __shfl_xor_sync(0xffffffff, rq0, 2);
    rs1 += __shfl_xor_sync(0xffffffff, rs1, 1);
    rs1 += __shfl_xor_sync(0xffffffff, rs1, 2);
    rq1 += __shfl_xor_sync(0xffffffff, rq1, 1);
    rq1 += __shfl_xor_sync(0xffffffff, rq1, 2);
    if (tg == 0) {
        redS[nh][mq * 16 + g] = rs0;
        redS[nh][mq * 16 + g + 8] = rs1;
        redQ[nh][mq * 16 + g] = rq0;
        redQ[nh][mq * 16 + g + 8] = rq1;
    }
    __syncthreads();
    float mu0 = (redS[0][mq * 16 + g] + redS[1][mq * 16 + g]) * (1.f / DD);
    float mu1 = (redS[0][mq * 16 + g + 8] + redS[1][mq * 16 + g + 8]) * (1.f / DD);
    float v0 = fmaxf((redQ[0][mq * 16 + g] + redQ[1][mq * 16 + g]) * (1.f / DD) - mu0 * mu0, 0.f);
    float v1 = fmaxf((redQ[0][mq * 16 + g + 8] + redQ[1][mq * 16 + g + 8]) * (1.f / DD) - mu1 * mu1, 0.f);
    float rst0 = rsqrtf(v0 + 1e-3f), rst1 = rsqrtf(v1 + 1e-3f);
    #pragma unroll
    for (int nt = 0; nt < 8; nt++) {
        int col = nh * 64 + nt * 8 + 2 * tg;
        float2 gm = *(const float2*)&g2[col];
        float2 bt = *(const float2*)&be2[col];
        float2 lo = {(acc[nt][0] - mu0) * rst0 * gm.x + bt.x,
                     (acc[nt][1] - mu0) * rst0 * gm.y + bt.y};
        float2 hi = {(acc[nt][2] - mu1) * rst1 * gm.x + bt.x,
                     (acc[nt][3] - mu1) * rst1 * gm.y + bt.y};
        *(float2*)&g_x[(size_t)r0 * DD + col] = lo;
        *(float2*)&g_x[(size_t)r1 * DD + col] = hi;
    }
}

// ---------------- masked mean-pool + MLP head + sigmoid ----------------
__global__ __launch_bounds__(256) void head_kernel(
    const int* __restrict__ length,
    const float* __restrict__ Wm1, const float* __restrict__ bm1,
    const float* __restrict__ Wm2, const float* __restrict__ bm2,
    float* __restrict__ out) {
    int b = blockIdx.x;
    int t = threadIdx.x;
    __shared__ float part[2][DD];
    __shared__ float agg[DD];
    __shared__ float hh[MLPH];
    __shared__ float red[8];
    int cnt = length[b] + 1;
    int d = t & 127, grp = t >> 7;
    float s0 = 0.f, s1 = 0.f, s2 = 0.f, s3 = 0.f;
    int ss = grp;
    for (; ss + 6 < cnt; ss += 8) {
        s0 += g_x[(b * SS + ss) * DD + d];
        s1 += g_x[(b * SS + ss + 2) * DD + d];
        s2 += g_x[(b * SS + ss + 4) * DD + d];
        s3 += g_x[(b * SS + ss + 6) * DD + d];
    }
    for (; ss < cnt; ss += 2) s0 += g_x[(b * SS + ss) * DD + d];
    part[grp][d] = s0 + s1 + s2 + s3;
    __syncthreads();
    if (t < DD) agg[t] = (part[0][t] + part[1][t]) / (float)cnt;
    __syncthreads();
    {
        float acc = bm1[t];
        #pragma unroll 8
        for (int k = 0; k < DD; k++) acc += agg[k] * Wm1[k * MLPH + t];
        hh[t] = fmaxf(acc, 0.f);
    }
    __syncthreads();
    float v = hh[t] * Wm2[t];
    #pragma unroll
    for (int o = 16; o > 0; o >>= 1) v += __shfl_xor_sync(0xffffffff, v, o);
    if ((t & 31) == 0) red[t >> 5] = v;
    __syncthreads();
    if (t == 0) {
        float s = 0.f;
        #pragma unroll
        for (int i = 0; i < 8; i++) s += red[i];
        s += bm2[0];
        out[b] = 1.f / (1.f + __expf(-s));
    }
}

// ---------------- launch ----------------
extern "C" void kernel_launch(void* const* d_in, const int* in_sizes, int n_in,
                              void* d_out, int out_size) {
    (void)in_sizes; (void)n_in; (void)out_size;
    const float* demo       = (const float*)d_in[0];
    const float* times      = (const float*)d_in[1];
    const float* values     = (const float*)d_in[2];
    const int*   length     = (const int*)d_in[3];
    const float* timescales = (const float*)d_in[4];
    const float* W_demo = (const float*)d_in[5];
    const float* b_demo = (const float*)d_in[6];
    const float* W_val  = (const float*)d_in[7];
    const float* b_val  = (const float*)d_in[8];
    const float* Wq = (const float*)d_in[9];
    const float* bq = (const float*)d_in[10];
    const float* Wk = (const float*)d_in[11];
    const float* bk = (const float*)d_in[12];
    const float* Wv = (const float*)d_in[13];
    const float* bv = (const float*)d_in[14];
    const float* Wo = (const float*)d_in[15];
    const float* bo = (const float*)d_in[16];
    const float* ln1g = (const float*)d_in[17];
    const float* ln1b = (const float*)d_in[18];
    const float* W1 = (const float*)d_in[19];
    const float* b1 = (const float*)d_in[20];
    const float* W2 = (const float*)d_in[21];
    const float* b2 = (const float*)d_in[22];
    const float* ln2g = (const float*)d_in[23];
    const float* ln2b = (const float*)d_in[24];
    const float* Wm1 = (const float*)d_in[25];
    const float* bm1 = (const float*)d_in[26];
    const float* Wm2 = (const float*)d_in[27];
    const float* bm2 = (const float*)d_in[28];
    float* out = (float*)d_out;

    cudaFuncSetAttribute(embed_mma_kernel, cudaFuncAttributeMaxDynamicSharedMemorySize, EMBED_SMEM_BYTES);
    cudaFuncSetAttribute(qkv_mma_kernel, cudaFuncAttributeMaxDynamicSharedMemorySize, GEMM_SMEM_BYTES);
    cudaFuncSetAttribute(oproj_ln_mma_kernel, cudaFuncAttributeMaxDynamicSharedMemorySize, GEMM_SMEM_BYTES);
    cudaFuncSetAttribute(ffn1_mma_kernel, cudaFuncAttributeMaxDynamicSharedMemorySize, GEMM_SMEM_BYTES);
    cudaFuncSetAttribute(ffn2_ln_mma_kernel, cudaFuncAttributeMaxDynamicSharedMemorySize, GEMM_SMEM_BYTES);
    cudaFuncSetAttribute(attn_mma_kernel, cudaFuncAttributeMaxDynamicSharedMemorySize, ATTN_SMEM_BYTES);

    demo_kernel<<<BB, 128>>>(demo, W_demo, b_demo);
    dim3 ge(16, BB);
    embed_mma_kernel<<<ge, 256, EMBED_SMEM_BYTES>>>(times, values, timescales, W_val, b_val, length);

    int ntiles = BB * SS / 64;
    for (int l = 0; l < NLAY; l++) {
        dim3 gq(ntiles, 3);
        qkv_mma_kernel<<<gq, 256, GEMM_SMEM_BYTES>>>(length,
            Wq + l * DD * DD, bq + l * DD,
            Wk + l * DD * DD, bk + l * DD,
            Wv + l * DD * DD, bv + l * DD);
        dim3 ag(SS / 128, HH, BB);
        attn_mma_kernel<<<ag, 128, ATTN_SMEM_BYTES>>>(length);
        oproj_ln_mma_kernel<<<ntiles, 256, GEMM_SMEM_BYTES>>>(length,
            Wo + l * DD * DD, bo + l * DD, ln1g + l * DD, ln1b + l * DD);
        dim3 gf(ntiles, 4);
        ffn1_mma_kernel<<<gf, 256, GEMM_SMEM_BYTES>>>(length, W1 + l * DD * DFF, b1 + l * DFF);
        ffn2_ln_mma_kernel<<<ntiles, 256, GEMM_SMEM_BYTES>>>(length,
            W2 + l * DFF * DD, b2 + l * DD, ln2g + l * DD, ln2b + l * DD);
    }

    head_kernel<<<BB, 256>>>(length, Wm1, bm1, Wm2, bm2, out);
}

// round 15
// speedup vs baseline: 1.3712x; 1.1875x over previous
#include <cuda_runtime.h>
#include <cuda_fp16.h>
#include <math.h>

#define BB 16
#define LL 1023
#define SS 1024
#define DD 128
#define DVAL 64
#define NDEMO 16
#define HH 8
#define DH 16
#define NLAY 2
#define DFF 512
#define MLPH 256

#define AS_ELEMS (64 * 36)
#define BS_ELEMS (32 * 136)
#define STAGE_ELEMS (AS_ELEMS + BS_ELEMS)
#define GEMM_SMEM_BYTES (3 * STAGE_ELEMS * 4)
#define EMBED_SMEM_BYTES (2 * STAGE_ELEMS * 4)

// ---------------- device scratch (no allocs allowed) ----------------
__device__ float g_x[BB * SS * DD];
__device__ float g_q[BB * SS * DD];    // head-major: [b][h][s][DH]
__device__ float g_k[BB * SS * DD];    // head-major
__device__ __half g_v[BB * SS * DD];   // head-major transposed: [b][h][d][s], fp16
__device__ float g_o[BB * SS * DD];    // token-major
__device__ float g_h[BB * SS * DFF];

__device__ __forceinline__ unsigned f2tf(float x) {
    unsigned r;
    asm("cvt.rna.tf32.f32 %0, %1;" : "=r"(r) : "f"(x));
    return r;
}

__device__ __forceinline__ float ex2f(float x) {
    float r;
    asm("ex2.approx.ftz.f32 %0, %1;" : "=f"(r) : "f"(x));
    return r;
}

__device__ __forceinline__ void mma_tf32(float* c, unsigned a0, unsigned a1,
                                         unsigned a2, unsigned a3,
                                         unsigned b0, unsigned b1) {
    asm("mma.sync.aligned.m16n8k8.row.col.f32.tf32.tf32.f32 "
        "{%0,%1,%2,%3},{%4,%5,%6,%7},{%8,%9},{%0,%1,%2,%3};"
        : "+f"(c[0]), "+f"(c[1]), "+f"(c[2]), "+f"(c[3])
        : "r"(a0), "r"(a1), "r"(a2), "r"(a3), "r"(b0), "r"(b1));
}

__device__ __forceinline__ void mma_f16(float* c, unsigned a0, unsigned a1,
                                        unsigned a2, unsigned a3,
                                        unsigned b0, unsigned b1) {
    asm("mma.sync.aligned.m16n8k16.row.col.f32.f16.f16.f32 "
        "{%0,%1,%2,%3},{%4,%5,%6,%7},{%8,%9},{%0,%1,%2,%3};"
        : "+f"(c[0]), "+f"(c[1]), "+f"(c[2]), "+f"(c[3])
        : "r"(a0), "r"(a1), "r"(a2), "r"(a3), "r"(b0), "r"(b1));
}

__device__ __forceinline__ unsigned smem_u32(const void* p) {
    return (unsigned)__cvta_generic_to_shared(p);
}

__device__ __forceinline__ void cp_async16(unsigned s, const void* g) {
    asm volatile("cp.async.ca.shared.global [%0], [%1], 16;" :: "r"(s), "l"(g));
}
#define CP_COMMIT() asm volatile("cp.async.commit_group;" ::: "memory")
#define CP_WAIT2() asm volatile("cp.async.wait_group 2;" ::: "memory")
#define CP_WAIT1() asm volatile("cp.async.wait_group 1;" ::: "memory")
#define CP_WAIT0() asm volatile("cp.async.wait_group 0;" ::: "memory")

// ---------------- GEMM tile: 64 rows x 128 cols, 256 threads ----------------
__device__ __forceinline__ void compute_chunk(float (*acc)[4],
                                              const unsigned (*As)[36],
                                              const unsigned (*Bs)[136],
                                              int mq, int nh, int g, int tg) {
    int mr = mq * 16;
    #pragma unroll
    for (int ks = 0; ks < 4; ks++) {
        unsigned a0 = As[mr + g][ks * 8 + tg];
        unsigned a1 = As[mr + g + 8][ks * 8 + tg];
        unsigned a2 = As[mr + g][ks * 8 + tg + 4];
        unsigned a3 = As[mr + g + 8][ks * 8 + tg + 4];
        #pragma unroll
        for (int nt = 0; nt < 8; nt++) {
            unsigned b0 = Bs[ks * 8 + tg][nh * 64 + nt * 8 + g];
            unsigned b1 = Bs[ks * 8 + tg + 4][nh * 64 + nt * 8 + g];
            mma_tf32(acc[nt], a0, a1, a2, a3, b0, b1);
        }
    }
}

// cp.async triple-buffered (depth-2) GEMM mainloop over nK k-chunks of 32.
__device__ __forceinline__ void gemm_mainloop_cp(
    float (*acc)[4], unsigned* smemu,
    const float* Ag, int lda, const float* Wg, int ldw, int nK,
    int t, int mq, int nh, int g, int tg) {
    int ra = t >> 2, c0 = (t & 3) * 8;
    int rb = t >> 3, f0 = t & 7;

    auto stage = [&](int kc) {
        unsigned* base = smemu + (kc % 3) * STAGE_ELEMS;
        unsigned (*As)[36] = (unsigned(*)[36])base;
        unsigned (*Bs)[136] = (unsigned(*)[136])(base + AS_ELEMS);
        const float* ap = Ag + (size_t)ra * lda + kc * 32 + c0;
        cp_async16(smem_u32(&As[ra][c0]), ap);
        cp_async16(smem_u32(&As[ra][c0 + 4]), ap + 4);
        const float* bp = Wg + (size_t)(kc * 32 + rb) * ldw;
        #pragma unroll
        for (int j = 0; j < 4; j++) {
            int c = (f0 + j * 8) * 4;
            cp_async16(smem_u32(&Bs[rb][c]), bp + c);
        }
        CP_COMMIT();
    };

    stage(0);
    if (nK > 1) stage(1);
    for (int kc = 0; kc < nK; kc++) {
        if (kc + 2 < nK) {
            stage(kc + 2);
            CP_WAIT2();
        } else if (kc + 1 < nK) {
            CP_WAIT1();
        } else {
            CP_WAIT0();
        }
        __syncthreads();
        unsigned* base = smemu + (kc % 3) * STAGE_ELEMS;
        compute_chunk(acc, (const unsigned(*)[36])base,
                      (const unsigned(*)[136])(base + AS_ELEMS), mq, nh, g, tg);
        __syncthreads();
    }
}

// ---------------- demo token row ----------------
__global__ __launch_bounds__(128) void demo_kernel(
    const float* __restrict__ demo,
    const float* __restrict__ W_demo, const float* __restrict__ b_demo) {
    int b = blockIdx.x, d = threadIdx.x;
    float acc = b_demo[d];
    #pragma unroll
    for (int k = 0; k < NDEMO; k++) acc += demo[b * NDEMO + k] * W_demo[k * DD + d];
    g_x[(size_t)b * SS * DD + d] = acc;
}

// ---------------- embedding (value tokens) via mma: grid (16 tiles, BB) ----------------
__global__ __launch_bounds__(256) void embed_mma_kernel(
    const float* __restrict__ times, const float* __restrict__ values,
    const float* __restrict__ timescales,
    const float* __restrict__ W_val, const float* __restrict__ b_val,
    const int* __restrict__ length) {
    int tile = blockIdx.x, b = blockIdx.y;
    int row0 = tile * 64;
    if (row0 >= length[b]) return;

    extern __shared__ unsigned smemu[];
    int t = threadIdx.x, w = t >> 5, lane = t & 31;
    int g = lane >> 2, tg = lane & 3, mq = w >> 1, nh = w & 1;

    int ra = t >> 2, c0a = (t & 3) * 8;
    int rb = t >> 3, f0 = t & 7;

    auto stage = [&](int kc, int buf) {
        unsigned* base = smemu + buf * STAGE_ELEMS;
        unsigned (*As)[36] = (unsigned(*)[36])base;
        unsigned (*Bs)[136] = (unsigned(*)[136])(base + AS_ELEMS);
        int tt = row0 + ra;
        int te = (tt > LL - 1) ? (LL - 1) : tt;
        const float* ap = values + ((size_t)b * LL + te) * DVAL + kc * 32 + c0a;
        cp_async16(smem_u32(&As[ra][c0a]), ap);
        cp_async16(smem_u32(&As[ra][c0a + 4]), ap + 4);
        const float* bp = W_val + (size_t)(kc * 32 + rb) * DD;
        #pragma unroll
        for (int j = 0; j < 4; j++) {
            int c = (f0 + j * 8) * 4;
            cp_async16(smem_u32(&Bs[rb][c]), bp + c);
        }
        CP_COMMIT();
    };

    float acc[8][4];
    #pragma unroll
    for (int i = 0; i < 8; i++) acc[i][0] = acc[i][1] = acc[i][2] = acc[i][3] = 0.f;

    stage(0, 0);
    stage(1, 1);
    #pragma unroll
    for (int kc = 0; kc < 2; kc++) {
        if (kc == 0) CP_WAIT1(); else CP_WAIT0();
        __syncthreads();
        unsigned* base = smemu + kc * STAGE_ELEMS;
        compute_chunk(acc, (const unsigned(*)[36])base,
                      (const unsigned(*)[136])(base + AS_ELEMS), mq, nh, g, tg);
        __syncthreads();
    }

    int t0 = row0 + mq * 16 + g, t1 = t0 + 8;
    float tm0 = (t0 <= LL - 1) ? times[b * LL + t0] : 0.f;
    float tm1 = (t1 <= LL - 1) ? times[b * LL + t1] : 0.f;
    #pragma unroll
    for (int nt = 0; nt < 8; nt++) {
        int col = nh * 64 + nt * 8 + 2 * tg;
        float2 bi = *(const float2*)&b_val[col];
        float ts0 = timescales[col & 63], ts1 = timescales[(col + 1) & 63];
        float a0 = __fdividef(tm0, ts0), a1 = __fdividef(tm0, ts1);
        float b0 = __fdividef(tm1, ts0), b1 = __fdividef(tm1, ts1);
        float pe00 = (col < 64) ? __sinf(a0) : __cosf(a0);
        float pe01 = (col + 1 < 64) ? __sinf(a1) : __cosf(a1);
        float pe10 = (col < 64) ? __sinf(b0) : __cosf(b0);
        float pe11 = (col + 1 < 64) ? __sinf(b1) : __cosf(b1);
        if (t0 <= LL - 1) {
            float2 lo = {acc[nt][0] + bi.x + pe00, acc[nt][1] + bi.y + pe01};
            *(float2*)&g_x[((size_t)b * SS + t0 + 1) * DD + col] = lo;
        }
        if (t1 <= LL - 1) {
            float2 hi = {acc[nt][2] + bi.x + pe10, acc[nt][3] + bi.y + pe11};
            *(float2*)&g_x[((size_t)b * SS + t1 + 1) * DD + col] = hi;
        }
    }
}

// ---------------- QKV: grid (tiles, 3); Q/K head-major fp32, V transposed fp16 ----------------
__global__ __launch_bounds__(256) void qkv_mma_kernel(
    const int* __restrict__ length,
    const float* __restrict__ Wq, const float* __restrict__ bq,
    const float* __restrict__ Wk, const float* __restrict__ bk,
    const float* __restrict__ Wv, const float* __restrict__ bv) {
    int row0 = blockIdx.x * 64;
    int b = row0 >> 10;
    int valid_len = length[b] + 1;
    int s0base = row0 & (SS - 1);
    if (s0base >= valid_len) return;
    int wi = blockIdx.y;
    const float* W = (wi == 0) ? Wq : (wi == 1) ? Wk : Wv;
    const float* bias = (wi == 0) ? bq : (wi == 1) ? bk : bv;

    extern __shared__ unsigned smemu[];
    int t = threadIdx.x, w = t >> 5, lane = t & 31;
    int g = lane >> 2, tg = lane & 3, mq = w >> 1, nh = w & 1;

    float acc[8][4];
    #pragma unroll
    for (int i = 0; i < 8; i++) acc[i][0] = acc[i][1] = acc[i][2] = acc[i][3] = 0.f;

    gemm_mainloop_cp(acc, smemu, g_x + (size_t)row0 * DD, DD, W, DD, 4,
                     t, mq, nh, g, tg);

    int s0 = s0base + mq * 16 + g, s1 = s0 + 8;
    if (wi == 2) {
        // V: transposed fp16 [b][h][d][s]
        #pragma unroll
        for (int nt = 0; nt < 8; nt++) {
            int col = nh * 64 + nt * 8 + 2 * tg;
            int hcol = col >> 4, d = col & 15;
            float2 bi = *(const float2*)&bias[col];
            size_t base = ((size_t)b * HH + hcol) * DH;
            g_v[(base + d) * SS + s0] = __float2half_rn(acc[nt][0] + bi.x);
            g_v[(base + d + 1) * SS + s0] = __float2half_rn(acc[nt][1] + bi.y);
            g_v[(base + d) * SS + s1] = __float2half_rn(acc[nt][2] + bi.x);
            g_v[(base + d + 1) * SS + s1] = __float2half_rn(acc[nt][3] + bi.y);
        }
    } else {
        float* out = (wi == 0) ? g_q : g_k;
        #pragma unroll
        for (int nt = 0; nt < 8; nt++) {
            int col = nh * 64 + nt * 8 + 2 * tg;
            int hcol = col >> 4, d = col & 15;
            float2 bi = *(const float2*)&bias[col];
            float2 lo = {acc[nt][0] + bi.x, acc[nt][1] + bi.y};
            float2 hi = {acc[nt][2] + bi.x, acc[nt][3] + bi.y};
            size_t base = ((size_t)b * HH + hcol) * SS;
            *(float2*)&out[(base + s0) * DH + d] = lo;
            *(float2*)&out[(base + s1) * DH + d] = hi;
        }
    }
}

// ---------------- flash attention: P in registers (fp16 PV), no Ps smem ----------------
__global__ __launch_bounds__(128) void attn_mma_kernel(const int* __restrict__ length) {
    const int qt = blockIdx.x, h = blockIdx.y, b = blockIdx.z;
    int valid_len = length[b] + 1;
    int q0 = qt * 128;
    if (q0 >= valid_len) return;

    __shared__ unsigned Ks[2][64][20];   // fp32 bits, [key][d]
    __shared__ __half Vs[2][16][72];     // fp16, [d][key]

    int t = threadIdx.x;
    int w = t >> 5, lane = t & 31;
    int g = lane >> 2, tg = lane & 3;
    size_t hb = ((size_t)b * HH + h) * SS;       // Q/K row base
    size_t hbd = ((size_t)b * HH + h) * DH;      // V row base (transposed)
    int orow_base = b * SS + q0 + w * 32;

    int key_st = t >> 1, d8 = (t & 1) << 3;
    int vrow = t >> 3, vseg = (t & 7) * 8;
    auto stage = [&](int c, int buf) {
        size_t ksrc = (hb + c * 64 + key_st) * DH + d8;
        const float* kp = g_k + ksrc;
        cp_async16(smem_u32(&Ks[buf][key_st][d8]), kp);
        cp_async16(smem_u32(&Ks[buf][key_st][d8 + 4]), kp + 4);
        const __half* vp = g_v + (hbd + vrow) * SS + c * 64 + vseg;
        cp_async16(smem_u32(&Vs[buf][vrow][vseg]), vp);
        CP_COMMIT();
    };

    const float qscale = 0.25f * 1.44269504f;
    unsigned qa[2][2][4];
    #pragma unroll
    for (int mt = 0; mt < 2; mt++)
        #pragma unroll
        for (int ks = 0; ks < 2; ks++) {
            size_t a_lo = (hb + q0 + w * 32 + mt * 16 + g) * DH + ks * 8 + tg;
            size_t a_hi = a_lo + 8 * DH;
            qa[mt][ks][0] = f2tf(g_q[a_lo] * qscale);
            qa[mt][ks][1] = f2tf(g_q[a_hi] * qscale);
            qa[mt][ks][2] = f2tf(g_q[a_lo + 4] * qscale);
            qa[mt][ks][3] = f2tf(g_q[a_hi + 4] * qscale);
        }

    float l[2][2] = {{0.f, 0.f}, {0.f, 0.f}};
    float oc[2][2][4];
    #pragma unroll
    for (int mt = 0; mt < 2; mt++)
        #pragma unroll
        for (int dt = 0; dt < 2; dt++)
            oc[mt][dt][0] = oc[mt][dt][1] = oc[mt][dt][2] = oc[mt][dt][3] = 0.f;

    int nch = (valid_len + 63) >> 6;
    stage(0, 0);

    for (int c = 0; c < nch; c++) {
        int bi = c & 1;
        if (c + 1 < nch) {
            stage(c + 1, bi ^ 1);
            CP_WAIT1();
        } else {
            CP_WAIT0();
        }
        __syncthreads();

        int limit = valid_len - c * 64;
        #pragma unroll
        for (int mt = 0; mt < 2; mt++) {
            unsigned ph[8][2];
            #pragma unroll
            for (int nt = 0; nt < 8; nt++) {
                unsigned kb0a = Ks[bi][nt * 8 + g][tg];
                unsigned kb1a = Ks[bi][nt * 8 + g][tg + 4];
                unsigned kb0b = Ks[bi][nt * 8 + g][8 + tg];
                unsigned kb1b = Ks[bi][nt * 8 + g][8 + tg + 4];
                float sc[4] = {0.f, 0.f, 0.f, 0.f};
                mma_tf32(sc, qa[mt][0][0], qa[mt][0][1], qa[mt][0][2], qa[mt][0][3], kb0a, kb1a);
                mma_tf32(sc, qa[mt][1][0], qa[mt][1][1], qa[mt][1][2], qa[mt][1][3], kb0b, kb1b);
                int col0 = nt * 8 + 2 * tg, col1 = col0 + 1;
                float p0 = ex2f((col0 < limit) ? sc[0] : -1e30f);
                float p1 = ex2f((col1 < limit) ? sc[1] : -1e30f);
                float p2 = ex2f((col0 < limit) ? sc[2] : -1e30f);
                float p3 = ex2f((col1 < limit) ? sc[3] : -1e30f);
                l[mt][0] += p0 + p1;
                l[mt][1] += p2 + p3;
                __half2 h0 = __floats2half2_rn(p0, p1);
                __half2 h1 = __floats2half2_rn(p2, p3);
                ph[nt][0] = *(unsigned*)&h0;
                ph[nt][1] = *(unsigned*)&h1;
            }
            // O += P V (fp16 k16, P from registers, V from smem)
            #pragma unroll
            for (int j = 0; j < 4; j++) {
                #pragma unroll
                for (int dt = 0; dt < 2; dt++) {
                    unsigned vb0 = *(const unsigned*)&Vs[bi][dt * 8 + g][j * 16 + 2 * tg];
                    unsigned vb1 = *(const unsigned*)&Vs[bi][dt * 8 + g][j * 16 + 2 * tg + 8];
                    mma_f16(oc[mt][dt], ph[2 * j][0], ph[2 * j][1],
                            ph[2 * j + 1][0], ph[2 * j + 1][1], vb0, vb1);
                }
            }
        }
        __syncthreads();
    }

    #pragma unroll
    for (int mt = 0; mt < 2; mt++) {
        l[mt][0] += __shfl_xor_sync(0xffffffff, l[mt][0], 1);
        l[mt][0] += __shfl_xor_sync(0xffffffff, l[mt][0], 2);
        l[mt][1] += __shfl_xor_sync(0xffffffff, l[mt][1], 1);
        l[mt][1] += __shfl_xor_sync(0xffffffff, l[mt][1], 2);
        float inv0 = 1.f / l[mt][0], inv1 = 1.f / l[mt][1];
        #pragma unroll
        for (int dt = 0; dt < 2; dt++) {
            int col = h * DH + dt * 8 + 2 * tg;
            int r = orow_base + mt * 16 + g;
            float2 lo = {oc[mt][dt][0] * inv0, oc[mt][dt][1] * inv0};
            float2 hi = {oc[mt][dt][2] * inv1, oc[mt][dt][3] * inv1};
            *(float2*)&g_o[(size_t)r * DD + col] = lo;
            *(float2*)&g_o[(size_t)(r + 8) * DD + col] = hi;
        }
    }
}

// ---------------- O-proj + residual + LN1 ----------------
__global__ __launch_bounds__(256) void oproj_ln_mma_kernel(
    const int* __restrict__ length,
    const float* __restrict__ Wo, const float* __restrict__ bo,
    const float* __restrict__ g1, const float* __restrict__ be1) {
    int row0 = blockIdx.x * 64;
    int b = row0 >> 10;
    int valid_len = length[b] + 1;
    if ((row0 & (SS - 1)) >= valid_len) return;

    extern __shared__ unsigned smemu[];
    __shared__ float redS[2][64];
    __shared__ float redQ[2][64];
    int t = threadIdx.x, w = t >> 5, lane = t & 31;
    int g = lane >> 2, tg = lane & 3, mq = w >> 1, nh = w & 1;

    float acc[8][4];
    #pragma unroll
    for (int i = 0; i < 8; i++) acc[i][0] = acc[i][1] = acc[i][2] = acc[i][3] = 0.f;

    gemm_mainloop_cp(acc, smemu, g_o + (size_t)row0 * DD, DD, Wo, DD, 4,
                     t, mq, nh, g, tg);

    int r0 = row0 + mq * 16 + g, r1 = r0 + 8;
    float rs0 = 0.f, rq0 = 0.f, rs1 = 0.f, rq1 = 0.f;
    #pragma unroll
    for (int nt = 0; nt < 8; nt++) {
        int col = nh * 64 + nt * 8 + 2 * tg;
        float2 bi = *(const float2*)&bo[col];
        float2 e0 = *(const float2*)&g_x[(size_t)r0 * DD + col];
        float2 e1 = *(const float2*)&g_x[(size_t)r1 * DD + col];
        acc[nt][0] += bi.x + e0.x;
        acc[nt][1] += bi.y + e0.y;
        acc[nt][2] += bi.x + e1.x;
        acc[nt][3] += bi.y + e1.y;
        rs0 += acc[nt][0] + acc[nt][1];
        rq0 += acc[nt][0] * acc[nt][0] + acc[nt][1] * acc[nt][1];
        rs1 += acc[nt][2] + acc[nt][3];
        rq1 += acc[nt][2] * acc[nt][2] + acc[nt][3] * acc[nt][3];
    }
    rs0 += __shfl_xor_sync(0xffffffff, rs0, 1);
    rs0 += __shfl_xor_sync(0xffffffff, rs0, 2);
    rq0 += __shfl_xor_sync(0xffffffff, rq0, 1);
    rq0 += __shfl_xor_sync(0xffffffff, rq0, 2);
    rs1 += __shfl_xor_sync(0xffffffff, rs1, 1);
    rs1 += __shfl_xor_sync(0xffffffff, rs1, 2);
    rq1 += __shfl_xor_sync(0xffffffff, rq1, 1);
    rq1 += __shfl_xor_sync(0xffffffff, rq1, 2);
    if (tg == 0) {
        redS[nh][mq * 16 + g] = rs0;
        redS[nh][mq * 16 + g + 8] = rs1;
        redQ[nh][mq * 16 + g] = rq0;
        redQ[nh][mq * 16 + g + 8] = rq1;
    }
    __syncthreads();
    float mu0 = (redS[0][mq * 16 + g] + redS[1][mq * 16 + g]) * (1.f / DD);
    float mu1 = (redS[0][mq * 16 + g + 8] + redS[1][mq * 16 + g + 8]) * (1.f / DD);
    float v0 = fmaxf((redQ[0][mq * 16 + g] + redQ[1][mq * 16 + g]) * (1.f / DD) - mu0 * mu0, 0.f);
    float v1 = fmaxf((redQ[0][mq * 16 + g + 8] + redQ[1][mq * 16 + g + 8]) * (1.f / DD) - mu1 * mu1, 0.f);
    float rst0 = rsqrtf(v0 + 1e-3f), rst1 = rsqrtf(v1 + 1e-3f);
    #pragma unroll
    for (int nt = 0; nt < 8; nt++) {
        int col = nh * 64 + nt * 8 + 2 * tg;
        float2 gm = *(const float2*)&g1[col];
        float2 bt = *(const float2*)&be1[col];
        float2 lo = {(acc[nt][0] - mu0) * rst0 * gm.x + bt.x,
                     (acc[nt][1] - mu0) * rst0 * gm.y + bt.y};
        float2 hi = {(acc[nt][2] - mu1) * rst1 * gm.x + bt.x,
                     (acc[nt][3] - mu1) * rst1 * gm.y + bt.y};
        *(float2*)&g_x[(size_t)r0 * DD + col] = lo;
        *(float2*)&g_x[(size_t)r1 * DD + col] = hi;
    }
}

// ---------------- FFN1: grid (tiles, 4) ----------------
__global__ __launch_bounds__(256) void ffn1_mma_kernel(
    const int* __restrict__ length,
    const float* __restrict__ W1, const float* __restrict__ b1) {
    int row0 = blockIdx.x * 64;
    int b = row0 >> 10;
    int valid_len = length[b] + 1;
    if ((row0 & (SS - 1)) >= valid_len) return;
    int ncol0 = blockIdx.y * 128;

    extern __shared__ unsigned smemu[];
    int t = threadIdx.x, w = t >> 5, lane = t & 31;
    int g = lane >> 2, tg = lane & 3, mq = w >> 1, nh = w & 1;

    float acc[8][4];
    #pragma unroll
    for (int i = 0; i < 8; i++) acc[i][0] = acc[i][1] = acc[i][2] = acc[i][3] = 0.f;

    gemm_mainloop_cp(acc, smemu, g_x + (size_t)row0 * DD, DD, W1 + ncol0, DFF, 4,
                     t, mq, nh, g, tg);

    int r0 = row0 + mq * 16 + g, r1 = r0 + 8;
    #pragma unroll
    for (int nt = 0; nt < 8; nt++) {
        int col = ncol0 + nh * 64 + nt * 8 + 2 * tg;
        float2 bi = *(const float2*)&b1[col];
        float2 lo = {fmaxf(acc[nt][0] + bi.x, 0.f), fmaxf(acc[nt][1] + bi.y, 0.f)};
        float2 hi = {fmaxf(acc[nt][2] + bi.x, 0.f), fmaxf(acc[nt][3] + bi.y, 0.f)};
        *(float2*)&g_h[(size_t)r0 * DFF + col] = lo;
        *(float2*)&g_h[(size_t)r1 * DFF + col] = hi;
    }
}

// ---------------- FFN2 + residual + LN2 ----------------
__global__ __launch_bounds__(256) void ffn2_ln_mma_kernel(
    const int* __restrict__ length,
    const float* __restrict__ W2, const float* __restrict__ b2,
    const float* __restrict__ g2, const float* __restrict__ be2) {
    int row0 = blockIdx.x * 64;
    int b = row0 >> 10;
    int valid_len = length[b] + 1;
    if ((row0 & (SS - 1)) >= valid_len) return;

    extern __shared__ unsigned smemu[];
    __shared__ float redS[2][64];
    __shared__ float redQ[2][64];
    int t = threadIdx.x, w = t >> 5, lane = t & 31;
    int g = lane >> 2, tg = lane & 3, mq = w >> 1, nh = w & 1;

    float acc[8][4];
    #pragma unroll
    for (int i = 0; i < 8; i++) acc[i][0] = acc[i][1] = acc[i][2] = acc[i][3] = 0.f;

    gemm_mainloop_cp(acc, smemu, g_h + (size_t)row0 * DFF, DFF, W2, DD, DFF / 32,
                     t, mq, nh, g, tg);

    int r0 = row0 + mq * 16 + g, r1 = r0 + 8;
    float rs0 = 0.f, rq0 = 0.f, rs1 = 0.f, rq1 = 0.f;
    #pragma unroll
    for (int nt = 0; nt < 8; nt++) {
        int col = nh * 64 + nt * 8 + 2 * tg;
        float2 bi = *(const float2*)&b2[col];
        float2 e0 = *(const float2*)&g_x[(size_t)r0 * DD + col];
        float2 e1 = *(const float2*)&g_x[(size_t)r1 * DD + col];
        acc[nt][0] += bi.x + e0.x;
        acc[nt][1] += bi.y + e0.y;
        acc[nt][2] += bi.x + e1.x;
        acc[nt][3] += bi.y + e1.y;
        rs0 += acc[nt][0] + acc[nt][1];
        rq0 += acc[nt][0] * acc[nt][0] + acc[nt][1] * acc[nt][1];
        rs1 += acc[nt][2] + acc[nt][3];
        rq1 += acc[nt][2] * acc[nt][2] + acc[nt][3] * acc[nt][3];
    }
    rs0 += __shfl_xor_sync(0xffffffff, rs0, 1);
    rs0 += __shfl_xor_sync(0xffffffff, rs0, 2);
    rq0 += __shfl_xor_sync(0xffffffff, rq0, 1);
    rq0 += __shfl_xor_sync(0xffffffff, rq0, 2);
    rs1 += __shfl_xor_sync(0xffffffff, rs1, 1);
    rs1 += __shfl_xor_sync(0xffffffff, rs1, 2);
    rq1 += __shfl_xor_sync(0xffffffff, rq1, 1);
    rq1 += __shfl_xor_sync(0xffffffff, rq1, 2);
    if (tg == 0) {
        redS[nh][mq * 16 + g] = rs0;
        redS[nh][mq * 16 + g + 8] = rs1;
        redQ[nh][mq * 16 + g] = rq0;
        redQ[nh][mq * 16 + g + 8] = rq1;
    }
    __syncthreads();
    float mu0 = (redS[0][mq * 16 + g] + redS[1][mq * 16 + g]) * (1.f / DD);
    float mu1 = (redS[0][mq * 16 + g + 8] + redS[1][mq * 16 + g + 8]) * (1.f / DD);
    float v0 = fmaxf((redQ[0][mq * 16 + g] + redQ[1][mq * 16 + g]) * (1.f / DD) - mu0 * mu0, 0.f);
    float v1 = fmaxf((redQ[0][mq * 16 + g + 8] + redQ[1][mq * 16 + g + 8]) * (1.f / DD) - mu1 * mu1, 0.f);
    float rst0 = rsqrtf(v0 + 1e-3f), rst1 = rsqrtf(v1 + 1e-3f);
    #pragma unroll
    for (int nt = 0; nt < 8; nt++) {
        int col = nh * 64 + nt * 8 + 2 * tg;
        float2 gm = *(const float2*)&g2[col];
        float2 bt = *(const float2*)&be2[col];
        float2 lo = {(acc[nt][0] - mu0) * rst0 * gm.x + bt.x,
                     (acc[nt][1] - mu0) * rst0 * gm.y + bt.y};
        float2 hi = {(acc[nt][2] - mu1) * rst1 * gm.x + bt.x,
                     (acc[nt][3] - mu1) * rst1 * gm.y + bt.y};
        *(float2*)&g_x[(size_t)r0 * DD + col] = lo;
        *(float2*)&g_x[(size_t)r1 * DD + col] = hi;
    }
}

// ---------------- masked mean-pool + MLP head + sigmoid ----------------
__global__ __launch_bounds__(256) void head_kernel(
    const int* __restrict__ length,
    const float* __restrict__ Wm1, const float* __restrict__ bm1,
    const float* __restrict__ Wm2, const float* __restrict__ bm2,
    float* __restrict__ out) {
    int b = blockIdx.x;
    int t = threadIdx.x;
    __shared__ float part[2][DD];
    __shared__ float agg[DD];
    __shared__ float hh[MLPH];
    __shared__ float red[8];
    int cnt = length[b] + 1;
    int d = t & 127, grp = t >> 7;
    float s0 = 0.f, s1 = 0.f, s2 = 0.f, s3 = 0.f;
    int ss = grp;
    for (; ss + 6 < cnt; ss += 8) {
        s0 += g_x[(b * SS + ss) * DD + d];
        s1 += g_x[(b * SS + ss + 2) * DD + d];
        s2 += g_x[(b * SS + ss + 4) * DD + d];
        s3 += g_x[(b * SS + ss + 6) * DD + d];
    }
    for (; ss < cnt; ss += 2) s0 += g_x[(b * SS + ss) * DD + d];
    part[grp][d] = s0 + s1 + s2 + s3;
    __syncthreads();
    if (t < DD) agg[t] = (part[0][t] + part[1][t]) / (float)cnt;
    __syncthreads();
    {
        float acc = bm1[t];
        #pragma unroll 8
        for (int k = 0; k < DD; k++) acc += agg[k] * Wm1[k * MLPH + t];
        hh[t] = fmaxf(acc, 0.f);
    }
    __syncthreads();
    float v = hh[t] * Wm2[t];
    #pragma unroll
    for (int o = 16; o > 0; o >>= 1) v += __shfl_xor_sync(0xffffffff, v, o);
    if ((t & 31) == 0) red[t >> 5] = v;
    __syncthreads();
    if (t == 0) {
        float s = 0.f;
        #pragma unroll
        for (int i = 0; i < 8; i++) s += red[i];
        s += bm2[0];
        out[b] = 1.f / (1.f + __expf(-s));
    }
}

// ---------------- launch ----------------
extern "C" void kernel_launch(void* const* d_in, const int* in_sizes, int n_in,
                              void* d_out, int out_size) {
    (void)in_sizes; (void)n_in; (void)out_size;
    const float* demo       = (const float*)d_in[0];
    const float* times      = (const float*)d_in[1];
    const float* values     = (const float*)d_in[2];
    const int*   length     = (const int*)d_in[3];
    const float* timescales = (const float*)d_in[4];
    const float* W_demo = (const float*)d_in[5];
    const float* b_demo = (const float*)d_in[6];
    const float* W_val  = (const float*)d_in[7];
    const float* b_val  = (const float*)d_in[8];
    const float* Wq = (const float*)d_in[9];
    const float* bq = (const float*)d_in[10];
    const float* Wk = (const float*)d_in[11];
    const float* bk = (const float*)d_in[12];
    const float* Wv = (const float*)d_in[13];
    const float* bv = (const float*)d_in[14];
    const float* Wo = (const float*)d_in[15];
    const float* bo = (const float*)d_in[16];
    const float* ln1g = (const float*)d_in[17];
    const float* ln1b = (const float*)d_in[18];
    const float* W1 = (const float*)d_in[19];
    const float* b1 = (const float*)d_in[20];
    const float* W2 = (const float*)d_in[21];
    const float* b2 = (const float*)d_in[22];
    const float* ln2g = (const float*)d_in[23];
    const float* ln2b = (const float*)d_in[24];
    const float* Wm1 = (const float*)d_in[25];
    const float* bm1 = (const float*)d_in[26];
    const float* Wm2 = (const float*)d_in[27];
    const float* bm2 = (const float*)d_in[28];
    float* out = (float*)d_out;

    cudaFuncSetAttribute(embed_mma_kernel, cudaFuncAttributeMaxDynamicSharedMemorySize, EMBED_SMEM_BYTES);
    cudaFuncSetAttribute(qkv_mma_kernel, cudaFuncAttributeMaxDynamicSharedMemorySize, GEMM_SMEM_BYTES);
    cudaFuncSetAttribute(oproj_ln_mma_kernel, cudaFuncAttributeMaxDynamicSharedMemorySize, GEMM_SMEM_BYTES);
    cudaFuncSetAttribute(ffn1_mma_kernel, cudaFuncAttributeMaxDynamicSharedMemorySize, GEMM_SMEM_BYTES);
    cudaFuncSetAttribute(ffn2_ln_mma_kernel, cudaFuncAttributeMaxDynamicSharedMemorySize, GEMM_SMEM_BYTES);

    demo_kernel<<<BB, 128>>>(demo, W_demo, b_demo);
    dim3 ge(16, BB);
    embed_mma_kernel<<<ge, 256, EMBED_SMEM_BYTES>>>(times, values, timescales, W_val, b_val, length);

    int ntiles = BB * SS / 64;
    for (int l = 0; l < NLAY; l++) {
        dim3 gq(ntiles, 3);
        qkv_mma_kernel<<<gq, 256, GEMM_SMEM_BYTES>>>(length,
            Wq + l * DD * DD, bq + l * DD,
            Wk + l * DD * DD, bk + l * DD,
            Wv + l * DD * DD, bv + l * DD);
        dim3 ag(SS / 128, HH, BB);
        attn_mma_kernel<<<ag, 128>>>(length);
        oproj_ln_mma_kernel<<<ntiles, 256, GEMM_SMEM_BYTES>>>(length,
            Wo + l * DD * DD, bo + l * DD, ln1g + l * DD, ln1b + l * DD);
        dim3 gf(ntiles, 4);
        ffn1_mma_kernel<<<gf, 256, GEMM_SMEM_BYTES>>>(length, W1 + l * DD * DFF, b1 + l * DFF);
        ffn2_ln_mma_kernel<<<ntiles, 256, GEMM_SMEM_BYTES>>>(length,
            W2 + l * DFF * DD, b2 + l * DD, ln2g + l * DD, ln2b + l * DD);
    }

    head_kernel<<<BB, 256>>>(length, Wm1, bm1, Wm2, bm2, out);
}

// round 16
// speedup vs baseline: 1.4154x; 1.0323x over previous
#include <cuda_runtime.h>
#include <cuda_fp16.h>
#include <math.h>

#define BB 16
#define LL 1023
#define SS 1024
#define DD 128
#define DVAL 64
#define NDEMO 16
#define HH 8
#define DH 16
#define NLAY 2
#define DFF 512
#define MLPH 256

#define AS_ELEMS (64 * 36)
#define BS_ELEMS (32 * 136)
#define STAGE_ELEMS (AS_ELEMS + BS_ELEMS)
#define GEMM_SMEM_BYTES (3 * STAGE_ELEMS * 4)
#define EMBED_SMEM_BYTES (2 * STAGE_ELEMS * 4)

// ---------------- device scratch (no allocs allowed) ----------------
__device__ float g_x[BB * SS * DD];
__device__ float g_q[BB * SS * DD];    // head-major: [b][h][s][DH], fp32
__device__ __half g_k[BB * SS * DD];   // head-major: [b][h][s][DH], fp16
__device__ __half g_v[BB * SS * DD];   // head-major transposed: [b][h][d][s], fp16
__device__ float g_o[BB * SS * DD];    // token-major
__device__ float g_h[BB * SS * DFF];

__device__ __forceinline__ unsigned f2tf(float x) {
    unsigned r;
    asm("cvt.rna.tf32.f32 %0, %1;" : "=r"(r) : "f"(x));
    return r;
}

__device__ __forceinline__ float ex2f(float x) {
    float r;
    asm("ex2.approx.ftz.f32 %0, %1;" : "=f"(r) : "f"(x));
    return r;
}

__device__ __forceinline__ void mma_tf32(float* c, unsigned a0, unsigned a1,
                                         unsigned a2, unsigned a3,
                                         unsigned b0, unsigned b1) {
    asm("mma.sync.aligned.m16n8k8.row.col.f32.tf32.tf32.f32 "
        "{%0,%1,%2,%3},{%4,%5,%6,%7},{%8,%9},{%0,%1,%2,%3};"
        : "+f"(c[0]), "+f"(c[1]), "+f"(c[2]), "+f"(c[3])
        : "r"(a0), "r"(a1), "r"(a2), "r"(a3), "r"(b0), "r"(b1));
}

__device__ __forceinline__ void mma_f16(float* c, unsigned a0, unsigned a1,
                                        unsigned a2, unsigned a3,
                                        unsigned b0, unsigned b1) {
    asm("mma.sync.aligned.m16n8k16.row.col.f32.f16.f16.f32 "
        "{%0,%1,%2,%3},{%4,%5,%6,%7},{%8,%9},{%0,%1,%2,%3};"
        : "+f"(c[0]), "+f"(c[1]), "+f"(c[2]), "+f"(c[3])
        : "r"(a0), "r"(a1), "r"(a2), "r"(a3), "r"(b0), "r"(b1));
}

__device__ __forceinline__ unsigned smem_u32(const void* p) {
    return (unsigned)__cvta_generic_to_shared(p);
}

__device__ __forceinline__ void cp_async16(unsigned s, const void* g) {
    asm volatile("cp.async.ca.shared.global [%0], [%1], 16;" :: "r"(s), "l"(g));
}
#define CP_COMMIT() asm volatile("cp.async.commit_group;" ::: "memory")
#define CP_WAIT2() asm volatile("cp.async.wait_group 2;" ::: "memory")
#define CP_WAIT1() asm volatile("cp.async.wait_group 1;" ::: "memory")
#define CP_WAIT0() asm volatile("cp.async.wait_group 0;" ::: "memory")

// ---------------- GEMM tile: 64 rows x 128 cols, 256 threads ----------------
__device__ __forceinline__ void compute_chunk(float (*acc)[4],
                                              const unsigned (*As)[36],
                                              const unsigned (*Bs)[136],
                                              int mq, int nh, int g, int tg) {
    int mr = mq * 16;
    #pragma unroll
    for (int ks = 0; ks < 4; ks++) {
        unsigned a0 = As[mr + g][ks * 8 + tg];
        unsigned a1 = As[mr + g + 8][ks * 8 + tg];
        unsigned a2 = As[mr + g][ks * 8 + tg + 4];
        unsigned a3 = As[mr + g + 8][ks * 8 + tg + 4];
        #pragma unroll
        for (int nt = 0; nt < 8; nt++) {
            unsigned b0 = Bs[ks * 8 + tg][nh * 64 + nt * 8 + g];
            unsigned b1 = Bs[ks * 8 + tg + 4][nh * 64 + nt * 8 + g];
            mma_tf32(acc[nt], a0, a1, a2, a3, b0, b1);
        }
    }
}

// cp.async triple-buffered (depth-2) GEMM mainloop over nK k-chunks of 32.
__device__ __forceinline__ void gemm_mainloop_cp(
    float (*acc)[4], unsigned* smemu,
    const float* Ag, int lda, const float* Wg, int ldw, int nK,
    int t, int mq, int nh, int g, int tg) {
    int ra = t >> 2, c0 = (t & 3) * 8;
    int rb = t >> 3, f0 = t & 7;

    auto stage = [&](int kc) {
        unsigned* base = smemu + (kc % 3) * STAGE_ELEMS;
        unsigned (*As)[36] = (unsigned(*)[36])base;
        unsigned (*Bs)[136] = (unsigned(*)[136])(base + AS_ELEMS);
        const float* ap = Ag + (size_t)ra * lda + kc * 32 + c0;
        cp_async16(smem_u32(&As[ra][c0]), ap);
        cp_async16(smem_u32(&As[ra][c0 + 4]), ap + 4);
        const float* bp = Wg + (size_t)(kc * 32 + rb) * ldw;
        #pragma unroll
        for (int j = 0; j < 4; j++) {
            int c = (f0 + j * 8) * 4;
            cp_async16(smem_u32(&Bs[rb][c]), bp + c);
        }
        CP_COMMIT();
    };

    stage(0);
    if (nK > 1) stage(1);
    for (int kc = 0; kc < nK; kc++) {
        if (kc + 2 < nK) {
            stage(kc + 2);
            CP_WAIT2();
        } else if (kc + 1 < nK) {
            CP_WAIT1();
        } else {
            CP_WAIT0();
        }
        __syncthreads();
        unsigned* base = smemu + (kc % 3) * STAGE_ELEMS;
        compute_chunk(acc, (const unsigned(*)[36])base,
                      (const unsigned(*)[136])(base + AS_ELEMS), mq, nh, g, tg);
        __syncthreads();
    }
}

// ---------------- demo token row ----------------
__global__ __launch_bounds__(128) void demo_kernel(
    const float* __restrict__ demo,
    const float* __restrict__ W_demo, const float* __restrict__ b_demo) {
    int b = blockIdx.x, d = threadIdx.x;
    float acc = b_demo[d];
    #pragma unroll
    for (int k = 0; k < NDEMO; k++) acc += demo[b * NDEMO + k] * W_demo[k * DD + d];
    g_x[(size_t)b * SS * DD + d] = acc;
}

// ---------------- embedding (value tokens) via mma: grid (16 tiles, BB) ----------------
__global__ __launch_bounds__(256) void embed_mma_kernel(
    const float* __restrict__ times, const float* __restrict__ values,
    const float* __restrict__ timescales,
    const float* __restrict__ W_val, const float* __restrict__ b_val,
    const int* __restrict__ length) {
    int tile = blockIdx.x, b = blockIdx.y;
    int row0 = tile * 64;
    if (row0 >= length[b]) return;

    extern __shared__ unsigned smemu[];
    int t = threadIdx.x, w = t >> 5, lane = t & 31;
    int g = lane >> 2, tg = lane & 3, mq = w >> 1, nh = w & 1;

    int ra = t >> 2, c0a = (t & 3) * 8;
    int rb = t >> 3, f0 = t & 7;

    auto stage = [&](int kc, int buf) {
        unsigned* base = smemu + buf * STAGE_ELEMS;
        unsigned (*As)[36] = (unsigned(*)[36])base;
        unsigned (*Bs)[136] = (unsigned(*)[136])(base + AS_ELEMS);
        int tt = row0 + ra;
        int te = (tt > LL - 1) ? (LL - 1) : tt;
        const float* ap = values + ((size_t)b * LL + te) * DVAL + kc * 32 + c0a;
        cp_async16(smem_u32(&As[ra][c0a]), ap);
        cp_async16(smem_u32(&As[ra][c0a + 4]), ap + 4);
        const float* bp = W_val + (size_t)(kc * 32 + rb) * DD;
        #pragma unroll
        for (int j = 0; j < 4; j++) {
            int c = (f0 + j * 8) * 4;
            cp_async16(smem_u32(&Bs[rb][c]), bp + c);
        }
        CP_COMMIT();
    };

    float acc[8][4];
    #pragma unroll
    for (int i = 0; i < 8; i++) acc[i][0] = acc[i][1] = acc[i][2] = acc[i][3] = 0.f;

    stage(0, 0);
    stage(1, 1);
    #pragma unroll
    for (int kc = 0; kc < 2; kc++) {
        if (kc == 0) CP_WAIT1(); else CP_WAIT0();
        __syncthreads();
        unsigned* base = smemu + kc * STAGE_ELEMS;
        compute_chunk(acc, (const unsigned(*)[36])base,
                      (const unsigned(*)[136])(base + AS_ELEMS), mq, nh, g, tg);
        __syncthreads();
    }

    int t0 = row0 + mq * 16 + g, t1 = t0 + 8;
    float tm0 = (t0 <= LL - 1) ? times[b * LL + t0] : 0.f;
    float tm1 = (t1 <= LL - 1) ? times[b * LL + t1] : 0.f;
    #pragma unroll
    for (int nt = 0; nt < 8; nt++) {
        int col = nh * 64 + nt * 8 + 2 * tg;
        float2 bi = *(const float2*)&b_val[col];
        float ts0 = timescales[col & 63], ts1 = timescales[(col + 1) & 63];
        float a0 = __fdividef(tm0, ts0), a1 = __fdividef(tm0, ts1);
        float b0 = __fdividef(tm1, ts0), b1 = __fdividef(tm1, ts1);
        float pe00 = (col < 64) ? __sinf(a0) : __cosf(a0);
        float pe01 = (col + 1 < 64) ? __sinf(a1) : __cosf(a1);
        float pe10 = (col < 64) ? __sinf(b0) : __cosf(b0);
        float pe11 = (col + 1 < 64) ? __sinf(b1) : __cosf(b1);
        if (t0 <= LL - 1) {
            float2 lo = {acc[nt][0] + bi.x + pe00, acc[nt][1] + bi.y + pe01};
            *(float2*)&g_x[((size_t)b * SS + t0 + 1) * DD + col] = lo;
        }
        if (t1 <= LL - 1) {
            float2 hi = {acc[nt][2] + bi.x + pe10, acc[nt][3] + bi.y + pe11};
            *(float2*)&g_x[((size_t)b * SS + t1 + 1) * DD + col] = hi;
        }
    }
}

// ---------------- QKV: grid (tiles, 3); Q fp32, K fp16, V transposed fp16 ----------------
__global__ __launch_bounds__(256) void qkv_mma_kernel(
    const int* __restrict__ length,
    const float* __restrict__ Wq, const float* __restrict__ bq,
    const float* __restrict__ Wk, const float* __restrict__ bk,
    const float* __restrict__ Wv, const float* __restrict__ bv) {
    int row0 = blockIdx.x * 64;
    int b = row0 >> 10;
    int valid_len = length[b] + 1;
    int s0base = row0 & (SS - 1);
    if (s0base >= valid_len) return;
    int wi = blockIdx.y;
    const float* W = (wi == 0) ? Wq : (wi == 1) ? Wk : Wv;
    const float* bias = (wi == 0) ? bq : (wi == 1) ? bk : bv;

    extern __shared__ unsigned smemu[];
    int t = threadIdx.x, w = t >> 5, lane = t & 31;
    int g = lane >> 2, tg = lane & 3, mq = w >> 1, nh = w & 1;

    float acc[8][4];
    #pragma unroll
    for (int i = 0; i < 8; i++) acc[i][0] = acc[i][1] = acc[i][2] = acc[i][3] = 0.f;

    gemm_mainloop_cp(acc, smemu, g_x + (size_t)row0 * DD, DD, W, DD, 4,
                     t, mq, nh, g, tg);

    int s0 = s0base + mq * 16 + g, s1 = s0 + 8;
    if (wi == 2) {
        // V: transposed fp16 [b][h][d][s]
        #pragma unroll
        for (int nt = 0; nt < 8; nt++) {
            int col = nh * 64 + nt * 8 + 2 * tg;
            int hcol = col >> 4, d = col & 15;
            float2 bi = *(const float2*)&bias[col];
            size_t base = ((size_t)b * HH + hcol) * DH;
            g_v[(base + d) * SS + s0] = __float2half_rn(acc[nt][0] + bi.x);
            g_v[(base + d + 1) * SS + s0] = __float2half_rn(acc[nt][1] + bi.y);
            g_v[(base + d) * SS + s1] = __float2half_rn(acc[nt][2] + bi.x);
            g_v[(base + d + 1) * SS + s1] = __float2half_rn(acc[nt][3] + bi.y);
        }
    } else if (wi == 1) {
        // K: head-major fp16 [b][h][s][16]
        #pragma unroll
        for (int nt = 0; nt < 8; nt++) {
            int col = nh * 64 + nt * 8 + 2 * tg;
            int hcol = col >> 4, d = col & 15;
            float2 bi = *(const float2*)&bias[col];
            size_t base = ((size_t)b * HH + hcol) * SS;
            __half2 lo = __floats2half2_rn(acc[nt][0] + bi.x, acc[nt][1] + bi.y);
            __half2 hi = __floats2half2_rn(acc[nt][2] + bi.x, acc[nt][3] + bi.y);
            *(__half2*)&g_k[(base + s0) * DH + d] = lo;
            *(__half2*)&g_k[(base + s1) * DH + d] = hi;
        }
    } else {
        #pragma unroll
        for (int nt = 0; nt < 8; nt++) {
            int col = nh * 64 + nt * 8 + 2 * tg;
            int hcol = col >> 4, d = col & 15;
            float2 bi = *(const float2*)&bias[col];
            float2 lo = {acc[nt][0] + bi.x, acc[nt][1] + bi.y};
            float2 hi = {acc[nt][2] + bi.x, acc[nt][3] + bi.y};
            size_t base = ((size_t)b * HH + hcol) * SS;
            *(float2*)&g_q[(base + s0) * DH + d] = lo;
            *(float2*)&g_q[(base + s1) * DH + d] = hi;
        }
    }
}

// ---------------- flash attention: full fp16 QK + PV, P in registers ----------------
__global__ __launch_bounds__(128) void attn_mma_kernel(const int* __restrict__ length) {
    const int qt = blockIdx.x, h = blockIdx.y, b = blockIdx.z;
    int valid_len = length[b] + 1;
    int q0 = qt * 128;
    if (q0 >= valid_len) return;

    __shared__ __half Ks[2][64][24];     // fp16, [key][d], stride 24 (bank-clean)
    __shared__ __half Vs[2][16][72];     // fp16, [d][key]

    int t = threadIdx.x;
    int w = t >> 5, lane = t & 31;
    int g = lane >> 2, tg = lane & 3;
    size_t hb = ((size_t)b * HH + h) * SS;       // Q/K row base
    size_t hbd = ((size_t)b * HH + h) * DH;      // V row base (transposed)
    int orow_base = b * SS + q0 + w * 32;

    int key_st = t >> 1, kseg = (t & 1) << 3;
    int vrow = t >> 3, vseg = (t & 7) * 8;
    auto stage = [&](int c, int buf) {
        const __half* kp = g_k + (hb + c * 64 + key_st) * DH + kseg;
        cp_async16(smem_u32(&Ks[buf][key_st][kseg]), kp);
        const __half* vp = g_v + (hbd + vrow) * SS + c * 64 + vseg;
        cp_async16(smem_u32(&Vs[buf][vrow][vseg]), vp);
        CP_COMMIT();
    };

    const float qscale = 0.25f * 1.44269504f;
    unsigned qa[2][4];   // fp16 A-frags per mt
    #pragma unroll
    for (int mt = 0; mt < 2; mt++) {
        size_t r0 = (hb + q0 + w * 32 + mt * 16 + g) * DH;
        size_t r1 = r0 + 8 * DH;
        float2 x0 = *(const float2*)&g_q[r0 + 2 * tg];
        float2 x1 = *(const float2*)&g_q[r1 + 2 * tg];
        float2 x2 = *(const float2*)&g_q[r0 + 8 + 2 * tg];
        float2 x3 = *(const float2*)&g_q[r1 + 8 + 2 * tg];
        __half2 h0 = __floats2half2_rn(x0.x * qscale, x0.y * qscale);
        __half2 h1 = __floats2half2_rn(x1.x * qscale, x1.y * qscale);
        __half2 h2 = __floats2half2_rn(x2.x * qscale, x2.y * qscale);
        __half2 h3 = __floats2half2_rn(x3.x * qscale, x3.y * qscale);
        qa[mt][0] = *(unsigned*)&h0;
        qa[mt][1] = *(unsigned*)&h1;
        qa[mt][2] = *(unsigned*)&h2;
        qa[mt][3] = *(unsigned*)&h3;
    }

    float l[2][2] = {{0.f, 0.f}, {0.f, 0.f}};
    float oc[2][2][4];
    #pragma unroll
    for (int mt = 0; mt < 2; mt++)
        #pragma unroll
        for (int dt = 0; dt < 2; dt++)
            oc[mt][dt][0] = oc[mt][dt][1] = oc[mt][dt][2] = oc[mt][dt][3] = 0.f;

    int nch = (valid_len + 63) >> 6;
    stage(0, 0);

    for (int c = 0; c < nch; c++) {
        int bi = c & 1;
        if (c + 1 < nch) {
            stage(c + 1, bi ^ 1);
            CP_WAIT1();
        } else {
            CP_WAIT0();
        }
        __syncthreads();

        int limit = valid_len - c * 64;
        #pragma unroll
        for (int mt = 0; mt < 2; mt++) {
            unsigned ph[8][2];
            #pragma unroll
            for (int nt = 0; nt < 8; nt++) {
                unsigned kb0 = *(const unsigned*)&Ks[bi][nt * 8 + g][2 * tg];
                unsigned kb1 = *(const unsigned*)&Ks[bi][nt * 8 + g][8 + 2 * tg];
                float sc[4] = {0.f, 0.f, 0.f, 0.f};
                mma_f16(sc, qa[mt][0], qa[mt][1], qa[mt][2], qa[mt][3], kb0, kb1);
                int col0 = nt * 8 + 2 * tg, col1 = col0 + 1;
                float p0 = ex2f((col0 < limit) ? sc[0] : -1e30f);
                float p1 = ex2f((col1 < limit) ? sc[1] : -1e30f);
                float p2 = ex2f((col0 < limit) ? sc[2] : -1e30f);
                float p3 = ex2f((col1 < limit) ? sc[3] : -1e30f);
                l[mt][0] += p0 + p1;
                l[mt][1] += p2 + p3;
                __half2 h0 = __floats2half2_rn(p0, p1);
                __half2 h1 = __floats2half2_rn(p2, p3);
                ph[nt][0] = *(unsigned*)&h0;
                ph[nt][1] = *(unsigned*)&h1;
            }
            #pragma unroll
            for (int j = 0; j < 4; j++) {
                #pragma unroll
                for (int dt = 0; dt < 2; dt++) {
                    unsigned vb0 = *(const unsigned*)&Vs[bi][dt * 8 + g][j * 16 + 2 * tg];
                    unsigned vb1 = *(const unsigned*)&Vs[bi][dt * 8 + g][j * 16 + 2 * tg + 8];
                    mma_f16(oc[mt][dt], ph[2 * j][0], ph[2 * j][1],
                            ph[2 * j + 1][0], ph[2 * j + 1][1], vb0, vb1);
                }
            }
        }
        __syncthreads();
    }

    #pragma unroll
    for (int mt = 0; mt < 2; mt++) {
        l[mt][0] += __shfl_xor_sync(0xffffffff, l[mt][0], 1);
        l[mt][0] += __shfl_xor_sync(0xffffffff, l[mt][0], 2);
        l[mt][1] += __shfl_xor_sync(0xffffffff, l[mt][1], 1);
        l[mt][1] += __shfl_xor_sync(0xffffffff, l[mt][1], 2);
        float inv0 = 1.f / l[mt][0], inv1 = 1.f / l[mt][1];
        #pragma unroll
        for (int dt = 0; dt < 2; dt++) {
            int col = h * DH + dt * 8 + 2 * tg;
            int r = orow_base + mt * 16 + g;
            float2 lo = {oc[mt][dt][0] * inv0, oc[mt][dt][1] * inv0};
            float2 hi = {oc[mt][dt][2] * inv1, oc[mt][dt][3] * inv1};
            *(float2*)&g_o[(size_t)r * DD + col] = lo;
            *(float2*)&g_o[(size_t)(r + 8) * DD + col] = hi;
        }
    }
}

// ---------------- O-proj + residual + LN1 ----------------
__global__ __launch_bounds__(256) void oproj_ln_mma_kernel(
    const int* __restrict__ length,
    const float* __restrict__ Wo, const float* __restrict__ bo,
    const float* __restrict__ g1, const float* __restrict__ be1) {
    int row0 = blockIdx.x * 64;
    int b = row0 >> 10;
    int valid_len = length[b] + 1;
    if ((row0 & (SS - 1)) >= valid_len) return;

    extern __shared__ unsigned smemu[];
    __shared__ float redS[2][64];
    __shared__ float redQ[2][64];
    int t = threadIdx.x, w = t >> 5, lane = t & 31;
    int g = lane >> 2, tg = lane & 3, mq = w >> 1, nh = w & 1;

    float acc[8][4];
    #pragma unroll
    for (int i = 0; i < 8; i++) acc[i][0] = acc[i][1] = acc[i][2] = acc[i][3] = 0.f;

    gemm_mainloop_cp(acc, smemu, g_o + (size_t)row0 * DD, DD, Wo, DD, 4,
                     t, mq, nh, g, tg);

    int r0 = row0 + mq * 16 + g, r1 = r0 + 8;
    float rs0 = 0.f, rq0 = 0.f, rs1 = 0.f, rq1 = 0.f;
    #pragma unroll
    for (int nt = 0; nt < 8; nt++) {
        int col = nh * 64 + nt * 8 + 2 * tg;
        float2 bi = *(const float2*)&bo[col];
        float2 e0 = *(const float2*)&g_x[(size_t)r0 * DD + col];
        float2 e1 = *(const float2*)&g_x[(size_t)r1 * DD + col];
        acc[nt][0] += bi.x + e0.x;
        acc[nt][1] += bi.y + e0.y;
        acc[nt][2] += bi.x + e1.x;
        acc[nt][3] += bi.y + e1.y;
        rs0 += acc[nt][0] + acc[nt][1];
        rq0 += acc[nt][0] * acc[nt][0] + acc[nt][1] * acc[nt][1];
        rs1 += acc[nt][2] + acc[nt][3];
        rq1 += acc[nt][2] * acc[nt][2] + acc[nt][3] * acc[nt][3];
    }
    rs0 += __shfl_xor_sync(0xffffffff, rs0, 1);
    rs0 += __shfl_xor_sync(0xffffffff, rs0, 2);
    rq0 += __shfl_xor_sync(0xffffffff, rq0, 1);
    rq0 += __shfl_xor_sync(0xffffffff, rq0, 2);
    rs1 += __shfl_xor_sync(0xffffffff, rs1, 1);
    rs1 += __shfl_xor_sync(0xffffffff, rs1, 2);
    rq1 += __shfl_xor_sync(0xffffffff, rq1, 1);
    rq1 += __shfl_xor_sync(0xffffffff, rq1, 2);
    if (tg == 0) {
        redS[nh][mq * 16 + g] = rs0;
        redS[nh][mq * 16 + g + 8] = rs1;
        redQ[nh][mq * 16 + g] = rq0;
        redQ[nh][mq * 16 + g + 8] = rq1;
    }
    __syncthreads();
    float mu0 = (redS[0][mq * 16 + g] + redS[1][mq * 16 + g]) * (1.f / DD);
    float mu1 = (redS[0][mq * 16 + g + 8] + redS[1][mq * 16 + g + 8]) * (1.f / DD);
    float v0 = fmaxf((redQ[0][mq * 16 + g] + redQ[1][mq * 16 + g]) * (1.f / DD) - mu0 * mu0, 0.f);
    float v1 = fmaxf((redQ[0][mq * 16 + g + 8] + redQ[1][mq * 16 + g + 8]) * (1.f / DD) - mu1 * mu1, 0.f);
    float rst0 = rsqrtf(v0 + 1e-3f), rst1 = rsqrtf(v1 + 1e-3f);
    #pragma unroll
    for (int nt = 0; nt < 8; nt++) {
        int col = nh * 64 + nt * 8 + 2 * tg;
        float2 gm = *(const float2*)&g1[col];
        float2 bt = *(const float2*)&be1[col];
        float2 lo = {(acc[nt][0] - mu0) * rst0 * gm.x + bt.x,
                     (acc[nt][1] - mu0) * rst0 * gm.y + bt.y};
        float2 hi = {(acc[nt][2] - mu1) * rst1 * gm.x + bt.x,
                     (acc[nt][3] - mu1) * rst1 * gm.y + bt.y};
        *(float2*)&g_x[(size_t)r0 * DD + col] = lo;
        *(float2*)&g_x[(size_t)r1 * DD + col] = hi;
    }
}

// ---------------- FFN1: grid (tiles, 4) ----------------
__global__ __launch_bounds__(256) void ffn1_mma_kernel(
    const int* __restrict__ length,
    const float* __restrict__ W1, const float* __restrict__ b1) {
    int row0 = blockIdx.x * 64;
    int b = row0 >> 10;
    int valid_len = length[b] + 1;
    if ((row0 & (SS - 1)) >= valid_len) return;
    int ncol0 = blockIdx.y * 128;

    extern __shared__ unsigned smemu[];
    int t = threadIdx.x, w = t >> 5, lane = t & 31;
    int g = lane >> 2, tg = lane & 3, mq = w >> 1, nh = w & 1;

    float acc[8][4];
    #pragma unroll
    for (int i = 0; i < 8; i++) acc[i][0] = acc[i][1] = acc[i][2] = acc[i][3] = 0.f;

    gemm_mainloop_cp(acc, smemu, g_x + (size_t)row0 * DD, DD, W1 + ncol0, DFF, 4,
                     t, mq, nh, g, tg);

    int r0 = row0 + mq * 16 + g, r1 = r0 + 8;
    #pragma unroll
    for (int nt = 0; nt < 8; nt++) {
        int col = ncol0 + nh * 64 + nt * 8 + 2 * tg;
        float2 bi = *(const float2*)&b1[col];
        float2 lo = {fmaxf(acc[nt][0] + bi.x, 0.f), fmaxf(acc[nt][1] + bi.y, 0.f)};
        float2 hi = {fmaxf(acc[nt][2] + bi.x, 0.f), fmaxf(acc[nt][3] + bi.y, 0.f)};
        *(float2*)&g_h[(size_t)r0 * DFF + col] = lo;
        *(float2*)&g_h[(size_t)r1 * DFF + col] = hi;
    }
}

// ---------------- FFN2 + residual + LN2 ----------------
__global__ __launch_bounds__(256) void ffn2_ln_mma_kernel(
    const int* __restrict__ length,
    const float* __restrict__ W2, const float* __restrict__ b2,
    const float* __restrict__ g2, const float* __restrict__ be2) {
    int row0 = blockIdx.x * 64;
    int b = row0 >> 10;
    int valid_len = length[b] + 1;
    if ((row0 & (SS - 1)) >= valid_len) return;

    extern __shared__ unsigned smemu[];
    __shared__ float redS[2][64];
    __shared__ float redQ[2][64];
    int t = threadIdx.x, w = t >> 5, lane = t & 31;
    int g = lane >> 2, tg = lane & 3, mq = w >> 1, nh = w & 1;

    float acc[8][4];
    #pragma unroll
    for (int i = 0; i < 8; i++) acc[i][0] = acc[i][1] = acc[i][2] = acc[i][3] = 0.f;

    gemm_mainloop_cp(acc, smemu, g_h + (size_t)row0 * DFF, DFF, W2, DD, DFF / 32,
                     t, mq, nh, g, tg);

    int r0 = row0 + mq * 16 + g, r1 = r0 + 8;
    float rs0 = 0.f, rq0 = 0.f, rs1 = 0.f, rq1 = 0.f;
    #pragma unroll
    for (int nt = 0; nt < 8; nt++) {
        int col = nh * 64 + nt * 8 + 2 * tg;
        float2 bi = *(const float2*)&b2[col];
        float2 e0 = *(const float2*)&g_x[(size_t)r0 * DD + col];
        float2 e1 = *(const float2*)&g_x[(size_t)r1 * DD + col];
        acc[nt][0] += bi.x + e0.x;
        acc[nt][1] += bi.y + e0.y;
        acc[nt][2] += bi.x + e1.x;
        acc[nt][3] += bi.y + e1.y;
        rs0 += acc[nt][0] + acc[nt][1];
        rq0 += acc[nt][0] * acc[nt][0] + acc[nt][1] * acc[nt][1];
        rs1 += acc[nt][2] + acc[nt][3];
        rq1 += acc[nt][2] * acc[nt][2] + acc[nt][3] * acc[nt][3];
    }
    rs0 += __shfl_xor_sync(0xffffffff, rs0, 1);
    rs0 += __shfl_xor_sync(0xffffffff, rs0, 2);
    rq0 += __shfl_xor_sync(0xffffffff, rq0, 1);
    rq0 += __shfl_xor_sync(0xffffffff, rq0, 2);
    rs1 += __shfl_xor_sync(0xffffffff, rs1, 1);
    rs1 += __shfl_xor_sync(0xffffffff, rs1, 2);
    rq1 += __shfl_xor_sync(0xffffffff, rq1, 1);
    rq1 += __shfl_xor_sync(0xffffffff, rq1, 2);
    if (tg == 0) {
        redS[nh][mq * 16 + g] = rs0;
        redS[nh][mq * 16 + g + 8] = rs1;
        redQ[nh][mq * 16 + g] = rq0;
        redQ[nh][mq * 16 + g + 8] = rq1;
    }
    __syncthreads();
    float mu0 = (redS[0][mq * 16 + g] + redS[1][mq * 16 + g]) * (1.f / DD);
    float mu1 = (redS[0][mq * 16 + g + 8] + redS[1][mq * 16 + g + 8]) * (1.f / DD);
    float v0 = fmaxf((redQ[0][mq * 16 + g] + redQ[1][mq * 16 + g]) * (1.f / DD) - mu0 * mu0, 0.f);
    float v1 = fmaxf((redQ[0][mq * 16 + g + 8] + redQ[1][mq * 16 + g + 8]) * (1.f / DD) - mu1 * mu1, 0.f);
    float rst0 = rsqrtf(v0 + 1e-3f), rst1 = rsqrtf(v1 + 1e-3f);
    #pragma unroll
    for (int nt = 0; nt < 8; nt++) {
        int col = nh * 64 + nt * 8 + 2 * tg;
        float2 gm = *(const float2*)&g2[col];
        float2 bt = *(const float2*)&be2[col];
        float2 lo = {(acc[nt][0] - mu0) * rst0 * gm.x + bt.x,
                     (acc[nt][1] - mu0) * rst0 * gm.y + bt.y};
        float2 hi = {(acc[nt][2] - mu1) * rst1 * gm.x + bt.x,
                     (acc[nt][3] - mu1) * rst1 * gm.y + bt.y};
        *(float2*)&g_x[(size_t)r0 * DD + col] = lo;
        *(float2*)&g_x[(size_t)r1 * DD + col] = hi;
    }
}

// ---------------- masked mean-pool + MLP head + sigmoid ----------------
__global__ __launch_bounds__(256) void head_kernel(
    const int* __restrict__ length,
    const float* __restrict__ Wm1, const float* __restrict__ bm1,
    const float* __restrict__ Wm2, const float* __restrict__ bm2,
    float* __restrict__ out) {
    int b = blockIdx.x;
    int t = threadIdx.x;
    __shared__ float part[2][DD];
    __shared__ float agg[DD];
    __shared__ float hh[MLPH];
    __shared__ float red[8];
    int cnt = length[b] + 1;
    int d = t & 127, grp = t >> 7;
    float s0 = 0.f, s1 = 0.f, s2 = 0.f, s3 = 0.f;
    int ss = grp;
    for (; ss + 6 < cnt; ss += 8) {
        s0 += g_x[(b * SS + ss) * DD + d];
        s1 += g_x[(b * SS + ss + 2) * DD + d];
        s2 += g_x[(b * SS + ss + 4) * DD + d];
        s3 += g_x[(b * SS + ss + 6) * DD + d];
    }
    for (; ss < cnt; ss += 2) s0 += g_x[(b * SS + ss) * DD + d];
    part[grp][d] = s0 + s1 + s2 + s3;
    __syncthreads();
    if (t < DD) agg[t] = (part[0][t] + part[1][t]) / (float)cnt;
    __syncthreads();
    {
        float acc = bm1[t];
        #pragma unroll 8
        for (int k = 0; k < DD; k++) acc += agg[k] * Wm1[k * MLPH + t];
        hh[t] = fmaxf(acc, 0.f);
    }
    __syncthreads();
    float v = hh[t] * Wm2[t];
    #pragma unroll
    for (int o = 16; o > 0; o >>= 1) v += __shfl_xor_sync(0xffffffff, v, o);
    if ((t & 31) == 0) red[t >> 5] = v;
    __syncthreads();
    if (t == 0) {
        float s = 0.f;
        #pragma unroll
        for (int i = 0; i < 8; i++) s += red[i];
        s += bm2[0];
        out[b] = 1.f / (1.f + __expf(-s));
    }
}

// ---------------- launch ----------------
extern "C" void kernel_launch(void* const* d_in, const int* in_sizes, int n_in,
                              void* d_out, int out_size) {
    (void)in_sizes; (void)n_in; (void)out_size;
    const float* demo       = (const float*)d_in[0];
    const float* times      = (const float*)d_in[1];
    const float* values     = (const float*)d_in[2];
    const int*   length     = (const int*)d_in[3];
    const float* timescales = (const float*)d_in[4];
    const float* W_demo = (const float*)d_in[5];
    const float* b_demo = (const float*)d_in[6];
    const float* W_val  = (const float*)d_in[7];
    const float* b_val  = (const float*)d_in[8];
    const float* Wq = (const float*)d_in[9];
    const float* bq = (const float*)d_in[10];
    const float* Wk = (const float*)d_in[11];
    const float* bk = (const float*)d_in[12];
    const float* Wv = (const float*)d_in[13];
    const float* bv = (const float*)d_in[14];
    const float* Wo = (const float*)d_in[15];
    const float* bo = (const float*)d_in[16];
    const float* ln1g = (const float*)d_in[17];
    const float* ln1b = (const float*)d_in[18];
    const float* W1 = (const float*)d_in[19];
    const float* b1 = (const float*)d_in[20];
    const float* W2 = (const float*)d_in[21];
    const float* b2 = (const float*)d_in[22];
    const float* ln2g = (const float*)d_in[23];
    const float* ln2b = (const float*)d_in[24];
    const float* Wm1 = (const float*)d_in[25];
    const float* bm1 = (const float*)d_in[26];
    const float* Wm2 = (const float*)d_in[27];
    const float* bm2 = (const float*)d_in[28];
    float* out = (float*)d_out;

    cudaFuncSetAttribute(embed_mma_kernel, cudaFuncAttributeMaxDynamicSharedMemorySize, EMBED_SMEM_BYTES);
    cudaFuncSetAttribute(qkv_mma_kernel, cudaFuncAttributeMaxDynamicSharedMemorySize, GEMM_SMEM_BYTES);
    cudaFuncSetAttribute(oproj_ln_mma_kernel, cudaFuncAttributeMaxDynamicSharedMemorySize, GEMM_SMEM_BYTES);
    cudaFuncSetAttribute(ffn1_mma_kernel, cudaFuncAttributeMaxDynamicSharedMemorySize, GEMM_SMEM_BYTES);
    cudaFuncSetAttribute(ffn2_ln_mma_kernel, cudaFuncAttributeMaxDynamicSharedMemorySize, GEMM_SMEM_BYTES);

    demo_kernel<<<BB, 128>>>(demo, W_demo, b_demo);
    dim3 ge(16, BB);
    embed_mma_kernel<<<ge, 256, EMBED_SMEM_BYTES>>>(times, values, timescales, W_val, b_val, length);

    int ntiles = BB * SS / 64;
    for (int l = 0; l < NLAY; l++) {
        dim3 gq(ntiles, 3);
        qkv_mma_kernel<<<gq, 256, GEMM_SMEM_BYTES>>>(length,
            Wq + l * DD * DD, bq + l * DD,
            Wk + l * DD * DD, bk + l * DD,
            Wv + l * DD * DD, bv + l * DD);
        dim3 ag(SS / 128, HH, BB);
        attn_mma_kernel<<<ag, 128>>>(length);
        oproj_ln_mma_kernel<<<ntiles, 256, GEMM_SMEM_BYTES>>>(length,
            Wo + l * DD * DD, bo + l * DD, ln1g + l * DD, ln1b + l * DD);
        dim3 gf(ntiles, 4);
        ffn1_mma_kernel<<<gf, 256, GEMM_SMEM_BYTES>>>(length, W1 + l * DD * DFF, b1 + l * DFF);
        ffn2_ln_mma_kernel<<<ntiles, 256, GEMM_SMEM_BYTES>>>(length,
            W2 + l * DFF * DD, b2 + l * DD, ln2g + l * DD, ln2b + l * DD);
    }

    head_kernel<<<BB, 256>>>(length, Wm1, bm1, Wm2, bm2, out);
}

// round 17
// speedup vs baseline: 1.4626x; 1.0333x over previous
#include <cuda_runtime.h>
#include <cuda_fp16.h>
#include <math.h>

#define BB 16
#define LL 1023
#define SS 1024
#define DD 128
#define DVAL 64
#define NDEMO 16
#define HH 8
#define DH 16
#define NLAY 2
#define DFF 512
#define MLPH 256

#define AS_ELEMS (64 * 36)
#define BS_ELEMS (32 * 136)
#define STAGE_ELEMS (AS_ELEMS + BS_ELEMS)
#define EMBED_SMEM_BYTES (2 * STAGE_ELEMS * 4)

// fp16 GEMM staging: A fp32 [64][36] + B fp16 [128][40]
#define BH_STRIDE 40
#define BH_WORDS (128 * BH_STRIDE / 2)            // 2560 words
#define STAGE_F16 (AS_ELEMS + BH_WORDS)           // 4864 words
#define GEMM_F16_SMEM_BYTES (3 * STAGE_F16 * 4)   // 58368 B

// per-layer fp16 transposed-weight scratch layout (halves)
#define WL_SIZE 196608
#define WOFF_Q 0
#define WOFF_K 16384
#define WOFF_V 32768
#define WOFF_O 49152
#define WOFF_W1 65536
#define WOFF_W2 131072

// ---------------- device scratch (no allocs allowed) ----------------
__device__ float g_x[BB * SS * DD];
__device__ float g_q[BB * SS * DD];    // head-major: [b][h][s][DH], fp32
__device__ __half g_k[BB * SS * DD];   // head-major fp16
__device__ __half g_v[BB * SS * DD];   // head-major transposed [b][h][d][s], fp16
__device__ float g_o[BB * SS * DD];    // token-major
__device__ float g_h[BB * SS * DFF];
__device__ __half g_wh[NLAY * WL_SIZE];  // fp16 transposed weights [n][k]

__device__ __forceinline__ unsigned f2tf(float x) {
    unsigned r;
    asm("cvt.rna.tf32.f32 %0, %1;" : "=r"(r) : "f"(x));
    return r;
}

__device__ __forceinline__ float ex2f(float x) {
    float r;
    asm("ex2.approx.ftz.f32 %0, %1;" : "=f"(r) : "f"(x));
    return r;
}

__device__ __forceinline__ void mma_tf32(float* c, unsigned a0, unsigned a1,
                                         unsigned a2, unsigned a3,
                                         unsigned b0, unsigned b1) {
    asm("mma.sync.aligned.m16n8k8.row.col.f32.tf32.tf32.f32 "
        "{%0,%1,%2,%3},{%4,%5,%6,%7},{%8,%9},{%0,%1,%2,%3};"
        : "+f"(c[0]), "+f"(c[1]), "+f"(c[2]), "+f"(c[3])
        : "r"(a0), "r"(a1), "r"(a2), "r"(a3), "r"(b0), "r"(b1));
}

__device__ __forceinline__ void mma_f16(float* c, unsigned a0, unsigned a1,
                                        unsigned a2, unsigned a3,
                                        unsigned b0, unsigned b1) {
    asm("mma.sync.aligned.m16n8k16.row.col.f32.f16.f16.f32 "
        "{%0,%1,%2,%3},{%4,%5,%6,%7},{%8,%9},{%0,%1,%2,%3};"
        : "+f"(c[0]), "+f"(c[1]), "+f"(c[2]), "+f"(c[3])
        : "r"(a0), "r"(a1), "r"(a2), "r"(a3), "r"(b0), "r"(b1));
}

__device__ __forceinline__ unsigned smem_u32(const void* p) {
    return (unsigned)__cvta_generic_to_shared(p);
}

__device__ __forceinline__ void cp_async16(unsigned s, const void* g) {
    asm volatile("cp.async.ca.shared.global [%0], [%1], 16;" :: "r"(s), "l"(g));
}
#define CP_COMMIT() asm volatile("cp.async.commit_group;" ::: "memory")
#define CP_WAIT2() asm volatile("cp.async.wait_group 2;" ::: "memory")
#define CP_WAIT1() asm volatile("cp.async.wait_group 1;" ::: "memory")
#define CP_WAIT0() asm volatile("cp.async.wait_group 0;" ::: "memory")

// ---------------- weight prep: fp32 [k][n] -> fp16 [n][k] ----------------
__global__ __launch_bounds__(256) void prep_weights_kernel(
    const float* __restrict__ Wq, const float* __restrict__ Wk,
    const float* __restrict__ Wv, const float* __restrict__ Wo,
    const float* __restrict__ W1, const float* __restrict__ W2) {
    int idx = blockIdx.x * 256 + threadIdx.x;
    if (idx >= NLAY * WL_SIZE) return;
    int l = idx / WL_SIZE, r = idx % WL_SIZE;
    float v;
    if (r < 65536) {
        int m = r >> 14, rr = r & 16383;
        int n = rr >> 7, k = rr & 127;
        const float* src = (m == 0) ? Wq : (m == 1) ? Wk : (m == 2) ? Wv : Wo;
        v = src[l * 16384 + k * 128 + n];
    } else if (r < 131072) {
        int rr = r - 65536;
        int n = rr >> 7, k = rr & 127;
        v = W1[l * 65536 + k * 512 + n];
    } else {
        int rr = r - 131072;
        int n = rr >> 9, k = rr & 511;
        v = W2[l * 65536 + k * 128 + n];
    }
    g_wh[idx] = __float2half_rn(v);
}

// ---------------- tf32 GEMM chunk (embed kernel only) ----------------
__device__ __forceinline__ void compute_chunk(float (*acc)[4],
                                              const unsigned (*As)[36],
                                              const unsigned (*Bs)[136],
                                              int mq, int nh, int g, int tg) {
    int mr = mq * 16;
    #pragma unroll
    for (int ks = 0; ks < 4; ks++) {
        unsigned a0 = As[mr + g][ks * 8 + tg];
        unsigned a1 = As[mr + g + 8][ks * 8 + tg];
        unsigned a2 = As[mr + g][ks * 8 + tg + 4];
        unsigned a3 = As[mr + g + 8][ks * 8 + tg + 4];
        #pragma unroll
        for (int nt = 0; nt < 8; nt++) {
            unsigned b0 = Bs[ks * 8 + tg][nh * 64 + nt * 8 + g];
            unsigned b1 = Bs[ks * 8 + tg + 4][nh * 64 + nt * 8 + g];
            mma_tf32(acc[nt], a0, a1, a2, a3, b0, b1);
        }
    }
}

// ---------------- fp16 GEMM mainloop: A fp32 tile, B fp16 transposed ----------------
__device__ __forceinline__ void gemm_mainloop_f16(
    float (*acc)[4], unsigned* smemu,
    const float* Ag, int lda, const __half* WT, int ldk, int nK,
    int t, int mq, int nh, int g, int tg) {
    int ra = t >> 2, c0 = (t & 3) * 8;
    int rbh = t >> 1, segh = (t & 1) * 16;

    auto stage = [&](int kc) {
        unsigned* base = smemu + (kc % 3) * STAGE_F16;
        unsigned (*As)[36] = (unsigned(*)[36])base;
        __half* Bh = (__half*)(base + AS_ELEMS);
        const float* ap = Ag + (size_t)ra * lda + kc * 32 + c0;
        cp_async16(smem_u32(&As[ra][c0]), ap);
        cp_async16(smem_u32(&As[ra][c0 + 4]), ap + 4);
        const __half* bp = WT + (size_t)rbh * ldk + kc * 32 + segh;
        cp_async16(smem_u32(&Bh[rbh * BH_STRIDE + segh]), bp);
        cp_async16(smem_u32(&Bh[rbh * BH_STRIDE + segh + 8]), bp + 8);
        CP_COMMIT();
    };

    stage(0);
    if (nK > 1) stage(1);
    for (int kc = 0; kc < nK; kc++) {
        if (kc + 2 < nK) {
            stage(kc + 2);
            CP_WAIT2();
        } else if (kc + 1 < nK) {
            CP_WAIT1();
        } else {
            CP_WAIT0();
        }
        __syncthreads();
        unsigned* base = smemu + (kc % 3) * STAGE_F16;
        const float (*Asf)[36] = (const float(*)[36])base;
        const __half* Bh = (const __half*)(base + AS_ELEMS);
        int rlo = mq * 16 + g, rhi = rlo + 8;
        #pragma unroll
        for (int ks = 0; ks < 2; ks++) {
            int kb = ks * 16;
            float2 x0 = *(const float2*)&Asf[rlo][kb + 2 * tg];
            float2 x1 = *(const float2*)&Asf[rhi][kb + 2 * tg];
            float2 x2 = *(const float2*)&Asf[rlo][kb + 8 + 2 * tg];
            float2 x3 = *(const float2*)&Asf[rhi][kb + 8 + 2 * tg];
            __half2 h0 = __floats2half2_rn(x0.x, x0.y);
            __half2 h1 = __floats2half2_rn(x1.x, x1.y);
            __half2 h2 = __floats2half2_rn(x2.x, x2.y);
            __half2 h3 = __floats2half2_rn(x3.x, x3.y);
            unsigned a0 = *(unsigned*)&h0, a1 = *(unsigned*)&h1;
            unsigned a2 = *(unsigned*)&h2, a3 = *(unsigned*)&h3;
            #pragma unroll
            for (int nt = 0; nt < 8; nt++) {
                int n = nh * 64 + nt * 8 + g;
                unsigned b0 = *(const unsigned*)&Bh[n * BH_STRIDE + kb + 2 * tg];
                unsigned b1 = *(const unsigned*)&Bh[n * BH_STRIDE + kb + 8 + 2 * tg];
                mma_f16(acc[nt], a0, a1, a2, a3, b0, b1);
            }
        }
        __syncthreads();
    }
}

// ---------------- demo token row ----------------
__global__ __launch_bounds__(128) void demo_kernel(
    const float* __restrict__ demo,
    const float* __restrict__ W_demo, const float* __restrict__ b_demo) {
    int b = blockIdx.x, d = threadIdx.x;
    float acc = b_demo[d];
    #pragma unroll
    for (int k = 0; k < NDEMO; k++) acc += demo[b * NDEMO + k] * W_demo[k * DD + d];
    g_x[(size_t)b * SS * DD + d] = acc;
}

// ---------------- embedding via tf32 mma: grid (16 tiles, BB) ----------------
__global__ __launch_bounds__(256) void embed_mma_kernel(
    const float* __restrict__ times, const float* __restrict__ values,
    const float* __restrict__ timescales,
    const float* __restrict__ W_val, const float* __restrict__ b_val,
    const int* __restrict__ length) {
    int tile = blockIdx.x, b = blockIdx.y;
    int row0 = tile * 64;
    if (row0 >= length[b]) return;

    extern __shared__ unsigned smemu[];
    int t = threadIdx.x, w = t >> 5, lane = t & 31;
    int g = lane >> 2, tg = lane & 3, mq = w >> 1, nh = w & 1;

    int ra = t >> 2, c0a = (t & 3) * 8;
    int rb = t >> 3, f0 = t & 7;

    auto stage = [&](int kc, int buf) {
        unsigned* base = smemu + buf * STAGE_ELEMS;
        unsigned (*As)[36] = (unsigned(*)[36])base;
        unsigned (*Bs)[136] = (unsigned(*)[136])(base + AS_ELEMS);
        int tt = row0 + ra;
        int te = (tt > LL - 1) ? (LL - 1) : tt;
        const float* ap = values + ((size_t)b * LL + te) * DVAL + kc * 32 + c0a;
        cp_async16(smem_u32(&As[ra][c0a]), ap);
        cp_async16(smem_u32(&As[ra][c0a + 4]), ap + 4);
        const float* bp = W_val + (size_t)(kc * 32 + rb) * DD;
        #pragma unroll
        for (int j = 0; j < 4; j++) {
            int c = (f0 + j * 8) * 4;
            cp_async16(smem_u32(&Bs[rb][c]), bp + c);
        }
        CP_COMMIT();
    };

    float acc[8][4];
    #pragma unroll
    for (int i = 0; i < 8; i++) acc[i][0] = acc[i][1] = acc[i][2] = acc[i][3] = 0.f;

    stage(0, 0);
    stage(1, 1);
    #pragma unroll
    for (int kc = 0; kc < 2; kc++) {
        if (kc == 0) CP_WAIT1(); else CP_WAIT0();
        __syncthreads();
        unsigned* base = smemu + kc * STAGE_ELEMS;
        compute_chunk(acc, (const unsigned(*)[36])base,
                      (const unsigned(*)[136])(base + AS_ELEMS), mq, nh, g, tg);
        __syncthreads();
    }

    int t0 = row0 + mq * 16 + g, t1 = t0 + 8;
    float tm0 = (t0 <= LL - 1) ? times[b * LL + t0] : 0.f;
    float tm1 = (t1 <= LL - 1) ? times[b * LL + t1] : 0.f;
    #pragma unroll
    for (int nt = 0; nt < 8; nt++) {
        int col = nh * 64 + nt * 8 + 2 * tg;
        float2 bi = *(const float2*)&b_val[col];
        float ts0 = timescales[col & 63], ts1 = timescales[(col + 1) & 63];
        float a0 = __fdividef(tm0, ts0), a1 = __fdividef(tm0, ts1);
        float b0 = __fdividef(tm1, ts0), b1 = __fdividef(tm1, ts1);
        float pe00 = (col < 64) ? __sinf(a0) : __cosf(a0);
        float pe01 = (col + 1 < 64) ? __sinf(a1) : __cosf(a1);
        float pe10 = (col < 64) ? __sinf(b0) : __cosf(b0);
        float pe11 = (col + 1 < 64) ? __sinf(b1) : __cosf(b1);
        if (t0 <= LL - 1) {
            float2 lo = {acc[nt][0] + bi.x + pe00, acc[nt][1] + bi.y + pe01};
            *(float2*)&g_x[((size_t)b * SS + t0 + 1) * DD + col] = lo;
        }
        if (t1 <= LL - 1) {
            float2 hi = {acc[nt][2] + bi.x + pe10, acc[nt][3] + bi.y + pe11};
            *(float2*)&g_x[((size_t)b * SS + t1 + 1) * DD + col] = hi;
        }
    }
}

// ---------------- QKV (fp16 weights): grid (tiles, 3) ----------------
__global__ __launch_bounds__(256) void qkv_mma_kernel(
    const int* __restrict__ length, const __half* __restrict__ WTl,
    const float* __restrict__ bq, const float* __restrict__ bk,
    const float* __restrict__ bv) {
    int row0 = blockIdx.x * 64;
    int b = row0 >> 10;
    int valid_len = length[b] + 1;
    int s0base = row0 & (SS - 1);
    if (s0base >= valid_len) return;
    int wi = blockIdx.y;
    const __half* WT = WTl + wi * 16384;
    const float* bias = (wi == 0) ? bq : (wi == 1) ? bk : bv;

    extern __shared__ unsigned smemu[];
    int t = threadIdx.x, w = t >> 5, lane = t & 31;
    int g = lane >> 2, tg = lane & 3, mq = w >> 1, nh = w & 1;

    float acc[8][4];
    #pragma unroll
    for (int i = 0; i < 8; i++) acc[i][0] = acc[i][1] = acc[i][2] = acc[i][3] = 0.f;

    gemm_mainloop_f16(acc, smemu, g_x + (size_t)row0 * DD, DD, WT, DD, 4,
                      t, mq, nh, g, tg);

    int s0 = s0base + mq * 16 + g, s1 = s0 + 8;
    if (wi == 2) {
        #pragma unroll
        for (int nt = 0; nt < 8; nt++) {
            int col = nh * 64 + nt * 8 + 2 * tg;
            int hcol = col >> 4, d = col & 15;
            float2 bi = *(const float2*)&bias[col];
            size_t base = ((size_t)b * HH + hcol) * DH;
            g_v[(base + d) * SS + s0] = __float2half_rn(acc[nt][0] + bi.x);
            g_v[(base + d + 1) * SS + s0] = __float2half_rn(acc[nt][1] + bi.y);
            g_v[(base + d) * SS + s1] = __float2half_rn(acc[nt][2] + bi.x);
            g_v[(base + d + 1) * SS + s1] = __float2half_rn(acc[nt][3] + bi.y);
        }
    } else if (wi == 1) {
        #pragma unroll
        for (int nt = 0; nt < 8; nt++) {
            int col = nh * 64 + nt * 8 + 2 * tg;
            int hcol = col >> 4, d = col & 15;
            float2 bi = *(const float2*)&bias[col];
            size_t base = ((size_t)b * HH + hcol) * SS;
            __half2 lo = __floats2half2_rn(acc[nt][0] + bi.x, acc[nt][1] + bi.y);
            __half2 hi = __floats2half2_rn(acc[nt][2] + bi.x, acc[nt][3] + bi.y);
            *(__half2*)&g_k[(base + s0) * DH + d] = lo;
            *(__half2*)&g_k[(base + s1) * DH + d] = hi;
        }
    } else {
        #pragma unroll
        for (int nt = 0; nt < 8; nt++) {
            int col = nh * 64 + nt * 8 + 2 * tg;
            int hcol = col >> 4, d = col & 15;
            float2 bi = *(const float2*)&bias[col];
            float2 lo = {acc[nt][0] + bi.x, acc[nt][1] + bi.y};
            float2 hi = {acc[nt][2] + bi.x, acc[nt][3] + bi.y};
            size_t base = ((size_t)b * HH + hcol) * SS;
            *(float2*)&g_q[(base + s0) * DH + d] = lo;
            *(float2*)&g_q[(base + s1) * DH + d] = hi;
        }
    }
}

// ---------------- flash attention: full fp16 QK + PV, P in registers ----------------
__global__ __launch_bounds__(128) void attn_mma_kernel(const int* __restrict__ length) {
    const int qt = blockIdx.x, h = blockIdx.y, b = blockIdx.z;
    int valid_len = length[b] + 1;
    int q0 = qt * 128;
    if (q0 >= valid_len) return;

    __shared__ __half Ks[2][64][24];
    __shared__ __half Vs[2][16][72];

    int t = threadIdx.x;
    int w = t >> 5, lane = t & 31;
    int g = lane >> 2, tg = lane & 3;
    size_t hb = ((size_t)b * HH + h) * SS;
    size_t hbd = ((size_t)b * HH + h) * DH;
    int orow_base = b * SS + q0 + w * 32;

    int key_st = t >> 1, kseg = (t & 1) << 3;
    int vrow = t >> 3, vseg = (t & 7) * 8;
    auto stage = [&](int c, int buf) {
        const __half* kp = g_k + (hb + c * 64 + key_st) * DH + kseg;
        cp_async16(smem_u32(&Ks[buf][key_st][kseg]), kp);
        const __half* vp = g_v + (hbd + vrow) * SS + c * 64 + vseg;
        cp_async16(smem_u32(&Vs[buf][vrow][vseg]), vp);
        CP_COMMIT();
    };

    const float qscale = 0.25f * 1.44269504f;
    unsigned qa[2][4];
    #pragma unroll
    for (int mt = 0; mt < 2; mt++) {
        size_t r0 = (hb + q0 + w * 32 + mt * 16 + g) * DH;
        size_t r1 = r0 + 8 * DH;
        float2 x0 = *(const float2*)&g_q[r0 + 2 * tg];
        float2 x1 = *(const float2*)&g_q[r1 + 2 * tg];
        float2 x2 = *(const float2*)&g_q[r0 + 8 + 2 * tg];
        float2 x3 = *(const float2*)&g_q[r1 + 8 + 2 * tg];
        __half2 h0 = __floats2half2_rn(x0.x * qscale, x0.y * qscale);
        __half2 h1 = __floats2half2_rn(x1.x * qscale, x1.y * qscale);
        __half2 h2 = __floats2half2_rn(x2.x * qscale, x2.y * qscale);
        __half2 h3 = __floats2half2_rn(x3.x * qscale, x3.y * qscale);
        qa[mt][0] = *(unsigned*)&h0;
        qa[mt][1] = *(unsigned*)&h1;
        qa[mt][2] = *(unsigned*)&h2;
        qa[mt][3] = *(unsigned*)&h3;
    }

    float l[2][2] = {{0.f, 0.f}, {0.f, 0.f}};
    float oc[2][2][4];
    #pragma unroll
    for (int mt = 0; mt < 2; mt++)
        #pragma unroll
        for (int dt = 0; dt < 2; dt++)
            oc[mt][dt][0] = oc[mt][dt][1] = oc[mt][dt][2] = oc[mt][dt][3] = 0.f;

    int nch = (valid_len + 63) >> 6;
    stage(0, 0);

    for (int c = 0; c < nch; c++) {
        int bi = c & 1;
        if (c + 1 < nch) {
            stage(c + 1, bi ^ 1);
            CP_WAIT1();
        } else {
            CP_WAIT0();
        }
        __syncthreads();

        int limit = valid_len - c * 64;
        #pragma unroll
        for (int mt = 0; mt < 2; mt++) {
            unsigned ph[8][2];
            #pragma unroll
            for (int nt = 0; nt < 8; nt++) {
                unsigned kb0 = *(const unsigned*)&Ks[bi][nt * 8 + g][2 * tg];
                unsigned kb1 = *(const unsigned*)&Ks[bi][nt * 8 + g][8 + 2 * tg];
                float sc[4] = {0.f, 0.f, 0.f, 0.f};
                mma_f16(sc, qa[mt][0], qa[mt][1], qa[mt][2], qa[mt][3], kb0, kb1);
                int col0 = nt * 8 + 2 * tg, col1 = col0 + 1;
                float p0 = ex2f((col0 < limit) ? sc[0] : -1e30f);
                float p1 = ex2f((col1 < limit) ? sc[1] : -1e30f);
                float p2 = ex2f((col0 < limit) ? sc[2] : -1e30f);
                float p3 = ex2f((col1 < limit) ? sc[3] : -1e30f);
                l[mt][0] += p0 + p1;
                l[mt][1] += p2 + p3;
                __half2 h0 = __floats2half2_rn(p0, p1);
                __half2 h1 = __floats2half2_rn(p2, p3);
                ph[nt][0] = *(unsigned*)&h0;
                ph[nt][1] = *(unsigned*)&h1;
            }
            #pragma unroll
            for (int j = 0; j < 4; j++) {
                #pragma unroll
                for (int dt = 0; dt < 2; dt++) {
                    unsigned vb0 = *(const unsigned*)&Vs[bi][dt * 8 + g][j * 16 + 2 * tg];
                    unsigned vb1 = *(const unsigned*)&Vs[bi][dt * 8 + g][j * 16 + 2 * tg + 8];
                    mma_f16(oc[mt][dt], ph[2 * j][0], ph[2 * j][1],
                            ph[2 * j + 1][0], ph[2 * j + 1][1], vb0, vb1);
                }
            }
        }
        __syncthreads();
    }

    #pragma unroll
    for (int mt = 0; mt < 2; mt++) {
        l[mt][0] += __shfl_xor_sync(0xffffffff, l[mt][0], 1);
        l[mt][0] += __shfl_xor_sync(0xffffffff, l[mt][0], 2);
        l[mt][1] += __shfl_xor_sync(0xffffffff, l[mt][1], 1);
        l[mt][1] += __shfl_xor_sync(0xffffffff, l[mt][1], 2);
        float inv0 = 1.f / l[mt][0], inv1 = 1.f / l[mt][1];
        #pragma unroll
        for (int dt = 0; dt < 2; dt++) {
            int col = h * DH + dt * 8 + 2 * tg;
            int r = orow_base + mt * 16 + g;
            float2 lo = {oc[mt][dt][0] * inv0, oc[mt][dt][1] * inv0};
            float2 hi = {oc[mt][dt][2] * inv1, oc[mt][dt][3] * inv1};
            *(float2*)&g_o[(size_t)r * DD + col] = lo;
            *(float2*)&g_o[(size_t)(r + 8) * DD + col] = hi;
        }
    }
}

// ---------------- O-proj + residual + LN1 (fp16 weights) ----------------
__global__ __launch_bounds__(256) void oproj_ln_mma_kernel(
    const int* __restrict__ length, const __half* __restrict__ WT,
    const float* __restrict__ bo,
    const float* __restrict__ g1, const float* __restrict__ be1) {
    int row0 = blockIdx.x * 64;
    int b = row0 >> 10;
    int valid_len = length[b] + 1;
    if ((row0 & (SS - 1)) >= valid_len) return;

    extern __shared__ unsigned smemu[];
    __shared__ float redS[2][64];
    __shared__ float redQ[2][64];
    int t = threadIdx.x, w = t >> 5, lane = t & 31;
    int g = lane >> 2, tg = lane & 3, mq = w >> 1, nh = w & 1;

    float acc[8][4];
    #pragma unroll
    for (int i = 0; i < 8; i++) acc[i][0] = acc[i][1] = acc[i][2] = acc[i][3] = 0.f;

    gemm_mainloop_f16(acc, smemu, g_o + (size_t)row0 * DD, DD, WT, DD, 4,
                      t, mq, nh, g, tg);

    int r0 = row0 + mq * 16 + g, r1 = r0 + 8;
    float rs0 = 0.f, rq0 = 0.f, rs1 = 0.f, rq1 = 0.f;
    #pragma unroll
    for (int nt = 0; nt < 8; nt++) {
        int col = nh * 64 + nt * 8 + 2 * tg;
        float2 bi = *(const float2*)&bo[col];
        float2 e0 = *(const float2*)&g_x[(size_t)r0 * DD + col];
        float2 e1 = *(const float2*)&g_x[(size_t)r1 * DD + col];
        acc[nt][0] += bi.x + e0.x;
        acc[nt][1] += bi.y + e0.y;
        acc[nt][2] += bi.x + e1.x;
        acc[nt][3] += bi.y + e1.y;
        rs0 += acc[nt][0] + acc[nt][1];
        rq0 += acc[nt][0] * acc[nt][0] + acc[nt][1] * acc[nt][1];
        rs1 += acc[nt][2] + acc[nt][3];
        rq1 += acc[nt][2] * acc[nt][2] + acc[nt][3] * acc[nt][3];
    }
    rs0 += __shfl_xor_sync(0xffffffff, rs0, 1);
    rs0 += __shfl_xor_sync(0xffffffff, rs0, 2);
    rq0 += __shfl_xor_sync(0xffffffff, rq0, 1);
    rq0 += __shfl_xor_sync(0xffffffff, rq0, 2);
    rs1 += __shfl_xor_sync(0xffffffff, rs1, 1);
    rs1 += __shfl_xor_sync(0xffffffff, rs1, 2);
    rq1 += __shfl_xor_sync(0xffffffff, rq1, 1);
    rq1 += __shfl_xor_sync(0xffffffff, rq1, 2);
    if (tg == 0) {
        redS[nh][mq * 16 + g] = rs0;
        redS[nh][mq * 16 + g + 8] = rs1;
        redQ[nh][mq * 16 + g] = rq0;
        redQ[nh][mq * 16 + g + 8] = rq1;
    }
    __syncthreads();
    float mu0 = (redS[0][mq * 16 + g] + redS[1][mq * 16 + g]) * (1.f / DD);
    float mu1 = (redS[0][mq * 16 + g + 8] + redS[1][mq * 16 + g + 8]) * (1.f / DD);
    float v0 = fmaxf((redQ[0][mq * 16 + g] + redQ[1][mq * 16 + g]) * (1.f / DD) - mu0 * mu0, 0.f);
    float v1 = fmaxf((redQ[0][mq * 16 + g + 8] + redQ[1][mq * 16 + g + 8]) * (1.f / DD) - mu1 * mu1, 0.f);
    float rst0 = rsqrtf(v0 + 1e-3f), rst1 = rsqrtf(v1 + 1e-3f);
    #pragma unroll
    for (int nt = 0; nt < 8; nt++) {
        int col = nh * 64 + nt * 8 + 2 * tg;
        float2 gm = *(const float2*)&g1[col];
        float2 bt = *(const float2*)&be1[col];
        float2 lo = {(acc[nt][0] - mu0) * rst0 * gm.x + bt.x,
                     (acc[nt][1] - mu0) * rst0 * gm.y + bt.y};
        float2 hi = {(acc[nt][2] - mu1) * rst1 * gm.x + bt.x,
                     (acc[nt][3] - mu1) * rst1 * gm.y + bt.y};
        *(float2*)&g_x[(size_t)r0 * DD + col] = lo;
        *(float2*)&g_x[(size_t)r1 * DD + col] = hi;
    }
}

// ---------------- FFN1 (fp16 weights): grid (tiles, 4) ----------------
__global__ __launch_bounds__(256) void ffn1_mma_kernel(
    const int* __restrict__ length, const __half* __restrict__ WT,
    const float* __restrict__ b1) {
    int row0 = blockIdx.x * 64;
    int b = row0 >> 10;
    int valid_len = length[b] + 1;
    if ((row0 & (SS - 1)) >= valid_len) return;
    int ncol0 = blockIdx.y * 128;

    extern __shared__ unsigned smemu[];
    int t = threadIdx.x, w = t >> 5, lane = t & 31;
    int g = lane >> 2, tg = lane & 3, mq = w >> 1, nh = w & 1;

    float acc[8][4];
    #pragma unroll
    for (int i = 0; i < 8; i++) acc[i][0] = acc[i][1] = acc[i][2] = acc[i][3] = 0.f;

    gemm_mainloop_f16(acc, smemu, g_x + (size_t)row0 * DD, DD,
                      WT + (size_t)ncol0 * DD, DD, 4, t, mq, nh, g, tg);

    int r0 = row0 + mq * 16 + g, r1 = r0 + 8;
    #pragma unroll
    for (int nt = 0; nt < 8; nt++) {
        int col = ncol0 + nh * 64 + nt * 8 + 2 * tg;
        float2 bi = *(const float2*)&b1[col];
        float2 lo = {fmaxf(acc[nt][0] + bi.x, 0.f), fmaxf(acc[nt][1] + bi.y, 0.f)};
        float2 hi = {fmaxf(acc[nt][2] + bi.x, 0.f), fmaxf(acc[nt][3] + bi.y, 0.f)};
        *(float2*)&g_h[(size_t)r0 * DFF + col] = lo;
        *(float2*)&g_h[(size_t)r1 * DFF + col] = hi;
    }
}

// ---------------- FFN2 + residual + LN2 (fp16 weights) ----------------
__global__ __launch_bounds__(256) void ffn2_ln_mma_kernel(
    const int* __restrict__ length, const __half* __restrict__ WT,
    const float* __restrict__ b2,
    const float* __restrict__ g2, const float* __restrict__ be2) {
    int row0 = blockIdx.x * 64;
    int b = row0 >> 10;
    int valid_len = length[b] + 1;
    if ((row0 & (SS - 1)) >= valid_len) return;

    extern __shared__ unsigned smemu[];
    __shared__ float redS[2][64];
    __shared__ float redQ[2][64];
    int t = threadIdx.x, w = t >> 5, lane = t & 31;
    int g = lane >> 2, tg = lane & 3, mq = w >> 1, nh = w & 1;

    float acc[8][4];
    #pragma unroll
    for (int i = 0; i < 8; i++) acc[i][0] = acc[i][1] = acc[i][2] = acc[i][3] = 0.f;

    gemm_mainloop_f16(acc, smemu, g_h + (size_t)row0 * DFF, DFF, WT, DFF,
                      DFF / 32, t, mq, nh, g, tg);

    int r0 = row0 + mq * 16 + g, r1 = r0 + 8;
    float rs0 = 0.f, rq0 = 0.f, rs1 = 0.f, rq1 = 0.f;
    #pragma unroll
    for (int nt = 0; nt < 8; nt++) {
        int col = nh * 64 + nt * 8 + 2 * tg;
        float2 bi = *(const float2*)&b2[col];
        float2 e0 = *(const float2*)&g_x[(size_t)r0 * DD + col];
        float2 e1 = *(const float2*)&g_x[(size_t)r1 * DD + col];
        acc[nt][0] += bi.x + e0.x;
        acc[nt][1] += bi.y + e0.y;
        acc[nt][2] += bi.x + e1.x;
        acc[nt][3] += bi.y + e1.y;
        rs0 += acc[nt][0] + acc[nt][1];
        rq0 += acc[nt][0] * acc[nt][0] + acc[nt][1] * acc[nt][1];
        rs1 += acc[nt][2] + acc[nt][3];
        rq1 += acc[nt][2] * acc[nt][2] + acc[nt][3] * acc[nt][3];
    }
    rs0 += __shfl_xor_sync(0xffffffff, rs0, 1);
    rs0 += __shfl_xor_sync(0xffffffff, rs0, 2);
    rq0 += __shfl_xor_sync(0xffffffff, rq0, 1);
    rq0 += __shfl_xor_sync(0xffffffff, rq0, 2);
    rs1 += __shfl_xor_sync(0xffffffff, rs1, 1);
    rs1 += __shfl_xor_sync(0xffffffff, rs1, 2);
    rq1 += __shfl_xor_sync(0xffffffff, rq1, 1);
    rq1 += __shfl_xor_sync(0xffffffff, rq1, 2);
    if (tg == 0) {
        redS[nh][mq * 16 + g] = rs0;
        redS[nh][mq * 16 + g + 8] = rs1;
        redQ[nh][mq * 16 + g] = rq0;
        redQ[nh][mq * 16 + g + 8] = rq1;
    }
    __syncthreads();
    float mu0 = (redS[0][mq * 16 + g] + redS[1][mq * 16 + g]) * (1.f / DD);
    float mu1 = (redS[0][mq * 16 + g + 8] + redS[1][mq * 16 + g + 8]) * (1.f / DD);
    float v0 = fmaxf((redQ[0][mq * 16 + g] + redQ[1][mq * 16 + g]) * (1.f / DD) - mu0 * mu0, 0.f);
    float v1 = fmaxf((redQ[0][mq * 16 + g + 8] + redQ[1][mq * 16 + g + 8]) * (1.f / DD) - mu1 * mu1, 0.f);
    float rst0 = rsqrtf(v0 + 1e-3f), rst1 = rsqrtf(v1 + 1e-3f);
    #pragma unroll
    for (int nt = 0; nt < 8; nt++) {
        int col = nh * 64 + nt * 8 + 2 * tg;
        float2 gm = *(const float2*)&g2[col];
        float2 bt = *(const float2*)&be2[col];
        float2 lo = {(acc[nt][0] - mu0) * rst0 * gm.x + bt.x,
                     (acc[nt][1] - mu0) * rst0 * gm.y + bt.y};
        float2 hi = {(acc[nt][2] - mu1) * rst1 * gm.x + bt.x,
                     (acc[nt][3] - mu1) * rst1 * gm.y + bt.y};
        *(float2*)&g_x[(size_t)r0 * DD + col] = lo;
        *(float2*)&g_x[(size_t)r1 * DD + col] = hi;
    }
}

// ---------------- masked mean-pool + MLP head + sigmoid ----------------
__global__ __launch_bounds__(256) void head_kernel(
    const int* __restrict__ length,
    const float* __restrict__ Wm1, const float* __restrict__ bm1,
    const float* __restrict__ Wm2, const float* __restrict__ bm2,
    float* __restrict__ out) {
    int b = blockIdx.x;
    int t = threadIdx.x;
    __shared__ float part[2][DD];
    __shared__ float agg[DD];
    __shared__ float hh[MLPH];
    __shared__ float red[8];
    int cnt = length[b] + 1;
    int d = t & 127, grp = t >> 7;
    float s0 = 0.f, s1 = 0.f, s2 = 0.f, s3 = 0.f;
    int ss = grp;
    for (; ss + 6 < cnt; ss += 8) {
        s0 += g_x[(b * SS + ss) * DD + d];
        s1 += g_x[(b * SS + ss + 2) * DD + d];
        s2 += g_x[(b * SS + ss + 4) * DD + d];
        s3 += g_x[(b * SS + ss + 6) * DD + d];
    }
    for (; ss < cnt; ss += 2) s0 += g_x[(b * SS + ss) * DD + d];
    part[grp][d] = s0 + s1 + s2 + s3;
    __syncthreads();
    if (t < DD) agg[t] = (part[0][t] + part[1][t]) / (float)cnt;
    __syncthreads();
    {
        float acc = bm1[t];
        #pragma unroll 8
        for (int k = 0; k < DD; k++) acc += agg[k] * Wm1[k * MLPH + t];
        hh[t] = fmaxf(acc, 0.f);
    }
    __syncthreads();
    float v = hh[t] * Wm2[t];
    #pragma unroll
    for (int o = 16; o > 0; o >>= 1) v += __shfl_xor_sync(0xffffffff, v, o);
    if ((t & 31) == 0) red[t >> 5] = v;
    __syncthreads();
    if (t == 0) {
        float s = 0.f;
        #pragma unroll
        for (int i = 0; i < 8; i++) s += red[i];
        s += bm2[0];
        out[b] = 1.f / (1.f + __expf(-s));
    }
}

// ---------------- launch ----------------
extern "C" void kernel_launch(void* const* d_in, const int* in_sizes, int n_in,
                              void* d_out, int out_size) {
    (void)in_sizes; (void)n_in; (void)out_size;
    const float* demo       = (const float*)d_in[0];
    const float* times      = (const float*)d_in[1];
    const float* values     = (const float*)d_in[2];
    const int*   length     = (const int*)d_in[3];
    const float* timescales = (const float*)d_in[4];
    const float* W_demo = (const float*)d_in[5];
    const float* b_demo = (const float*)d_in[6];
    const float* W_val  = (const float*)d_in[7];
    const float* b_val  = (const float*)d_in[8];
    const float* Wq = (const float*)d_in[9];
    const float* bq = (const float*)d_in[10];
    const float* Wk = (const float*)d_in[11];
    const float* bk = (const float*)d_in[12];
    const float* Wv = (const float*)d_in[13];
    const float* bv = (const float*)d_in[14];
    const float* Wo = (const float*)d_in[15];
    const float* bo = (const float*)d_in[16];
    const float* ln1g = (const float*)d_in[17];
    const float* ln1b = (const float*)d_in[18];
    const float* W1 = (const float*)d_in[19];
    const float* b1 = (const float*)d_in[20];
    const float* W2 = (const float*)d_in[21];
    const float* b2 = (const float*)d_in[22];
    const float* ln2g = (const float*)d_in[23];
    const float* ln2b = (const float*)d_in[24];
    const float* Wm1 = (const float*)d_in[25];
    const float* bm1 = (const float*)d_in[26];
    const float* Wm2 = (const float*)d_in[27];
    const float* bm2 = (const float*)d_in[28];
    float* out = (float*)d_out;

    cudaFuncSetAttribute(embed_mma_kernel, cudaFuncAttributeMaxDynamicSharedMemorySize, EMBED_SMEM_BYTES);
    cudaFuncSetAttribute(qkv_mma_kernel, cudaFuncAttributeMaxDynamicSharedMemorySize, GEMM_F16_SMEM_BYTES);
    cudaFuncSetAttribute(oproj_ln_mma_kernel, cudaFuncAttributeMaxDynamicSharedMemorySize, GEMM_F16_SMEM_BYTES);
    cudaFuncSetAttribute(ffn1_mma_kernel, cudaFuncAttributeMaxDynamicSharedMemorySize, GEMM_F16_SMEM_BYTES);
    cudaFuncSetAttribute(ffn2_ln_mma_kernel, cudaFuncAttributeMaxDynamicSharedMemorySize, GEMM_F16_SMEM_BYTES);

    prep_weights_kernel<<<(NLAY * WL_SIZE + 255) / 256, 256>>>(Wq, Wk, Wv, Wo, W1, W2);
    demo_kernel<<<BB, 128>>>(demo, W_demo, b_demo);
    dim3 ge(16, BB);
    embed_mma_kernel<<<ge, 256, EMBED_SMEM_BYTES>>>(times, values, timescales, W_val, b_val, length);

    // get device pointer to g_wh for offset arithmetic on host side
    int ntiles = BB * SS / 64;
    for (int l = 0; l < NLAY; l++) {
        // pass offsets into g_wh via small device-symbol-relative trick:
        // kernels take a WT pointer; compute it with cudaGetSymbolAddress once
        static __half* wh_base = nullptr;
        if (!wh_base) cudaGetSymbolAddress((void**)&wh_base, g_wh);
        const __half* WL = wh_base + (size_t)l * WL_SIZE;

        dim3 gq(ntiles, 3);
        qkv_mma_kernel<<<gq, 256, GEMM_F16_SMEM_BYTES>>>(length, WL + WOFF_Q,
            bq + l * DD, bk + l * DD, bv + l * DD);
        dim3 ag(SS / 128, HH, BB);
        attn_mma_kernel<<<ag, 128>>>(length);
        oproj_ln_mma_kernel<<<ntiles, 256, GEMM_F16_SMEM_BYTES>>>(length,
            WL + WOFF_O, bo + l * DD, ln1g + l * DD, ln1b + l * DD);
        dim3 gf(ntiles, 4);
        ffn1_mma_kernel<<<gf, 256, GEMM_F16_SMEM_BYTES>>>(length,
            WL + WOFF_W1, b1 + l * DFF);
        ffn2_ln_mma_kernel<<<ntiles, 256, GEMM_F16_SMEM_BYTES>>>(length,
            WL + WOFF_W2, b2 + l * DD, ln2g + l * DD, ln2b + l * DD);
    }

    head_kernel<<<BB, 256>>>(length, Wm1, bm1, Wm2, bm2, out);
}